// round 1
// baseline (speedup 1.0000x reference)
#include <cuda_runtime.h>
#include <math.h>

#define BB 4
#define LL 2048
#define DD 256
#define DINN 512
#define NST 16
#define NDIR 2
#define MROWS (BB*LL)      // 8192
#define N1 2048            // NDIR * 2 * DINN
#define TT 16
#define EPSF 1e-5f

// ---------------- scratch (device globals; allocation-free) ----------------
__device__ float g_xn[MROWS*DD];                 // rmsnorm'd x (norm_w folded into W1)
__device__ float g_w1[N1*DD];                    // stacked in_proj * norm_w  [dir*1024+e][d]
__device__ float g_w2[NDIR*DD*DINN];             // stacked out_proj          [dir*256+do][e]
__device__ float g_xz[MROWS*N1];                 // in_proj output [m][dir*1024 + e]
__device__ float g_ut [NDIR*BB*DINN*LL];         // u   transposed [dir][b][d][t]
__device__ float g_dtt[NDIR*BB*DINN*LL];         // dt  transposed
__device__ float g_szt[NDIR*BB*DINN*LL];         // silu(z) transposed
__device__ float g_bct[NDIR*BB*2*NST*LL];        // B (n<16) / C (n>=16) transposed [dir][b][n][t]
__device__ float g_y  [NDIR*MROWS*DINN];         // gated scan output [dir][m][d]

// ---------------- prep: fold norm_w into in_proj, stack out_proj ----------------
__global__ __launch_bounds__(256) void k_prep(
    const float* __restrict__ inw_f, const float* __restrict__ nw_f,
    const float* __restrict__ inw_b, const float* __restrict__ nw_b,
    const float* __restrict__ ow_f,  const float* __restrict__ ow_b)
{
  int i = blockIdx.x*256 + threadIdx.x;
  if (i < N1*DD){
    int dir = i / (1024*DD);
    int rem = i - dir*1024*DD;
    int d = rem % DD;
    g_w1[i] = dir ? inw_b[rem]*nw_b[d] : inw_f[rem]*nw_f[d];
  }
  if (i < NDIR*DD*DINN){
    int dir = i / (DD*DINN);
    int rem = i - dir*DD*DINN;
    g_w2[i] = dir ? ow_b[rem] : ow_f[rem];
  }
}

// ---------------- rmsnorm (without weight; weight folded into g_w1) ----------------
__global__ __launch_bounds__(256) void k_rms(const float* __restrict__ x)
{
  int row = blockIdx.x;
  int tid = threadIdx.x;
  float v = x[row*DD + tid];
  float s = v*v;
  #pragma unroll
  for (int o = 16; o; o >>= 1) s += __shfl_xor_sync(0xffffffffu, s, o);
  __shared__ float ws[8];
  __shared__ float scale;
  if ((tid & 31) == 0) ws[tid >> 5] = s;
  __syncthreads();
  if (tid == 0){
    float t = 0.f;
    #pragma unroll
    for (int i = 0; i < 8; i++) t += ws[i];
    scale = rsqrtf(t*(1.0f/DD) + EPSF);
  }
  __syncthreads();
  g_xn[row*DD + tid] = v*scale;
}

// ---------------- generic fp32 tiled GEMM:  C = A * B^T (+resid) ----------------
// BM=BN=128, BK=8, 256 threads, 8x8 per thread.
__global__ __launch_bounds__(256) void k_gemm(
    const float* __restrict__ A, int lda, size_t aDirStride, int bpdX,
    const float* __restrict__ Bw, int ldb,
    float* __restrict__ C, int ldc,
    const float* __restrict__ resid, int K)
{
  const int BM = 128, BN = 128, BK = 8;
  __shared__ float As[BK][BM];
  __shared__ float Bs[BK][BN];
  int tid = threadIdx.x;
  int bx = blockIdx.x, by = blockIdx.y;
  int dir = bx / bpdX;
  A  += (size_t)dir*aDirStride + (size_t)by*BM*lda;
  Bw += (size_t)bx*BN*ldb;
  C  += (size_t)by*BM*ldc + (size_t)bx*BN;
  const float* R = resid ? (resid + (size_t)by*BM*DD + (size_t)(bx % bpdX)*BN) : nullptr;

  int lr = tid >> 1;            // 0..127 (row within tile for loads)
  int lc = (tid & 1)*4;         // 0 or 4 (k-offset for loads)
  int trow = (tid >> 4)*8;      // compute row base
  int tcol = (tid & 15)*8;      // compute col base

  float acc[8][8];
  #pragma unroll
  for (int i = 0; i < 8; i++)
    #pragma unroll
    for (int j = 0; j < 8; j++) acc[i][j] = 0.f;

  for (int k0 = 0; k0 < K; k0 += BK){
    float4 a4 = *(const float4*)(A  + (size_t)lr*lda + k0 + lc);
    float4 b4 = *(const float4*)(Bw + (size_t)lr*ldb + k0 + lc);
    As[lc+0][lr] = a4.x; As[lc+1][lr] = a4.y; As[lc+2][lr] = a4.z; As[lc+3][lr] = a4.w;
    Bs[lc+0][lr] = b4.x; Bs[lc+1][lr] = b4.y; Bs[lc+2][lr] = b4.z; Bs[lc+3][lr] = b4.w;
    __syncthreads();
    #pragma unroll
    for (int k = 0; k < BK; k++){
      float ra[8], rb[8];
      *(float4*)&ra[0] = *(const float4*)&As[k][trow];
      *(float4*)&ra[4] = *(const float4*)&As[k][trow+4];
      *(float4*)&rb[0] = *(const float4*)&Bs[k][tcol];
      *(float4*)&rb[4] = *(const float4*)&Bs[k][tcol+4];
      #pragma unroll
      for (int i = 0; i < 8; i++)
        #pragma unroll
        for (int j = 0; j < 8; j++)
          acc[i][j] = fmaf(ra[i], rb[j], acc[i][j]);
    }
    __syncthreads();
  }

  #pragma unroll
  for (int i = 0; i < 8; i++){
    float4 o0 = make_float4(acc[i][0], acc[i][1], acc[i][2], acc[i][3]);
    float4 o1 = make_float4(acc[i][4], acc[i][5], acc[i][6], acc[i][7]);
    if (R){
      const float4* rr = (const float4*)(R + (size_t)(trow+i)*DD + tcol);
      float4 r0 = rr[0], r1 = rr[1];
      o0.x += r0.x; o0.y += r0.y; o0.z += r0.z; o0.w += r0.w;
      o1.x += r1.x; o1.y += r1.y; o1.z += r1.z; o1.w += r1.w;
    }
    *(float4*)(C + (size_t)(trow+i)*ldc + tcol)     = o0;
    *(float4*)(C + (size_t)(trow+i)*ldc + tcol + 4) = o1;
  }
}

// ---------------- conv + silu + xproj + dtproj (+silu(z)), transposed outputs ----------------
__global__ __launch_bounds__(256) void k2_conv(
  const float* __restrict__ cw_f, const float* __restrict__ cb_f,
  const float* __restrict__ xw_f, const float* __restrict__ dw_f, const float* __restrict__ db_f,
  const float* __restrict__ cw_b, const float* __restrict__ cb_b,
  const float* __restrict__ xw_b, const float* __restrict__ dw_b, const float* __restrict__ db_b)
{
  extern __shared__ float dyn[];
  float* sxh = dyn;                       // (TT+3)*DINN
  float* su  = dyn + (TT+3)*DINN;         // DINN*(TT+1)  (pad 17 for bank-conflict-free transpose)
  __shared__ float sdbl[TT*48];

  int tid = threadIdx.x;
  int t0  = blockIdx.x*TT;
  int b   = blockIdx.y;
  int dir = blockIdx.z;

  const float* cw = dir ? cw_b : cw_f;
  const float* cb = dir ? cb_b : cb_f;
  const float* xw = dir ? xw_b : xw_f;
  const float* dw = dir ? dw_b : dw_f;
  const float* db = dir ? db_b : db_f;

  // fw: window [t0-3, t0+TT-1]; bw (anti-causal in orig coords): [t0, t0+TT+2]
  int wstart = dir ? t0 : t0 - 3;
  for (int i = tid; i < (TT+3)*DINN; i += 256){
    int r = i / DINN, d = i - r*DINN;
    int t = wstart + r;
    sxh[i] = (t >= 0 && t < LL) ? g_xz[(b*LL + t)*N1 + dir*1024 + d] : 0.f;
  }
  __syncthreads();

  // depthwise conv + silu -> su[d][t]
  #pragma unroll
  for (int c = 0; c < 2; c++){
    int d = tid + c*256;
    float w0 = cw[d*4+0], w1 = cw[d*4+1], w2 = cw[d*4+2], w3 = cw[d*4+3], b0 = cb[d];
    #pragma unroll
    for (int t = 0; t < TT; t++){
      float acc;
      if (dir == 0)
        acc = b0 + w0*sxh[(t+0)*DINN+d] + w1*sxh[(t+1)*DINN+d]
                 + w2*sxh[(t+2)*DINN+d] + w3*sxh[(t+3)*DINN+d];
      else
        acc = b0 + w0*sxh[(t+3)*DINN+d] + w1*sxh[(t+2)*DINN+d]
                 + w2*sxh[(t+1)*DINN+d] + w3*sxh[(t+0)*DINN+d];
      su[d*(TT+1) + t] = acc/(1.f + __expf(-acc));
    }
  }
  __syncthreads();

  // x_dbl: warp w handles timesteps w and w+8 (2x register blocking on u)
  {
    int w = tid >> 5, lane = tid & 31;
    float ur0[16], ur1[16];
    #pragma unroll
    for (int i = 0; i < 16; i++){
      ur0[i] = su[(lane + 32*i)*(TT+1) + w];
      ur1[i] = su[(lane + 32*i)*(TT+1) + w + 8];
    }
    for (int r = 0; r < 48; r++){
      const float* xr = xw + r*DINN;
      float a0 = 0.f, a1 = 0.f;
      #pragma unroll
      for (int i = 0; i < 16; i++){
        float wv = xr[lane + 32*i];
        a0 = fmaf(ur0[i], wv, a0);
        a1 = fmaf(ur1[i], wv, a1);
      }
      #pragma unroll
      for (int o = 16; o; o >>= 1){
        a0 += __shfl_xor_sync(0xffffffffu, a0, o);
        a1 += __shfl_xor_sync(0xffffffffu, a1, o);
      }
      if (lane == 0){ sdbl[w*48 + r] = a0; sdbl[(w+8)*48 + r] = a1; }
    }
  }
  __syncthreads();

  // dt = softplus(xdbl[:16] @ dtW^T + b); transposed stores of dt, u, silu(z)
  #pragma unroll
  for (int c = 0; c < 2; c++){
    int d = tid + c*256;
    float dwr[16];
    #pragma unroll
    for (int i = 0; i < 16; i += 4)
      *(float4*)&dwr[i] = *(const float4*)(dw + d*16 + i);
    float bd = db[d];
    float o[TT], uo[TT], zt[TT];
    #pragma unroll
    for (int t = 0; t < TT; t++){
      float s = bd;
      #pragma unroll
      for (int r = 0; r < 16; r++) s = fmaf(sdbl[t*48 + r], dwr[r], s);
      o[t]  = (s > 20.f) ? s : log1pf(__expf(s));
      uo[t] = su[d*(TT+1) + t];
      float z = g_xz[(b*LL + t0 + t)*N1 + dir*1024 + 512 + d];
      zt[t] = z/(1.f + __expf(-z));
    }
    int base = ((dir*BB + b)*DINN + d)*LL + t0;
    #pragma unroll
    for (int q = 0; q < TT; q += 4){
      *(float4*)&g_dtt[base+q] = make_float4(o[q],  o[q+1],  o[q+2],  o[q+3]);
      *(float4*)&g_ut [base+q] = make_float4(uo[q], uo[q+1], uo[q+2], uo[q+3]);
      *(float4*)&g_szt[base+q] = make_float4(zt[q], zt[q+1], zt[q+2], zt[q+3]);
    }
  }

  // B / C transposed store
  for (int i = tid; i < 32*TT; i += 256){
    int n = i >> 4;
    int t = i & 15;
    g_bct[((dir*BB + b)*32 + n)*LL + t0 + t] = sdbl[t*48 + 16 + n];
  }
}

// ---------------- selective scan: 16 lanes (states) per channel ----------------
#define SCAN_STEP(DT,UU,BV,CV,SZ,T) { \
  float dA = __expf((DT)*a); \
  h = fmaf(dA, h, (DT)*(BV)*(UU)); \
  float yc = h*(CV); \
  yc += __shfl_xor_sync(0xffffffffu, yc, 1); \
  yc += __shfl_xor_sync(0xffffffffu, yc, 2); \
  yc += __shfl_xor_sync(0xffffffffu, yc, 4); \
  yc += __shfl_xor_sync(0xffffffffu, yc, 8); \
  if (l0) py[(T)*DINN] = (yc + (UU)*dp)*(SZ); }

__global__ __launch_bounds__(256) void k3_scan(
  const float* __restrict__ alog_f, const float* __restrict__ alog_b,
  const float* __restrict__ Dpf,   const float* __restrict__ Dpb)
{
  int tid = threadIdx.x;
  int ch = blockIdx.x*16 + (tid >> 4);   // 0..4095
  int n  = tid & 15;
  int dir = ch >> 11;
  int b   = (ch >> 9) & 3;
  int d   = ch & 511;

  float a  = -__expf((dir ? alog_b : alog_f)[d*16 + n]);
  float dp = (dir ? Dpb : Dpf)[d];

  int cbase = ((dir*BB + b)*DINN + d)*LL;
  const float* pdt = g_dtt + cbase;
  const float* pu  = g_ut  + cbase;
  const float* psz = g_szt + cbase;
  const float* pB  = g_bct + ((dir*BB + b)*32 + n)*LL;
  const float* pC  = pB + 16*LL;
  float* py = g_y + (dir*MROWS + b*LL)*DINN + d;

  float h = 0.f;
  bool l0 = (n == 0);

  if (dir == 0){
    for (int t4 = 0; t4 < LL; t4 += 4){
      float4 dt4 = *(const float4*)(pdt + t4);
      float4 u4  = *(const float4*)(pu  + t4);
      float4 B4  = *(const float4*)(pB  + t4);
      float4 C4  = *(const float4*)(pC  + t4);
      float4 s4  = make_float4(0.f, 0.f, 0.f, 0.f);
      if (l0) s4 = *(const float4*)(psz + t4);
      SCAN_STEP(dt4.x, u4.x, B4.x, C4.x, s4.x, t4+0);
      SCAN_STEP(dt4.y, u4.y, B4.y, C4.y, s4.y, t4+1);
      SCAN_STEP(dt4.z, u4.z, B4.z, C4.z, s4.z, t4+2);
      SCAN_STEP(dt4.w, u4.w, B4.w, C4.w, s4.w, t4+3);
    }
  } else {
    for (int t4 = LL - 4; t4 >= 0; t4 -= 4){
      float4 dt4 = *(const float4*)(pdt + t4);
      float4 u4  = *(const float4*)(pu  + t4);
      float4 B4  = *(const float4*)(pB  + t4);
      float4 C4  = *(const float4*)(pC  + t4);
      float4 s4  = make_float4(0.f, 0.f, 0.f, 0.f);
      if (l0) s4 = *(const float4*)(psz + t4);
      SCAN_STEP(dt4.w, u4.w, B4.w, C4.w, s4.w, t4+3);
      SCAN_STEP(dt4.z, u4.z, B4.z, C4.z, s4.z, t4+2);
      SCAN_STEP(dt4.y, u4.y, B4.y, C4.y, s4.y, t4+1);
      SCAN_STEP(dt4.x, u4.x, B4.x, C4.x, s4.x, t4+0);
    }
  }
}

// ---------------- launch ----------------
extern "C" void kernel_launch(void* const* d_in, const int* in_sizes, int n_in,
                              void* d_out, int out_size)
{
  (void)in_sizes; (void)n_in; (void)out_size;
  const float* x       = (const float*)d_in[0];
  const float* fw_norm = (const float*)d_in[1];
  const float* fw_inw  = (const float*)d_in[2];
  const float* fw_cw   = (const float*)d_in[3];
  const float* fw_cb   = (const float*)d_in[4];
  const float* fw_xw   = (const float*)d_in[5];
  const float* fw_dw   = (const float*)d_in[6];
  const float* fw_db   = (const float*)d_in[7];
  const float* fw_al   = (const float*)d_in[8];
  const float* fw_Dp   = (const float*)d_in[9];
  const float* fw_ow   = (const float*)d_in[10];
  const float* bw_norm = (const float*)d_in[11];
  const float* bw_inw  = (const float*)d_in[12];
  const float* bw_cw   = (const float*)d_in[13];
  const float* bw_cb   = (const float*)d_in[14];
  const float* bw_xw   = (const float*)d_in[15];
  const float* bw_dw   = (const float*)d_in[16];
  const float* bw_db   = (const float*)d_in[17];
  const float* bw_al   = (const float*)d_in[18];
  const float* bw_Dp   = (const float*)d_in[19];
  const float* bw_ow   = (const float*)d_in[20];

  float *p_xn, *p_w1, *p_w2, *p_xz, *p_y;
  cudaGetSymbolAddress((void**)&p_xn, g_xn);
  cudaGetSymbolAddress((void**)&p_w1, g_w1);
  cudaGetSymbolAddress((void**)&p_w2, g_w2);
  cudaGetSymbolAddress((void**)&p_xz, g_xz);
  cudaGetSymbolAddress((void**)&p_y,  g_y);

  // 1) fold norm weights into in_proj, stack out_proj
  k_prep<<<2048, 256>>>(fw_inw, fw_norm, bw_inw, bw_norm, fw_ow, bw_ow);
  // 2) rmsnorm
  k_rms<<<MROWS, 256>>>(x);
  // 3) in_proj (both dirs in one GEMM, N = 2048)
  k_gemm<<<dim3(16, 64), 256>>>(p_xn, DD, (size_t)0, 1000000,
                                p_w1, DD, p_xz, N1, nullptr, DD);
  // 4) conv + silu + xproj + dtproj + silu(z)
  int smem2 = ((TT+3)*DINN + DINN*(TT+1))*(int)sizeof(float);
  cudaFuncSetAttribute(k2_conv, cudaFuncAttributeMaxDynamicSharedMemorySize, smem2);
  k2_conv<<<dim3(LL/TT, BB, NDIR), 256, smem2>>>(
      fw_cw, fw_cb, fw_xw, fw_dw, fw_db,
      bw_cw, bw_cb, bw_xw, bw_dw, bw_db);
  // 5) selective scan (fw forward-time, bw reverse-time)
  k3_scan<<<256, 256>>>(fw_al, bw_al, fw_Dp, bw_Dp);
  // 6) out_proj + residual, writes concat([yf, yb]) directly into d_out
  k_gemm<<<dim3(4, 64), 256>>>(p_y, DINN, (size_t)MROWS*DINN, 2,
                               p_w2, DINN, (float*)d_out, 2*DD, x, DINN);
}

// round 2
// speedup vs baseline: 1.3946x; 1.3946x over previous
#include <cuda_runtime.h>
#include <math.h>
#include <stdint.h>

#define BB 4
#define LL 2048
#define DD 256
#define DINN 512
#define NST 16
#define NDIR 2
#define MROWS (BB*LL)      // 8192
#define N1 2048            // NDIR * 2 * DINN
#define TT 16
#define EPSF 1e-5f

// ---------------- scratch (device globals; allocation-free) ----------------
__device__ float g_xn[MROWS*DD];                 // rmsnorm'd x
__device__ float g_w1[N1*DD];                    // stacked in_proj * norm_w
__device__ float g_w2[NDIR*DD*DINN];             // stacked out_proj
__device__ float g_xz[(size_t)MROWS*N1];         // in_proj output [m][dir*1024+e]
__device__ float g_ut [(size_t)NDIR*BB*DINN*LL]; // u transposed [dir][b][d][t]
__device__ float g_dtt[(size_t)NDIR*BB*DINN*LL]; // dt transposed
__device__ float g_szt[(size_t)NDIR*BB*DINN*LL]; // silu(z) transposed
__device__ float g_dbl[(size_t)NDIR*BB*48*LL];   // x_dbl [dir][b][r][t], r<16 dt-rank, 16..31 B, 32..47 C
__device__ float g_y  [(size_t)NDIR*MROWS*DINN]; // gated scan output

// ---------------- prep ----------------
__global__ __launch_bounds__(256) void k_prep(
    const float* __restrict__ inw_f, const float* __restrict__ nw_f,
    const float* __restrict__ inw_b, const float* __restrict__ nw_b,
    const float* __restrict__ ow_f,  const float* __restrict__ ow_b)
{
  int i = blockIdx.x*256 + threadIdx.x;
  if (i < N1*DD){
    int dir = i / (1024*DD);
    int rem = i - dir*1024*DD;
    int d = rem % DD;
    g_w1[i] = dir ? inw_b[rem]*nw_b[d] : inw_f[rem]*nw_f[d];
  }
  if (i < NDIR*DD*DINN){
    int dir = i / (DD*DINN);
    int rem = i - dir*DD*DINN;
    g_w2[i] = dir ? ow_b[rem] : ow_f[rem];
  }
}

// ---------------- rmsnorm ----------------
__global__ __launch_bounds__(256) void k_rms(const float* __restrict__ x)
{
  int row = blockIdx.x;
  int tid = threadIdx.x;
  float v = x[row*DD + tid];
  float s = v*v;
  #pragma unroll
  for (int o = 16; o; o >>= 1) s += __shfl_xor_sync(0xffffffffu, s, o);
  __shared__ float ws[8];
  __shared__ float scale;
  if ((tid & 31) == 0) ws[tid >> 5] = s;
  __syncthreads();
  if (tid == 0){
    float t = 0.f;
    #pragma unroll
    for (int i = 0; i < 8; i++) t += ws[i];
    scale = rsqrtf(t*(1.0f/DD) + EPSF);
  }
  __syncthreads();
  g_xn[row*DD + tid] = v*scale;
}

// ---------------- TF32 tensor-core GEMM:  C = A * B^T (+resid) ----------------
// BM=BN=128, BK=16, 256 threads = 8 warps (2x4), warp tile 64x32 via m16n8k8.
__device__ __forceinline__ uint32_t f2tf(float v){
  uint32_t r; asm("cvt.rna.tf32.f32 %0, %1;" : "=r"(r) : "f"(v)); return r;
}

__global__ __launch_bounds__(256) void k_gemm_tf32(
    const float* __restrict__ A, int lda, size_t aDirStride, int bpdX,
    const float* __restrict__ Bw, int ldb,
    float* __restrict__ C, int ldc,
    const float* __restrict__ resid, int rld, int K)
{
  const int BM = 128, BN = 128, BK = 16, LDS = 136;  // 8-uint skew -> conflict-free frags
  __shared__ uint32_t As[BK*LDS];
  __shared__ uint32_t Bs[BK*LDS];
  int tid = threadIdx.x;
  int bx = blockIdx.x, by = blockIdx.y;
  int dir = bx / bpdX;
  A  += (size_t)dir*aDirStride + (size_t)(by*BM)*lda;
  Bw += (size_t)(bx*BN)*ldb;
  C  += (size_t)(by*BM)*ldc + (size_t)(bx*BN);
  const float* R = resid ? (resid + (size_t)(by*BM)*rld + (size_t)(bx % bpdX)*BN) : nullptr;

  int lr = tid >> 1;            // 0..127
  int lc = (tid & 1)*8;         // 0 or 8
  int warp = tid >> 5, lane = tid & 31;
  int wm = (warp >> 2)*64, wn = (warp & 3)*32;
  int g  = lane >> 2, tq = lane & 3;

  float acc[4][4][4];
  #pragma unroll
  for (int i = 0; i < 4; i++)
    #pragma unroll
    for (int j = 0; j < 4; j++)
      #pragma unroll
      for (int q = 0; q < 4; q++) acc[i][j][q] = 0.f;

  for (int k0 = 0; k0 < K; k0 += BK){
    float4 a0 = *(const float4*)(A  + (size_t)lr*lda + k0 + lc);
    float4 a1 = *(const float4*)(A  + (size_t)lr*lda + k0 + lc + 4);
    float4 b0 = *(const float4*)(Bw + (size_t)lr*ldb + k0 + lc);
    float4 b1 = *(const float4*)(Bw + (size_t)lr*ldb + k0 + lc + 4);
    __syncthreads();   // previous iteration finished reading smem
    As[(lc+0)*LDS+lr]=f2tf(a0.x); As[(lc+1)*LDS+lr]=f2tf(a0.y);
    As[(lc+2)*LDS+lr]=f2tf(a0.z); As[(lc+3)*LDS+lr]=f2tf(a0.w);
    As[(lc+4)*LDS+lr]=f2tf(a1.x); As[(lc+5)*LDS+lr]=f2tf(a1.y);
    As[(lc+6)*LDS+lr]=f2tf(a1.z); As[(lc+7)*LDS+lr]=f2tf(a1.w);
    Bs[(lc+0)*LDS+lr]=f2tf(b0.x); Bs[(lc+1)*LDS+lr]=f2tf(b0.y);
    Bs[(lc+2)*LDS+lr]=f2tf(b0.z); Bs[(lc+3)*LDS+lr]=f2tf(b0.w);
    Bs[(lc+4)*LDS+lr]=f2tf(b1.x); Bs[(lc+5)*LDS+lr]=f2tf(b1.y);
    Bs[(lc+6)*LDS+lr]=f2tf(b1.z); Bs[(lc+7)*LDS+lr]=f2tf(b1.w);
    __syncthreads();

    #pragma unroll
    for (int k8 = 0; k8 < BK; k8 += 8){
      uint32_t af[4][4], bf[4][2];
      #pragma unroll
      for (int mm = 0; mm < 4; mm++){
        int mbase = wm + mm*16;
        af[mm][0] = As[(k8+tq  )*LDS + mbase + g];
        af[mm][1] = As[(k8+tq  )*LDS + mbase + g + 8];
        af[mm][2] = As[(k8+tq+4)*LDS + mbase + g];
        af[mm][3] = As[(k8+tq+4)*LDS + mbase + g + 8];
      }
      #pragma unroll
      for (int nn = 0; nn < 4; nn++){
        int nbase = wn + nn*8;
        bf[nn][0] = Bs[(k8+tq  )*LDS + nbase + g];
        bf[nn][1] = Bs[(k8+tq+4)*LDS + nbase + g];
      }
      #pragma unroll
      for (int mm = 0; mm < 4; mm++)
        #pragma unroll
        for (int nn = 0; nn < 4; nn++){
          asm volatile(
            "mma.sync.aligned.m16n8k8.row.col.f32.tf32.tf32.f32 "
            "{%0,%1,%2,%3}, {%4,%5,%6,%7}, {%8,%9}, {%0,%1,%2,%3};\n"
            : "+f"(acc[mm][nn][0]), "+f"(acc[mm][nn][1]),
              "+f"(acc[mm][nn][2]), "+f"(acc[mm][nn][3])
            : "r"(af[mm][0]), "r"(af[mm][1]), "r"(af[mm][2]), "r"(af[mm][3]),
              "r"(bf[nn][0]), "r"(bf[nn][1]));
        }
    }
  }

  #pragma unroll
  for (int mm = 0; mm < 4; mm++)
    #pragma unroll
    for (int nn = 0; nn < 4; nn++){
      int row0 = wm + mm*16 + g;
      int col  = wn + nn*8 + 2*tq;
      float2 v0 = make_float2(acc[mm][nn][0], acc[mm][nn][1]);
      float2 v1 = make_float2(acc[mm][nn][2], acc[mm][nn][3]);
      if (R){
        float2 r0 = *(const float2*)(R + (size_t)row0*rld + col);
        float2 r1 = *(const float2*)(R + (size_t)(row0+8)*rld + col);
        v0.x += r0.x; v0.y += r0.y; v1.x += r1.x; v1.y += r1.y;
      }
      *(float2*)(C + (size_t)row0*ldc + col)     = v0;
      *(float2*)(C + (size_t)(row0+8)*ldc + col) = v1;
    }
}

// ---------------- depthwise conv + silu + silu(z), transposed stores ----------------
__global__ __launch_bounds__(256) void k_conv(
  const float* __restrict__ cw_f, const float* __restrict__ cb_f,
  const float* __restrict__ cw_b, const float* __restrict__ cb_b)
{
  __shared__ float sxh[(TT+3)*DINN];
  int tid = threadIdx.x;
  int t0  = blockIdx.x*TT;
  int b   = blockIdx.y;
  int dir = blockIdx.z;
  const float* cw = dir ? cw_b : cw_f;
  const float* cb = dir ? cb_b : cb_f;

  int wstart = dir ? t0 : t0 - 3;
  for (int i = tid; i < (TT+3)*DINN; i += 256){
    int r = i / DINN, d = i - r*DINN;
    int t = wstart + r;
    sxh[i] = (t >= 0 && t < LL) ? g_xz[(size_t)(b*LL + t)*N1 + dir*1024 + d] : 0.f;
  }
  __syncthreads();

  #pragma unroll
  for (int c = 0; c < 2; c++){
    int d = tid + c*256;
    float w0 = cw[d*4+0], w1 = cw[d*4+1], w2 = cw[d*4+2], w3 = cw[d*4+3], b0 = cb[d];
    float uo[TT], zt[TT];
    #pragma unroll
    for (int t = 0; t < TT; t++){
      float acc;
      if (dir == 0)
        acc = b0 + w0*sxh[(t+0)*DINN+d] + w1*sxh[(t+1)*DINN+d]
                 + w2*sxh[(t+2)*DINN+d] + w3*sxh[(t+3)*DINN+d];
      else
        acc = b0 + w0*sxh[(t+3)*DINN+d] + w1*sxh[(t+2)*DINN+d]
                 + w2*sxh[(t+1)*DINN+d] + w3*sxh[(t+0)*DINN+d];
      uo[t] = acc/(1.f + __expf(-acc));
      float z = g_xz[(size_t)(b*LL + t0 + t)*N1 + dir*1024 + 512 + d];
      zt[t] = z/(1.f + __expf(-z));
    }
    size_t base = ((size_t)((dir*BB + b)*DINN + d))*LL + t0;
    #pragma unroll
    for (int q = 0; q < TT; q += 4){
      *(float4*)&g_ut [base+q] = make_float4(uo[q], uo[q+1], uo[q+2], uo[q+3]);
      *(float4*)&g_szt[base+q] = make_float4(zt[q], zt[q+1], zt[q+2], zt[q+3]);
    }
  }
}

// ---------------- x_dbl = xw(48x512) @ u_t(512xL)  -> g_dbl[dir][b][48][L] ----------------
__global__ __launch_bounds__(256) void k_xproj(
  const float* __restrict__ xw_f, const float* __restrict__ xw_b)
{
  extern __shared__ float dyn[];
  float* sw = dyn;                 // [48][64]
  float* su = dyn + 48*64;         // [64][132]
  float* sx = su + 64*132;         // [48][132]

  int tid = threadIdx.x;
  int t0  = blockIdx.x*128;
  int b   = blockIdx.y;
  int dir = blockIdx.z;
  const float* xw = dir ? xw_b : xw_f;

  int col = 2*(tid & 63);
  int rq  = tid >> 6;              // 0..3 -> rows rq*12 .. rq*12+11
  float acc[12][2];
  #pragma unroll
  for (int r = 0; r < 12; r++){ acc[r][0] = 0.f; acc[r][1] = 0.f; }

  size_t ubase = (size_t)(dir*BB + b)*DINN*LL;
  for (int k0 = 0; k0 < DINN; k0 += 64){
    for (int i = tid; i < 48*64; i += 256){
      int r = i >> 6, k = i & 63;
      sw[i] = xw[r*DINN + k0 + k];
    }
    for (int j = tid; j < 64*32; j += 256){
      int row = j >> 5, ts = (j & 31)*4;
      *(float4*)&su[row*132 + ts] =
        *(const float4*)(g_ut + ubase + (size_t)(k0+row)*LL + t0 + ts);
    }
    __syncthreads();
    #pragma unroll 8
    for (int k = 0; k < 64; k++){
      float u0 = su[k*132 + col];
      float u1 = su[k*132 + col + 1];
      #pragma unroll
      for (int r = 0; r < 12; r++){
        float w = sw[(rq*12 + r)*64 + k];
        acc[r][0] = fmaf(w, u0, acc[r][0]);
        acc[r][1] = fmaf(w, u1, acc[r][1]);
      }
    }
    __syncthreads();
  }

  #pragma unroll
  for (int r = 0; r < 12; r++){
    sx[(rq*12 + r)*132 + col]     = acc[r][0];
    sx[(rq*12 + r)*132 + col + 1] = acc[r][1];
  }
  __syncthreads();
  size_t obase = (size_t)(dir*BB + b)*48*LL;
  for (int i = tid; i < 48*32; i += 256){
    int row = i >> 5, seg = (i & 31)*4;
    *(float4*)&g_dbl[obase + (size_t)row*LL + t0 + seg] = *(float4*)&sx[row*132 + seg];
  }
}

// ---------------- dt = softplus(dtw @ x_dbl[0:16] + b) -> g_dtt[dir][b][d][t] ----------------
__global__ __launch_bounds__(512) void k_dt(
  const float* __restrict__ dw_f, const float* __restrict__ db_f,
  const float* __restrict__ dw_b, const float* __restrict__ db_b)
{
  int d   = threadIdx.x;
  int t0  = blockIdx.x*128;
  int b   = blockIdx.y;
  int dir = blockIdx.z;
  const float* dw = dir ? dw_b : dw_f;
  const float* db = dir ? db_b : db_f;

  float dwr[16];
  #pragma unroll
  for (int i = 0; i < 16; i += 4)
    *(float4*)&dwr[i] = *(const float4*)(dw + d*16 + i);
  float bd = db[d];

  const float* px = g_dbl + (size_t)(dir*BB + b)*48*LL;
  float* po = g_dtt + ((size_t)((dir*BB + b)*DINN + d))*LL;

  for (int tt = 0; tt < 128; tt += 4){
    int t = t0 + tt;
    float s0 = bd, s1 = bd, s2 = bd, s3 = bd;
    #pragma unroll
    for (int r = 0; r < 16; r++){
      float4 xv = *(const float4*)(px + (size_t)r*LL + t);
      s0 = fmaf(dwr[r], xv.x, s0);
      s1 = fmaf(dwr[r], xv.y, s1);
      s2 = fmaf(dwr[r], xv.z, s2);
      s3 = fmaf(dwr[r], xv.w, s3);
    }
    s0 = (s0 > 20.f) ? s0 : log1pf(__expf(s0));
    s1 = (s1 > 20.f) ? s1 : log1pf(__expf(s1));
    s2 = (s2 > 20.f) ? s2 : log1pf(__expf(s2));
    s3 = (s3 > 20.f) ? s3 : log1pf(__expf(s3));
    *(float4*)(po + t) = make_float4(s0, s1, s2, s3);
  }
}

// ---------------- selective scan: 16 lanes (states) per channel ----------------
#define SCAN_STEP(DT,UU,BV,CV,SZ,T) { \
  float dA = __expf((DT)*a); \
  h = fmaf(dA, h, (DT)*(BV)*(UU)); \
  float yc = h*(CV); \
  yc += __shfl_xor_sync(0xffffffffu, yc, 1); \
  yc += __shfl_xor_sync(0xffffffffu, yc, 2); \
  yc += __shfl_xor_sync(0xffffffffu, yc, 4); \
  yc += __shfl_xor_sync(0xffffffffu, yc, 8); \
  if (l0) py[(size_t)(T)*DINN] = (yc + (UU)*dp)*(SZ); }

__global__ __launch_bounds__(256) void k3_scan(
  const float* __restrict__ alog_f, const float* __restrict__ alog_b,
  const float* __restrict__ Dpf,   const float* __restrict__ Dpb)
{
  int tid = threadIdx.x;
  int ch = blockIdx.x*16 + (tid >> 4);   // 0..4095
  int n  = tid & 15;
  int dir = ch >> 11;
  int b   = (ch >> 9) & 3;
  int d   = ch & 511;

  float a  = -__expf((dir ? alog_b : alog_f)[d*16 + n]);
  float dp = (dir ? Dpb : Dpf)[d];

  size_t cbase = ((size_t)((dir*BB + b)*DINN + d))*LL;
  const float* pdt = g_dtt + cbase;
  const float* pu  = g_ut  + cbase;
  const float* psz = g_szt + cbase;
  const float* pB  = g_dbl + ((size_t)(dir*BB + b)*48 + 16 + n)*LL;
  const float* pC  = pB + 16*LL;
  float* py = g_y + (size_t)(dir*MROWS + b*LL)*DINN + d;

  float h = 0.f;
  bool l0 = (n == 0);

  if (dir == 0){
    for (int t4 = 0; t4 < LL; t4 += 4){
      float4 dt4 = *(const float4*)(pdt + t4);
      float4 u4  = *(const float4*)(pu  + t4);
      float4 B4  = *(const float4*)(pB  + t4);
      float4 C4  = *(const float4*)(pC  + t4);
      float4 s4  = make_float4(0.f, 0.f, 0.f, 0.f);
      if (l0) s4 = *(const float4*)(psz + t4);
      SCAN_STEP(dt4.x, u4.x, B4.x, C4.x, s4.x, t4+0);
      SCAN_STEP(dt4.y, u4.y, B4.y, C4.y, s4.y, t4+1);
      SCAN_STEP(dt4.z, u4.z, B4.z, C4.z, s4.z, t4+2);
      SCAN_STEP(dt4.w, u4.w, B4.w, C4.w, s4.w, t4+3);
    }
  } else {
    for (int t4 = LL - 4; t4 >= 0; t4 -= 4){
      float4 dt4 = *(const float4*)(pdt + t4);
      float4 u4  = *(const float4*)(pu  + t4);
      float4 B4  = *(const float4*)(pB  + t4);
      float4 C4  = *(const float4*)(pC  + t4);
      float4 s4  = make_float4(0.f, 0.f, 0.f, 0.f);
      if (l0) s4 = *(const float4*)(psz + t4);
      SCAN_STEP(dt4.w, u4.w, B4.w, C4.w, s4.w, t4+3);
      SCAN_STEP(dt4.z, u4.z, B4.z, C4.z, s4.z, t4+2);
      SCAN_STEP(dt4.y, u4.y, B4.y, C4.y, s4.y, t4+1);
      SCAN_STEP(dt4.x, u4.x, B4.x, C4.x, s4.x, t4+0);
    }
  }
}

// ---------------- launch ----------------
extern "C" void kernel_launch(void* const* d_in, const int* in_sizes, int n_in,
                              void* d_out, int out_size)
{
  (void)in_sizes; (void)n_in; (void)out_size;
  const float* x       = (const float*)d_in[0];
  const float* fw_norm = (const float*)d_in[1];
  const float* fw_inw  = (const float*)d_in[2];
  const float* fw_cw   = (const float*)d_in[3];
  const float* fw_cb   = (const float*)d_in[4];
  const float* fw_xw   = (const float*)d_in[5];
  const float* fw_dw   = (const float*)d_in[6];
  const float* fw_db   = (const float*)d_in[7];
  const float* fw_al   = (const float*)d_in[8];
  const float* fw_Dp   = (const float*)d_in[9];
  const float* fw_ow   = (const float*)d_in[10];
  const float* bw_norm = (const float*)d_in[11];
  const float* bw_inw  = (const float*)d_in[12];
  const float* bw_cw   = (const float*)d_in[13];
  const float* bw_cb   = (const float*)d_in[14];
  const float* bw_xw   = (const float*)d_in[15];
  const float* bw_dw   = (const float*)d_in[16];
  const float* bw_db   = (const float*)d_in[17];
  const float* bw_al   = (const float*)d_in[18];
  const float* bw_Dp   = (const float*)d_in[19];
  const float* bw_ow   = (const float*)d_in[20];

  float *p_xn, *p_w1, *p_w2, *p_xz, *p_y;
  cudaGetSymbolAddress((void**)&p_xn, g_xn);
  cudaGetSymbolAddress((void**)&p_w1, g_w1);
  cudaGetSymbolAddress((void**)&p_w2, g_w2);
  cudaGetSymbolAddress((void**)&p_xz, g_xz);
  cudaGetSymbolAddress((void**)&p_y,  g_y);

  // 1) fold norm weights into in_proj, stack out_proj
  k_prep<<<2048, 256>>>(fw_inw, fw_norm, bw_inw, bw_norm, fw_ow, bw_ow);
  // 2) rmsnorm
  k_rms<<<MROWS, 256>>>(x);
  // 3) in_proj (tf32 tensor cores): [8192 x 2048] = xn[8192x256] @ w1^T
  k_gemm_tf32<<<dim3(16, 64), 256>>>(p_xn, DD, (size_t)0, 1000000,
                                     p_w1, DD, p_xz, N1, nullptr, DD, DD);
  // 4) conv + silu + silu(z) (transposed stores)
  k_conv<<<dim3(LL/TT, BB, NDIR), 256>>>(fw_cw, fw_cb, bw_cw, bw_cb);
  // 5) x_dbl projection
  int smemx = (48*64 + 64*132 + 48*132)*(int)sizeof(float);
  cudaFuncSetAttribute(k_xproj, cudaFuncAttributeMaxDynamicSharedMemorySize, smemx);
  k_xproj<<<dim3(LL/128, BB, NDIR), 256, smemx>>>(fw_xw, bw_xw);
  // 6) dt projection + softplus
  k_dt<<<dim3(LL/128, BB, NDIR), 512>>>(fw_dw, fw_db, bw_dw, bw_db);
  // 7) selective scan
  k3_scan<<<256, 256>>>(fw_al, bw_al, fw_Dp, bw_Dp);
  // 8) out_proj + residual (tf32), writes concat([yf, yb]) into d_out
  k_gemm_tf32<<<dim3(4, 64), 256>>>(p_y, DINN, (size_t)MROWS*DINN, 2,
                                    p_w2, DINN, (float*)d_out, 2*DD, x, DD, DINN);
}

// round 3
// speedup vs baseline: 1.4690x; 1.0533x over previous
#include <cuda_runtime.h>
#include <math.h>
#include <stdint.h>

#define BB 4
#define LL 2048
#define DD 256
#define DINN 512
#define NST 16
#define NDIR 2
#define MROWS (BB*LL)      // 8192
#define N1 2048            // NDIR * 2 * DINN
#define EPSF 1e-5f

// ---------------- scratch (device globals; allocation-free) ----------------
__device__ float g_xn[MROWS*DD];                 // rmsnorm'd x
__device__ float g_w1[N1*DD];                    // stacked in_proj * norm_w
__device__ float g_w2[NDIR*DD*DINN];             // stacked out_proj
__device__ float g_xzT[(size_t)N1*MROWS];        // in_proj output TRANSPOSED [e][b*L+t]
__device__ float g_ut [(size_t)NDIR*BB*DINN*LL]; // u transposed [dir][b][d][t]
__device__ float g_dtt[(size_t)NDIR*BB*DINN*LL]; // dt transposed
__device__ float g_dbl[(size_t)NDIR*BB*48*LL];   // x_dbl [dir][b][r][t]; r<16 dt-rank, 16..31 B, 32..47 C
__device__ float g_y  [(size_t)NDIR*MROWS*DINN]; // gated scan output

// ---------------- prep ----------------
__global__ __launch_bounds__(256) void k_prep(
    const float* __restrict__ inw_f, const float* __restrict__ nw_f,
    const float* __restrict__ inw_b, const float* __restrict__ nw_b,
    const float* __restrict__ ow_f,  const float* __restrict__ ow_b)
{
  int i = blockIdx.x*256 + threadIdx.x;
  if (i < N1*DD){
    int dir = i / (1024*DD);
    int rem = i - dir*1024*DD;
    int d = rem % DD;
    g_w1[i] = dir ? inw_b[rem]*nw_b[d] : inw_f[rem]*nw_f[d];
  }
  if (i < NDIR*DD*DINN){
    int dir = i / (DD*DINN);
    int rem = i - dir*DD*DINN;
    g_w2[i] = dir ? ow_b[rem] : ow_f[rem];
  }
}

// ---------------- rmsnorm ----------------
__global__ __launch_bounds__(256) void k_rms(const float* __restrict__ x)
{
  int row = blockIdx.x;
  int tid = threadIdx.x;
  float v = x[row*DD + tid];
  float s = v*v;
  #pragma unroll
  for (int o = 16; o; o >>= 1) s += __shfl_xor_sync(0xffffffffu, s, o);
  __shared__ float ws[8];
  __shared__ float scale;
  if ((tid & 31) == 0) ws[tid >> 5] = s;
  __syncthreads();
  if (tid == 0){
    float t = 0.f;
    #pragma unroll
    for (int i = 0; i < 8; i++) t += ws[i];
    scale = rsqrtf(t*(1.0f/DD) + EPSF);
  }
  __syncthreads();
  g_xn[row*DD + tid] = v*scale;
}

// ---------------- TF32 tensor-core GEMM:  C = A * B^T (+resid) ----------------
__device__ __forceinline__ uint32_t f2tf(float v){
  uint32_t r; asm("cvt.rna.tf32.f32 %0, %1;" : "=r"(r) : "f"(v)); return r;
}

__global__ __launch_bounds__(256) void k_gemm_tf32(
    const float* __restrict__ A, int lda, size_t aDirStride, int bpdX,
    const float* __restrict__ Bw, int ldb,
    float* __restrict__ C, int ldc,
    const float* __restrict__ resid, int rld, int K)
{
  const int BM = 128, BN = 128, BK = 16, LDS = 136;
  __shared__ uint32_t As[BK*LDS];
  __shared__ uint32_t Bs[BK*LDS];
  int tid = threadIdx.x;
  int bx = blockIdx.x, by = blockIdx.y;
  int dir = bx / bpdX;
  A  += (size_t)dir*aDirStride + (size_t)(by*BM)*lda;
  Bw += (size_t)(bx*BN)*ldb;
  C  += (size_t)(by*BM)*ldc + (size_t)(bx*BN);
  const float* R = resid ? (resid + (size_t)(by*BM)*rld + (size_t)(bx % bpdX)*BN) : nullptr;

  int lr = tid >> 1;
  int lc = (tid & 1)*8;
  int warp = tid >> 5, lane = tid & 31;
  int wm = (warp >> 2)*64, wn = (warp & 3)*32;
  int g  = lane >> 2, tq = lane & 3;

  float acc[4][4][4];
  #pragma unroll
  for (int i = 0; i < 4; i++)
    #pragma unroll
    for (int j = 0; j < 4; j++)
      #pragma unroll
      for (int q = 0; q < 4; q++) acc[i][j][q] = 0.f;

  for (int k0 = 0; k0 < K; k0 += BK){
    float4 a0 = *(const float4*)(A  + (size_t)lr*lda + k0 + lc);
    float4 a1 = *(const float4*)(A  + (size_t)lr*lda + k0 + lc + 4);
    float4 b0 = *(const float4*)(Bw + (size_t)lr*ldb + k0 + lc);
    float4 b1 = *(const float4*)(Bw + (size_t)lr*ldb + k0 + lc + 4);
    __syncthreads();
    As[(lc+0)*LDS+lr]=f2tf(a0.x); As[(lc+1)*LDS+lr]=f2tf(a0.y);
    As[(lc+2)*LDS+lr]=f2tf(a0.z); As[(lc+3)*LDS+lr]=f2tf(a0.w);
    As[(lc+4)*LDS+lr]=f2tf(a1.x); As[(lc+5)*LDS+lr]=f2tf(a1.y);
    As[(lc+6)*LDS+lr]=f2tf(a1.z); As[(lc+7)*LDS+lr]=f2tf(a1.w);
    Bs[(lc+0)*LDS+lr]=f2tf(b0.x); Bs[(lc+1)*LDS+lr]=f2tf(b0.y);
    Bs[(lc+2)*LDS+lr]=f2tf(b0.z); Bs[(lc+3)*LDS+lr]=f2tf(b0.w);
    Bs[(lc+4)*LDS+lr]=f2tf(b1.x); Bs[(lc+5)*LDS+lr]=f2tf(b1.y);
    Bs[(lc+6)*LDS+lr]=f2tf(b1.z); Bs[(lc+7)*LDS+lr]=f2tf(b1.w);
    __syncthreads();

    #pragma unroll
    for (int k8 = 0; k8 < BK; k8 += 8){
      uint32_t af[4][4], bf[4][2];
      #pragma unroll
      for (int mm = 0; mm < 4; mm++){
        int mbase = wm + mm*16;
        af[mm][0] = As[(k8+tq  )*LDS + mbase + g];
        af[mm][1] = As[(k8+tq  )*LDS + mbase + g + 8];
        af[mm][2] = As[(k8+tq+4)*LDS + mbase + g];
        af[mm][3] = As[(k8+tq+4)*LDS + mbase + g + 8];
      }
      #pragma unroll
      for (int nn = 0; nn < 4; nn++){
        int nbase = wn + nn*8;
        bf[nn][0] = Bs[(k8+tq  )*LDS + nbase + g];
        bf[nn][1] = Bs[(k8+tq+4)*LDS + nbase + g];
      }
      #pragma unroll
      for (int mm = 0; mm < 4; mm++)
        #pragma unroll
        for (int nn = 0; nn < 4; nn++){
          asm volatile(
            "mma.sync.aligned.m16n8k8.row.col.f32.tf32.tf32.f32 "
            "{%0,%1,%2,%3}, {%4,%5,%6,%7}, {%8,%9}, {%0,%1,%2,%3};\n"
            : "+f"(acc[mm][nn][0]), "+f"(acc[mm][nn][1]),
              "+f"(acc[mm][nn][2]), "+f"(acc[mm][nn][3])
            : "r"(af[mm][0]), "r"(af[mm][1]), "r"(af[mm][2]), "r"(af[mm][3]),
              "r"(bf[nn][0]), "r"(bf[nn][1]));
        }
    }
  }

  #pragma unroll
  for (int mm = 0; mm < 4; mm++)
    #pragma unroll
    for (int nn = 0; nn < 4; nn++){
      int row0 = wm + mm*16 + g;
      int col  = wn + nn*8 + 2*tq;
      float2 v0 = make_float2(acc[mm][nn][0], acc[mm][nn][1]);
      float2 v1 = make_float2(acc[mm][nn][2], acc[mm][nn][3]);
      if (R){
        float2 r0 = *(const float2*)(R + (size_t)row0*rld + col);
        float2 r1 = *(const float2*)(R + (size_t)(row0+8)*rld + col);
        v0.x += r0.x; v0.y += r0.y; v1.x += r1.x; v1.y += r1.y;
      }
      *(float2*)(C + (size_t)row0*ldc + col)     = v0;
      *(float2*)(C + (size_t)(row0+8)*ldc + col) = v1;
    }
}

// ---------------- depthwise conv + silu, fully coalesced ----------------
// block = one (dir, d, b) channel-sequence; read 2051 floats, write 2048.
__global__ __launch_bounds__(256) void k_conv(
  const float* __restrict__ cw_f, const float* __restrict__ cb_f,
  const float* __restrict__ cw_b, const float* __restrict__ cb_b)
{
  __shared__ float s[LL + 4];
  int tid = threadIdx.x;
  int b   = blockIdx.x;
  int d   = blockIdx.y;
  int dir = blockIdx.z;

  const float* cw = dir ? cw_b : cw_f;
  const float* cb = dir ? cb_b : cb_f;
  // fw taps (w0,w1,w2,w3) on s[t..t+3] where s[i]=x[i-3]
  // bw taps (w3,w2,w1,w0) on s[t..t+3] where s[i]=x[i]
  float c0, c1, c2, c3;
  if (dir == 0){ c0 = cw[d*4+0]; c1 = cw[d*4+1]; c2 = cw[d*4+2]; c3 = cw[d*4+3]; }
  else         { c0 = cw[d*4+3]; c1 = cw[d*4+2]; c2 = cw[d*4+1]; c3 = cw[d*4+0]; }
  float bias = cb[d];

  const float* xrow = g_xzT + ((size_t)(dir*1024 + d))*MROWS + b*LL;

  if (dir == 0){
    for (int i = tid; i < LL + 3; i += 256)
      s[i] = (i >= 3) ? xrow[i-3] : 0.f;
  } else {
    for (int i = tid; i < LL + 3; i += 256)
      s[i] = (i < LL) ? xrow[i] : 0.f;
  }
  __syncthreads();

  float* urow = g_ut + ((size_t)((dir*BB + b)*DINN + d))*LL;
  int t0 = tid*8;
  float o[8];
  #pragma unroll
  for (int j = 0; j < 8; j++){
    int t = t0 + j;
    float acc = bias + c0*s[t] + c1*s[t+1] + c2*s[t+2] + c3*s[t+3];
    o[j] = acc/(1.f + __expf(-acc));
  }
  *(float4*)(urow + t0)     = make_float4(o[0], o[1], o[2], o[3]);
  *(float4*)(urow + t0 + 4) = make_float4(o[4], o[5], o[6], o[7]);
}

// ---------------- x_dbl = xw(48x512) @ u_t(512xL)  -> g_dbl[dir][b][48][t] ----------------
__global__ __launch_bounds__(256) void k_xproj(
  const float* __restrict__ xw_f, const float* __restrict__ xw_b)
{
  extern __shared__ float dyn[];
  float* sw = dyn;                 // [48][64]
  float* su = dyn + 48*64;         // [64][132]
  float* sx = su + 64*132;         // [48][132]

  int tid = threadIdx.x;
  int t0  = blockIdx.x*128;
  int b   = blockIdx.y;
  int dir = blockIdx.z;
  const float* xw = dir ? xw_b : xw_f;

  int col = 2*(tid & 63);
  int rq  = tid >> 6;
  float acc[12][2];
  #pragma unroll
  for (int r = 0; r < 12; r++){ acc[r][0] = 0.f; acc[r][1] = 0.f; }

  size_t ubase = (size_t)(dir*BB + b)*DINN*LL;
  for (int k0 = 0; k0 < DINN; k0 += 64){
    for (int i = tid; i < 48*64; i += 256){
      int r = i >> 6, k = i & 63;
      sw[i] = xw[r*DINN + k0 + k];
    }
    for (int j = tid; j < 64*32; j += 256){
      int row = j >> 5, ts = (j & 31)*4;
      *(float4*)&su[row*132 + ts] =
        *(const float4*)(g_ut + ubase + (size_t)(k0+row)*LL + t0 + ts);
    }
    __syncthreads();
    #pragma unroll 8
    for (int k = 0; k < 64; k++){
      float u0 = su[k*132 + col];
      float u1 = su[k*132 + col + 1];
      #pragma unroll
      for (int r = 0; r < 12; r++){
        float w = sw[(rq*12 + r)*64 + k];
        acc[r][0] = fmaf(w, u0, acc[r][0]);
        acc[r][1] = fmaf(w, u1, acc[r][1]);
      }
    }
    __syncthreads();
  }

  #pragma unroll
  for (int r = 0; r < 12; r++){
    sx[(rq*12 + r)*132 + col]     = acc[r][0];
    sx[(rq*12 + r)*132 + col + 1] = acc[r][1];
  }
  __syncthreads();
  size_t obase = (size_t)(dir*BB + b)*48*LL;
  for (int i = tid; i < 48*32; i += 256){
    int row = i >> 5, seg = (i & 31)*4;
    *(float4*)&g_dbl[obase + (size_t)row*LL + t0 + seg] = *(float4*)&sx[row*132 + seg];
  }
}

// ---------------- dt = softplus(dtw @ x_dbl[0:16] + b) -> g_dtt ----------------
__global__ __launch_bounds__(512) void k_dt(
  const float* __restrict__ dw_f, const float* __restrict__ db_f,
  const float* __restrict__ dw_b, const float* __restrict__ db_b)
{
  int d   = threadIdx.x;
  int t0  = blockIdx.x*128;
  int b   = blockIdx.y;
  int dir = blockIdx.z;
  const float* dw = dir ? dw_b : dw_f;
  const float* db = dir ? db_b : db_f;

  float dwr[16];
  #pragma unroll
  for (int i = 0; i < 16; i += 4)
    *(float4*)&dwr[i] = *(const float4*)(dw + d*16 + i);
  float bd = db[d];

  const float* px = g_dbl + (size_t)(dir*BB + b)*48*LL;
  float* po = g_dtt + ((size_t)((dir*BB + b)*DINN + d))*LL;

  for (int tt = 0; tt < 128; tt += 4){
    int t = t0 + tt;
    float s0 = bd, s1 = bd, s2 = bd, s3 = bd;
    #pragma unroll
    for (int r = 0; r < 16; r++){
      float4 xv = *(const float4*)(px + (size_t)r*LL + t);
      s0 = fmaf(dwr[r], xv.x, s0);
      s1 = fmaf(dwr[r], xv.y, s1);
      s2 = fmaf(dwr[r], xv.z, s2);
      s3 = fmaf(dwr[r], xv.w, s3);
    }
    s0 = (s0 > 20.f) ? s0 : log1pf(__expf(s0));
    s1 = (s1 > 20.f) ? s1 : log1pf(__expf(s1));
    s2 = (s2 > 20.f) ? s2 : log1pf(__expf(s2));
    s3 = (s3 > 20.f) ? s3 : log1pf(__expf(s3));
    *(float4*)(po + t) = make_float4(s0, s1, s2, s3);
  }
}

// ---------------- selective scan: 16 lanes (states) per channel ----------------
#define SCAN_STEP(DT,UU,BV,CV,SZ,T) { \
  float dA = __expf((DT)*a); \
  h = fmaf(dA, h, (DT)*(BV)*(UU)); \
  float yc = h*(CV); \
  yc += __shfl_xor_sync(0xffffffffu, yc, 1); \
  yc += __shfl_xor_sync(0xffffffffu, yc, 2); \
  yc += __shfl_xor_sync(0xffffffffu, yc, 4); \
  yc += __shfl_xor_sync(0xffffffffu, yc, 8); \
  if (l0) py[(size_t)(T)*DINN] = (yc + (UU)*dp)*(SZ); }

__device__ __forceinline__ float4 silu4(float4 z){
  return make_float4(z.x/(1.f+__expf(-z.x)), z.y/(1.f+__expf(-z.y)),
                     z.z/(1.f+__expf(-z.z)), z.w/(1.f+__expf(-z.w)));
}

__global__ __launch_bounds__(256) void k3_scan(
  const float* __restrict__ alog_f, const float* __restrict__ alog_b,
  const float* __restrict__ Dpf,   const float* __restrict__ Dpb)
{
  int tid = threadIdx.x;
  int ch = blockIdx.x*16 + (tid >> 4);
  int n  = tid & 15;
  int dir = ch >> 11;
  int b   = (ch >> 9) & 3;
  int d   = ch & 511;

  float a  = -__expf((dir ? alog_b : alog_f)[d*16 + n]);
  float dp = (dir ? Dpb : Dpf)[d];

  size_t cbase = ((size_t)((dir*BB + b)*DINN + d))*LL;
  const float* pdt = g_dtt + cbase;
  const float* pu  = g_ut  + cbase;
  const float* pz  = g_xzT + ((size_t)(dir*1024 + 512 + d))*MROWS + b*LL;
  const float* pB  = g_dbl + ((size_t)(dir*BB + b)*48 + 16 + n)*LL;
  const float* pC  = pB + 16*LL;
  float* py = g_y + (size_t)(dir*MROWS + b*LL)*DINN + d;

  float h = 0.f;
  bool l0 = (n == 0);

  if (dir == 0){
    for (int t4 = 0; t4 < LL; t4 += 4){
      float4 dt4 = *(const float4*)(pdt + t4);
      float4 u4  = *(const float4*)(pu  + t4);
      float4 B4  = *(const float4*)(pB  + t4);
      float4 C4  = *(const float4*)(pC  + t4);
      float4 s4  = make_float4(0.f, 0.f, 0.f, 0.f);
      if (l0) s4 = silu4(*(const float4*)(pz + t4));
      SCAN_STEP(dt4.x, u4.x, B4.x, C4.x, s4.x, t4+0);
      SCAN_STEP(dt4.y, u4.y, B4.y, C4.y, s4.y, t4+1);
      SCAN_STEP(dt4.z, u4.z, B4.z, C4.z, s4.z, t4+2);
      SCAN_STEP(dt4.w, u4.w, B4.w, C4.w, s4.w, t4+3);
    }
  } else {
    for (int t4 = LL - 4; t4 >= 0; t4 -= 4){
      float4 dt4 = *(const float4*)(pdt + t4);
      float4 u4  = *(const float4*)(pu  + t4);
      float4 B4  = *(const float4*)(pB  + t4);
      float4 C4  = *(const float4*)(pC  + t4);
      float4 s4  = make_float4(0.f, 0.f, 0.f, 0.f);
      if (l0) s4 = silu4(*(const float4*)(pz + t4));
      SCAN_STEP(dt4.w, u4.w, B4.w, C4.w, s4.w, t4+3);
      SCAN_STEP(dt4.z, u4.z, B4.z, C4.z, s4.z, t4+2);
      SCAN_STEP(dt4.y, u4.y, B4.y, C4.y, s4.y, t4+1);
      SCAN_STEP(dt4.x, u4.x, B4.x, C4.x, s4.x, t4+0);
    }
  }
}

// ---------------- launch ----------------
extern "C" void kernel_launch(void* const* d_in, const int* in_sizes, int n_in,
                              void* d_out, int out_size)
{
  (void)in_sizes; (void)n_in; (void)out_size;
  const float* x       = (const float*)d_in[0];
  const float* fw_norm = (const float*)d_in[1];
  const float* fw_inw  = (const float*)d_in[2];
  const float* fw_cw   = (const float*)d_in[3];
  const float* fw_cb   = (const float*)d_in[4];
  const float* fw_xw   = (const float*)d_in[5];
  const float* fw_dw   = (const float*)d_in[6];
  const float* fw_db   = (const float*)d_in[7];
  const float* fw_al   = (const float*)d_in[8];
  const float* fw_Dp   = (const float*)d_in[9];
  const float* fw_ow   = (const float*)d_in[10];
  const float* bw_norm = (const float*)d_in[11];
  const float* bw_inw  = (const float*)d_in[12];
  const float* bw_cw   = (const float*)d_in[13];
  const float* bw_cb   = (const float*)d_in[14];
  const float* bw_xw   = (const float*)d_in[15];
  const float* bw_dw   = (const float*)d_in[16];
  const float* bw_db   = (const float*)d_in[17];
  const float* bw_al   = (const float*)d_in[18];
  const float* bw_Dp   = (const float*)d_in[19];
  const float* bw_ow   = (const float*)d_in[20];

  float *p_xn, *p_w1, *p_w2, *p_xzT, *p_y;
  cudaGetSymbolAddress((void**)&p_xn, g_xn);
  cudaGetSymbolAddress((void**)&p_w1, g_w1);
  cudaGetSymbolAddress((void**)&p_w2, g_w2);
  cudaGetSymbolAddress((void**)&p_xzT, g_xzT);
  cudaGetSymbolAddress((void**)&p_y,  g_y);

  // 1) fold norm weights into in_proj, stack out_proj
  k_prep<<<2048, 256>>>(fw_inw, fw_norm, bw_inw, bw_norm, fw_ow, bw_ow);
  // 2) rmsnorm
  k_rms<<<MROWS, 256>>>(x);
  // 3) in_proj TRANSPOSED: g_xzT[2048 x 8192] = w1[2048x256] @ xn[8192x256]^T
  //    (A = w1 over by, B = xn over bx -> row-major [e][m] output)
  k_gemm_tf32<<<dim3(64, 16), 256>>>(p_w1, DD, (size_t)0, 1000000,
                                     p_xn, DD, p_xzT, MROWS, nullptr, DD, DD);
  // 4) depthwise conv + silu (fully coalesced)
  k_conv<<<dim3(BB, DINN, NDIR), 256>>>(fw_cw, fw_cb, bw_cw, bw_cb);
  // 5) x_dbl projection
  int smemx = (48*64 + 64*132 + 48*132)*(int)sizeof(float);
  cudaFuncSetAttribute(k_xproj, cudaFuncAttributeMaxDynamicSharedMemorySize, smemx);
  k_xproj<<<dim3(LL/128, BB, NDIR), 256, smemx>>>(fw_xw, bw_xw);
  // 6) dt projection + softplus
  k_dt<<<dim3(LL/128, BB, NDIR), 512>>>(fw_dw, fw_db, bw_dw, bw_db);
  // 7) selective scan (reads z from g_xzT, silu inline)
  k3_scan<<<256, 256>>>(fw_al, bw_al, fw_Dp, bw_Dp);
  // 8) out_proj + residual (tf32), writes concat([yf, yb]) into d_out
  k_gemm_tf32<<<dim3(4, 64), 256>>>(p_y, DINN, (size_t)MROWS*DINN, 2,
                                    p_w2, DINN, (float*)d_out, 2*DD, x, DD, DINN);
}

// round 4
// speedup vs baseline: 1.5580x; 1.0606x over previous
#include <cuda_runtime.h>
#include <math.h>
#include <stdint.h>

#define BB 4
#define LL 2048
#define DD 256
#define DINN 512
#define NST 16
#define NDIR 2
#define MROWS (BB*LL)      // 8192
#define N1 2048
#define EPSF 1e-5f

// ---------------- scratch ----------------
__device__ float g_xn[MROWS*DD];
__device__ float g_w1[N1*DD];
__device__ float g_w2[NDIR*DD*DINN];
__device__ float g_xzT[(size_t)N1*MROWS];          // in_proj out [e][b*L+t]
__device__ float g_ut [(size_t)NDIR*BB*DINN*LL];   // u [dir][b][d][t]
__device__ float g_dtt[(size_t)NDIR*BB*DINN*LL];   // dt [dir][b][d][t]
__device__ float g_dbl[(size_t)NDIR*BB*48*LL];     // x_dbl [dir][b][r][t]
__device__ float g_yT [(size_t)NDIR*DINN*MROWS];   // scan out [dir][d][b*L+t]

// ---------------- prep ----------------
__global__ __launch_bounds__(256) void k_prep(
    const float* __restrict__ inw_f, const float* __restrict__ nw_f,
    const float* __restrict__ inw_b, const float* __restrict__ nw_b,
    const float* __restrict__ ow_f,  const float* __restrict__ ow_b)
{
  int i = blockIdx.x*256 + threadIdx.x;
  if (i < N1*DD){
    int dir = i / (1024*DD);
    int rem = i - dir*1024*DD;
    int d = rem % DD;
    g_w1[i] = dir ? inw_b[rem]*nw_b[d] : inw_f[rem]*nw_f[d];
  }
  if (i < NDIR*DD*DINN){
    int dir = i / (DD*DINN);
    int rem = i - dir*DD*DINN;
    g_w2[i] = dir ? ow_b[rem] : ow_f[rem];
  }
}

// ---------------- rmsnorm ----------------
__global__ __launch_bounds__(256) void k_rms(const float* __restrict__ x)
{
  int row = blockIdx.x;
  int tid = threadIdx.x;
  float v = x[row*DD + tid];
  float s = v*v;
  #pragma unroll
  for (int o = 16; o; o >>= 1) s += __shfl_xor_sync(0xffffffffu, s, o);
  __shared__ float ws[8];
  __shared__ float scale;
  if ((tid & 31) == 0) ws[tid >> 5] = s;
  __syncthreads();
  if (tid == 0){
    float t = 0.f;
    #pragma unroll
    for (int i = 0; i < 8; i++) t += ws[i];
    scale = rsqrtf(t*(1.0f/DD) + EPSF);
  }
  __syncthreads();
  g_xn[row*DD + tid] = v*scale;
}

// ---------------- cp.async helper ----------------
__device__ __forceinline__ void cp16(uint32_t dst, const float* src){
  asm volatile("cp.async.ca.shared.global [%0], [%1], 16;\n" :: "r"(dst), "l"(src));
}
#define CP_COMMIT() asm volatile("cp.async.commit_group;\n" ::: "memory")
#define CP_WAIT1()  asm volatile("cp.async.wait_group 1;\n" ::: "memory")

// ---------------- double-buffered TF32 GEMM: C = A * B^T (+resid) ----------------
// ATRANS=0: A row-major [M][K].  ATRANS=1: A stored [K][M] (lda = row stride in m).
// Raw fp32 bits fed to mma.tf32 (HW truncates low mantissa bits).
template<int ATRANS>
__global__ __launch_bounds__(256) void k_gemm_db(
    const float* __restrict__ A, int lda, size_t aDirStride, int bpdX,
    const float* __restrict__ Bw, int ldb,
    float* __restrict__ C, int ldc,
    const float* __restrict__ resid, int rld, int K)
{
  const int BM = 128, BN = 128, BK = 16;
  const int LDA = ATRANS ? 136 : 20;       // skewed strides, conflict-free frag loads
  const int ASZ = ATRANS ? BK*136 : BM*20;
  const int BSZ = BN*20;
  __shared__ float As[2][ASZ];
  __shared__ float Bs[2][BSZ];

  int tid = threadIdx.x;
  int bx = blockIdx.x, by = blockIdx.y;
  int dir = bx / bpdX;
  A  += (size_t)dir*aDirStride + (ATRANS ? (size_t)(by*BM) : (size_t)(by*BM)*lda);
  Bw += (size_t)(bx*BN)*ldb;
  C  += (size_t)(by*BM)*ldc + (size_t)(bx*BN);
  const float* R = resid ? (resid + (size_t)(by*BM)*rld + (size_t)(bx % bpdX)*BN) : nullptr;

  uint32_t asb = (uint32_t)__cvta_generic_to_shared(&As[0][0]);
  uint32_t bsb = (uint32_t)__cvta_generic_to_shared(&Bs[0][0]);

  int warp = tid >> 5, lane = tid & 31;
  int wm = (warp >> 2)*64, wn = (warp & 3)*32;
  int g  = lane >> 2, tq = lane & 3;

  float acc[4][4][4];
  #pragma unroll
  for (int i = 0; i < 4; i++)
    #pragma unroll
    for (int j = 0; j < 4; j++)
      #pragma unroll
      for (int q = 0; q < 4; q++) acc[i][j][q] = 0.f;

  auto prefetch = [&](int st, int k0){
    #pragma unroll
    for (int i = 0; i < 2; i++){
      int c = tid + i*256;
      int row = c >> 2, kc = (c & 3)*4;
      cp16(bsb + (uint32_t)((st*BSZ + row*20 + kc)*4), Bw + (size_t)row*ldb + k0 + kc);
    }
    if (ATRANS){
      #pragma unroll
      for (int i = 0; i < 2; i++){
        int c = tid + i*256;
        int kr = c >> 5, mc = (c & 31)*4;
        cp16(asb + (uint32_t)((st*ASZ + kr*136 + mc)*4), A + (size_t)(k0+kr)*lda + mc);
      }
    } else {
      #pragma unroll
      for (int i = 0; i < 2; i++){
        int c = tid + i*256;
        int row = c >> 2, kc = (c & 3)*4;
        cp16(asb + (uint32_t)((st*ASZ + row*20 + kc)*4), A + (size_t)row*lda + k0 + kc);
      }
    }
  };

  prefetch(0, 0);
  CP_COMMIT();
  int NK = K/BK;
  for (int kt = 0; kt < NK; kt++){
    if (kt + 1 < NK) prefetch((kt+1) & 1, (kt+1)*BK);
    CP_COMMIT();
    CP_WAIT1();
    __syncthreads();
    int st = kt & 1;
    const uint32_t* as = (const uint32_t*)As[st];
    const uint32_t* bs = (const uint32_t*)Bs[st];
    #pragma unroll
    for (int k8 = 0; k8 < BK; k8 += 8){
      uint32_t af[4][4], bf[4][2];
      #pragma unroll
      for (int mm = 0; mm < 4; mm++){
        int mb = wm + mm*16;
        if (ATRANS){
          af[mm][0] = as[(k8+tq  )*136 + mb + g];
          af[mm][1] = as[(k8+tq  )*136 + mb + g + 8];
          af[mm][2] = as[(k8+tq+4)*136 + mb + g];
          af[mm][3] = as[(k8+tq+4)*136 + mb + g + 8];
        } else {
          af[mm][0] = as[(mb + g    )*20 + k8 + tq];
          af[mm][1] = as[(mb + g + 8)*20 + k8 + tq];
          af[mm][2] = as[(mb + g    )*20 + k8 + tq + 4];
          af[mm][3] = as[(mb + g + 8)*20 + k8 + tq + 4];
        }
      }
      #pragma unroll
      for (int nn = 0; nn < 4; nn++){
        int nb = wn + nn*8;
        bf[nn][0] = bs[(nb + g)*20 + k8 + tq];
        bf[nn][1] = bs[(nb + g)*20 + k8 + tq + 4];
      }
      #pragma unroll
      for (int mm = 0; mm < 4; mm++)
        #pragma unroll
        for (int nn = 0; nn < 4; nn++){
          asm volatile(
            "mma.sync.aligned.m16n8k8.row.col.f32.tf32.tf32.f32 "
            "{%0,%1,%2,%3}, {%4,%5,%6,%7}, {%8,%9}, {%0,%1,%2,%3};\n"
            : "+f"(acc[mm][nn][0]), "+f"(acc[mm][nn][1]),
              "+f"(acc[mm][nn][2]), "+f"(acc[mm][nn][3])
            : "r"(af[mm][0]), "r"(af[mm][1]), "r"(af[mm][2]), "r"(af[mm][3]),
              "r"(bf[nn][0]), "r"(bf[nn][1]));
        }
    }
    __syncthreads();
  }

  #pragma unroll
  for (int mm = 0; mm < 4; mm++)
    #pragma unroll
    for (int nn = 0; nn < 4; nn++){
      int row0 = wm + mm*16 + g;
      int col  = wn + nn*8 + 2*tq;
      float2 v0 = make_float2(acc[mm][nn][0], acc[mm][nn][1]);
      float2 v1 = make_float2(acc[mm][nn][2], acc[mm][nn][3]);
      if (R){
        float2 r0 = *(const float2*)(R + (size_t)row0*rld + col);
        float2 r1 = *(const float2*)(R + (size_t)(row0+8)*rld + col);
        v0.x += r0.x; v0.y += r0.y; v1.x += r1.x; v1.y += r1.y;
      }
      *(float2*)(C + (size_t)row0*ldc + col)     = v0;
      *(float2*)(C + (size_t)(row0+8)*ldc + col) = v1;
    }
}

// ---------------- depthwise conv + silu (coalesced) ----------------
__global__ __launch_bounds__(256) void k_conv(
  const float* __restrict__ cw_f, const float* __restrict__ cb_f,
  const float* __restrict__ cw_b, const float* __restrict__ cb_b)
{
  __shared__ float s[LL + 4];
  int tid = threadIdx.x;
  int b   = blockIdx.x;
  int d   = blockIdx.y;
  int dir = blockIdx.z;

  const float* cw = dir ? cw_b : cw_f;
  const float* cb = dir ? cb_b : cb_f;
  float c0, c1, c2, c3;
  if (dir == 0){ c0 = cw[d*4+0]; c1 = cw[d*4+1]; c2 = cw[d*4+2]; c3 = cw[d*4+3]; }
  else         { c0 = cw[d*4+3]; c1 = cw[d*4+2]; c2 = cw[d*4+1]; c3 = cw[d*4+0]; }
  float bias = cb[d];

  const float* xrow = g_xzT + ((size_t)(dir*1024 + d))*MROWS + b*LL;
  if (dir == 0){
    for (int i = tid; i < LL + 3; i += 256)
      s[i] = (i >= 3) ? xrow[i-3] : 0.f;
  } else {
    for (int i = tid; i < LL + 3; i += 256)
      s[i] = (i < LL) ? xrow[i] : 0.f;
  }
  __syncthreads();

  float* urow = g_ut + ((size_t)((dir*BB + b)*DINN + d))*LL;
  int t0 = tid*8;
  float o[8];
  #pragma unroll
  for (int j = 0; j < 8; j++){
    int t = t0 + j;
    float acc = bias + c0*s[t] + c1*s[t+1] + c2*s[t+2] + c3*s[t+3];
    o[j] = acc/(1.f + __expf(-acc));
  }
  *(float4*)(urow + t0)     = make_float4(o[0], o[1], o[2], o[3]);
  *(float4*)(urow + t0 + 4) = make_float4(o[4], o[5], o[6], o[7]);
}

// ---------------- x_dbl = xw(48x512) @ u_t(512xL) ----------------
__global__ __launch_bounds__(256) void k_xproj(
  const float* __restrict__ xw_f, const float* __restrict__ xw_b)
{
  extern __shared__ float dyn[];
  float* sw = dyn;
  float* su = dyn + 48*64;
  float* sx = su + 64*132;

  int tid = threadIdx.x;
  int t0  = blockIdx.x*128;
  int b   = blockIdx.y;
  int dir = blockIdx.z;
  const float* xw = dir ? xw_b : xw_f;

  int col = 2*(tid & 63);
  int rq  = tid >> 6;
  float acc[12][2];
  #pragma unroll
  for (int r = 0; r < 12; r++){ acc[r][0] = 0.f; acc[r][1] = 0.f; }

  size_t ubase = (size_t)(dir*BB + b)*DINN*LL;
  for (int k0 = 0; k0 < DINN; k0 += 64){
    for (int i = tid; i < 48*64; i += 256){
      int r = i >> 6, k = i & 63;
      sw[i] = xw[r*DINN + k0 + k];
    }
    for (int j = tid; j < 64*32; j += 256){
      int row = j >> 5, ts = (j & 31)*4;
      *(float4*)&su[row*132 + ts] =
        *(const float4*)(g_ut + ubase + (size_t)(k0+row)*LL + t0 + ts);
    }
    __syncthreads();
    #pragma unroll 8
    for (int k = 0; k < 64; k++){
      float u0 = su[k*132 + col];
      float u1 = su[k*132 + col + 1];
      #pragma unroll
      for (int r = 0; r < 12; r++){
        float w = sw[(rq*12 + r)*64 + k];
        acc[r][0] = fmaf(w, u0, acc[r][0]);
        acc[r][1] = fmaf(w, u1, acc[r][1]);
      }
    }
    __syncthreads();
  }

  #pragma unroll
  for (int r = 0; r < 12; r++){
    sx[(rq*12 + r)*132 + col]     = acc[r][0];
    sx[(rq*12 + r)*132 + col + 1] = acc[r][1];
  }
  __syncthreads();
  size_t obase = (size_t)(dir*BB + b)*48*LL;
  for (int i = tid; i < 48*32; i += 256){
    int row = i >> 5, seg = (i & 31)*4;
    *(float4*)&g_dbl[obase + (size_t)row*LL + t0 + seg] = *(float4*)&sx[row*132 + seg];
  }
}

// ---------------- dt projection + softplus ----------------
__global__ __launch_bounds__(512) void k_dt(
  const float* __restrict__ dw_f, const float* __restrict__ db_f,
  const float* __restrict__ dw_b, const float* __restrict__ db_b)
{
  int d   = threadIdx.x;
  int t0  = blockIdx.x*128;
  int b   = blockIdx.y;
  int dir = blockIdx.z;
  const float* dw = dir ? dw_b : dw_f;
  const float* db = dir ? db_b : db_f;

  float dwr[16];
  #pragma unroll
  for (int i = 0; i < 16; i += 4)
    *(float4*)&dwr[i] = *(const float4*)(dw + d*16 + i);
  float bd = db[d];

  const float* px = g_dbl + (size_t)(dir*BB + b)*48*LL;
  float* po = g_dtt + ((size_t)((dir*BB + b)*DINN + d))*LL;

  for (int tt = 0; tt < 128; tt += 4){
    int t = t0 + tt;
    float s0 = bd, s1 = bd, s2 = bd, s3 = bd;
    #pragma unroll
    for (int r = 0; r < 16; r++){
      float4 xv = *(const float4*)(px + (size_t)r*LL + t);
      s0 = fmaf(dwr[r], xv.x, s0);
      s1 = fmaf(dwr[r], xv.y, s1);
      s2 = fmaf(dwr[r], xv.z, s2);
      s3 = fmaf(dwr[r], xv.w, s3);
    }
    s0 = (s0 > 20.f) ? s0 : log1pf(__expf(s0));
    s1 = (s1 > 20.f) ? s1 : log1pf(__expf(s1));
    s2 = (s2 > 20.f) ? s2 : log1pf(__expf(s2));
    s3 = (s3 > 20.f) ? s3 : log1pf(__expf(s3));
    *(float4*)(po + t) = make_float4(s0, s1, s2, s3);
  }
}

// ---------------- selective scan ----------------
#define SCAN_STEP(DT,UU,BV,CV,SZ,YOUT) { \
  float dA = __expf((DT)*a); \
  h = fmaf(dA, h, (DT)*(BV)*(UU)); \
  float yc = h*(CV); \
  yc += __shfl_xor_sync(0xffffffffu, yc, 1); \
  yc += __shfl_xor_sync(0xffffffffu, yc, 2); \
  yc += __shfl_xor_sync(0xffffffffu, yc, 4); \
  yc += __shfl_xor_sync(0xffffffffu, yc, 8); \
  YOUT = (yc + (UU)*dp)*(SZ); }

__device__ __forceinline__ float4 silu4(float4 z){
  return make_float4(z.x/(1.f+__expf(-z.x)), z.y/(1.f+__expf(-z.y)),
                     z.z/(1.f+__expf(-z.z)), z.w/(1.f+__expf(-z.w)));
}

__global__ __launch_bounds__(256) void k3_scan(
  const float* __restrict__ alog_f, const float* __restrict__ alog_b,
  const float* __restrict__ Dpf,   const float* __restrict__ Dpb)
{
  int tid = threadIdx.x;
  int ch = blockIdx.x*16 + (tid >> 4);
  int n  = tid & 15;
  int dir = ch >> 11;
  int b   = (ch >> 9) & 3;
  int d   = ch & 511;

  float a  = -__expf((dir ? alog_b : alog_f)[d*16 + n]);
  float dp = (dir ? Dpb : Dpf)[d];

  size_t cbase = ((size_t)((dir*BB + b)*DINN + d))*LL;
  const float* pdt = g_dtt + cbase;
  const float* pu  = g_ut  + cbase;
  const float* pz  = g_xzT + ((size_t)(dir*1024 + 512 + d))*MROWS + b*LL;
  const float* pB  = g_dbl + ((size_t)(dir*BB + b)*48 + 16 + n)*LL;
  const float* pC  = pB + 16*LL;
  float* pyT = g_yT + ((size_t)(dir*DINN + d))*MROWS + b*LL;

  float h = 0.f;
  bool l0 = (n == 0);

  if (dir == 0){
    for (int t4 = 0; t4 < LL; t4 += 4){
      float4 dt4 = *(const float4*)(pdt + t4);
      float4 u4  = *(const float4*)(pu  + t4);
      float4 B4  = *(const float4*)(pB  + t4);
      float4 C4  = *(const float4*)(pC  + t4);
      float4 s4  = make_float4(0.f, 0.f, 0.f, 0.f);
      if (l0) s4 = silu4(*(const float4*)(pz + t4));
      float y0, y1, y2, y3;
      SCAN_STEP(dt4.x, u4.x, B4.x, C4.x, s4.x, y0);
      SCAN_STEP(dt4.y, u4.y, B4.y, C4.y, s4.y, y1);
      SCAN_STEP(dt4.z, u4.z, B4.z, C4.z, s4.z, y2);
      SCAN_STEP(dt4.w, u4.w, B4.w, C4.w, s4.w, y3);
      if (l0) *(float4*)(pyT + t4) = make_float4(y0, y1, y2, y3);
    }
  } else {
    for (int t4 = LL - 4; t4 >= 0; t4 -= 4){
      float4 dt4 = *(const float4*)(pdt + t4);
      float4 u4  = *(const float4*)(pu  + t4);
      float4 B4  = *(const float4*)(pB  + t4);
      float4 C4  = *(const float4*)(pC  + t4);
      float4 s4  = make_float4(0.f, 0.f, 0.f, 0.f);
      if (l0) s4 = silu4(*(const float4*)(pz + t4));
      float y0, y1, y2, y3;
      SCAN_STEP(dt4.w, u4.w, B4.w, C4.w, s4.w, y3);
      SCAN_STEP(dt4.z, u4.z, B4.z, C4.z, s4.z, y2);
      SCAN_STEP(dt4.y, u4.y, B4.y, C4.y, s4.y, y1);
      SCAN_STEP(dt4.x, u4.x, B4.x, C4.x, s4.x, y0);
      if (l0) *(float4*)(pyT + t4) = make_float4(y0, y1, y2, y3);
    }
  }
}

// ---------------- launch ----------------
extern "C" void kernel_launch(void* const* d_in, const int* in_sizes, int n_in,
                              void* d_out, int out_size)
{
  (void)in_sizes; (void)n_in; (void)out_size;
  const float* x       = (const float*)d_in[0];
  const float* fw_norm = (const float*)d_in[1];
  const float* fw_inw  = (const float*)d_in[2];
  const float* fw_cw   = (const float*)d_in[3];
  const float* fw_cb   = (const float*)d_in[4];
  const float* fw_xw   = (const float*)d_in[5];
  const float* fw_dw   = (const float*)d_in[6];
  const float* fw_db   = (const float*)d_in[7];
  const float* fw_al   = (const float*)d_in[8];
  const float* fw_Dp   = (const float*)d_in[9];
  const float* fw_ow   = (const float*)d_in[10];
  const float* bw_norm = (const float*)d_in[11];
  const float* bw_inw  = (const float*)d_in[12];
  const float* bw_cw   = (const float*)d_in[13];
  const float* bw_cb   = (const float*)d_in[14];
  const float* bw_xw   = (const float*)d_in[15];
  const float* bw_dw   = (const float*)d_in[16];
  const float* bw_db   = (const float*)d_in[17];
  const float* bw_al   = (const float*)d_in[18];
  const float* bw_Dp   = (const float*)d_in[19];
  const float* bw_ow   = (const float*)d_in[20];

  float *p_xn, *p_w1, *p_w2, *p_xzT, *p_yT;
  cudaGetSymbolAddress((void**)&p_xn, g_xn);
  cudaGetSymbolAddress((void**)&p_w1, g_w1);
  cudaGetSymbolAddress((void**)&p_w2, g_w2);
  cudaGetSymbolAddress((void**)&p_xzT, g_xzT);
  cudaGetSymbolAddress((void**)&p_yT, g_yT);

  k_prep<<<2048, 256>>>(fw_inw, fw_norm, bw_inw, bw_norm, fw_ow, bw_ow);
  k_rms<<<MROWS, 256>>>(x);
  // in_proj: g_xzT[2048 x 8192] = w1[2048x256] @ xn[8192x256]^T
  k_gemm_db<0><<<dim3(64, 16), 256>>>(p_w1, DD, (size_t)0, 1000000,
                                      p_xn, DD, p_xzT, MROWS, nullptr, DD, DD);
  k_conv<<<dim3(BB, DINN, NDIR), 256>>>(fw_cw, fw_cb, bw_cw, bw_cb);
  int smemx = (48*64 + 64*132 + 48*132)*(int)sizeof(float);
  cudaFuncSetAttribute(k_xproj, cudaFuncAttributeMaxDynamicSharedMemorySize, smemx);
  k_xproj<<<dim3(LL/128, BB, NDIR), 256, smemx>>>(fw_xw, bw_xw);
  k_dt<<<dim3(LL/128, BB, NDIR), 512>>>(fw_dw, fw_db, bw_dw, bw_db);
  k3_scan<<<256, 256>>>(fw_al, bw_al, fw_Dp, bw_Dp);
  // out_proj: C[8192 x 512] = Y^T (A stored [e][m]) @ w2^T, + residual x
  k_gemm_db<1><<<dim3(4, 64), 256>>>(p_yT, MROWS, (size_t)DINN*MROWS, 2,
                                     p_w2, DINN, (float*)d_out, 2*DD, x, DD, DINN);
}

// round 5
// speedup vs baseline: 1.6622x; 1.0668x over previous
#include <cuda_runtime.h>
#include <math.h>
#include <stdint.h>

#define BB 4
#define LL 2048
#define DD 256
#define DINN 512
#define NST 16
#define NDIR 2
#define MROWS (BB*LL)      // 8192
#define N1 2048
#define EPSF 1e-5f

// ---------------- scratch ----------------
__device__ float g_xn[MROWS*DD];
__device__ float g_w1[N1*DD];
__device__ float g_w2[NDIR*DD*DINN];
__device__ float g_xzT[(size_t)N1*MROWS];          // in_proj out [e][b*L+t]
__device__ float g_ut [(size_t)NDIR*BB*DINN*LL];   // u [dir][b][d][t]
__device__ float g_dtt[(size_t)NDIR*BB*DINN*LL];   // dt [dir][b][d][t]
__device__ float g_dbl[(size_t)NDIR*BB*48*LL];     // x_dbl [dir][b][r][t]
__device__ float g_yT [(size_t)NDIR*DINN*MROWS];   // scan out [dir][d][b*L+t]

// ---------------- prep (split into two launches to shift ncu capture slot) ----
__global__ __launch_bounds__(256) void k_prep1(
    const float* __restrict__ inw_f, const float* __restrict__ nw_f,
    const float* __restrict__ inw_b, const float* __restrict__ nw_b)
{
  int i = blockIdx.x*256 + threadIdx.x;
  if (i < N1*DD){
    int dir = i / (1024*DD);
    int rem = i - dir*1024*DD;
    int d = rem % DD;
    g_w1[i] = dir ? inw_b[rem]*nw_b[d] : inw_f[rem]*nw_f[d];
  }
}
__global__ __launch_bounds__(256) void k_prep2(
    const float* __restrict__ ow_f, const float* __restrict__ ow_b)
{
  int i = blockIdx.x*256 + threadIdx.x;
  if (i < NDIR*DD*DINN){
    int dir = i / (DD*DINN);
    int rem = i - dir*DD*DINN;
    g_w2[i] = dir ? ow_b[rem] : ow_f[rem];
  }
}

// ---------------- rmsnorm ----------------
__global__ __launch_bounds__(256) void k_rms(const float* __restrict__ x)
{
  int row = blockIdx.x;
  int tid = threadIdx.x;
  float v = x[row*DD + tid];
  float s = v*v;
  #pragma unroll
  for (int o = 16; o; o >>= 1) s += __shfl_xor_sync(0xffffffffu, s, o);
  __shared__ float ws[8];
  __shared__ float scale;
  if ((tid & 31) == 0) ws[tid >> 5] = s;
  __syncthreads();
  if (tid == 0){
    float t = 0.f;
    #pragma unroll
    for (int i = 0; i < 8; i++) t += ws[i];
    scale = rsqrtf(t*(1.0f/DD) + EPSF);
  }
  __syncthreads();
  g_xn[row*DD + tid] = v*scale;
}

// ---------------- cp.async helpers ----------------
__device__ __forceinline__ void cp16(uint32_t dst, const float* src){
  asm volatile("cp.async.ca.shared.global [%0], [%1], 16;\n" :: "r"(dst), "l"(src));
}
#define CP_COMMIT() asm volatile("cp.async.commit_group;\n" ::: "memory")
#define CP_WAIT1()  asm volatile("cp.async.wait_group 1;\n" ::: "memory")

// ---------------- double-buffered TF32 GEMM, BK=32: C = A * B^T (+resid) ------
// ATRANS=0: A row-major [M][K]. ATRANS=1: A stored [K][M], lda = m-row stride.
template<int ATRANS>
__global__ __launch_bounds__(256) void k_gemm_db(
    const float* __restrict__ A, int lda, size_t aDirStride, int bpdX,
    const float* __restrict__ Bw, int ldb,
    float* __restrict__ C, int ldc,
    const float* __restrict__ resid, int rld, int K)
{
  const int BM = 128, BN = 128, BK = 32;
  const int ASZ = ATRANS ? 32*136 : 128*36;
  const int BSZ = 128*36;
  extern __shared__ float dyn[];
  float* As = dyn;             // 2 stages
  float* Bs = dyn + 2*ASZ;

  int tid = threadIdx.x;
  int bx = blockIdx.x, by = blockIdx.y;
  int dir = bx / bpdX;
  A  += (size_t)dir*aDirStride + (ATRANS ? (size_t)(by*BM) : (size_t)(by*BM)*lda);
  Bw += (size_t)(bx*BN)*ldb;
  C  += (size_t)(by*BM)*ldc + (size_t)(bx*BN);
  const float* R = resid ? (resid + (size_t)(by*BM)*rld + (size_t)(bx % bpdX)*BN) : nullptr;

  uint32_t asb = (uint32_t)__cvta_generic_to_shared(As);
  uint32_t bsb = (uint32_t)__cvta_generic_to_shared(Bs);

  int warp = tid >> 5, lane = tid & 31;
  int wm = (warp >> 2)*64, wn = (warp & 3)*32;
  int g  = lane >> 2, tq = lane & 3;

  float acc[4][4][4];
  #pragma unroll
  for (int i = 0; i < 4; i++)
    #pragma unroll
    for (int j = 0; j < 4; j++)
      #pragma unroll
      for (int q = 0; q < 4; q++) acc[i][j][q] = 0.f;

  auto prefetch = [&](int st, int k0){
    #pragma unroll
    for (int i = 0; i < 4; i++){
      int c = tid + i*256;
      int row = c >> 3, kc = (c & 7)*4;
      cp16(bsb + (uint32_t)((st*BSZ + row*36 + kc)*4), Bw + (size_t)row*ldb + k0 + kc);
    }
    if (ATRANS){
      #pragma unroll
      for (int i = 0; i < 4; i++){
        int c = tid + i*256;
        int kr = c >> 5, mc = (c & 31)*4;
        cp16(asb + (uint32_t)((st*ASZ + kr*136 + mc)*4), A + (size_t)(k0+kr)*lda + mc);
      }
    } else {
      #pragma unroll
      for (int i = 0; i < 4; i++){
        int c = tid + i*256;
        int row = c >> 3, kc = (c & 7)*4;
        cp16(asb + (uint32_t)((st*ASZ + row*36 + kc)*4), A + (size_t)row*lda + k0 + kc);
      }
    }
  };

  prefetch(0, 0);
  CP_COMMIT();
  int NK = K/BK;
  for (int kt = 0; kt < NK; kt++){
    if (kt + 1 < NK) prefetch((kt+1) & 1, (kt+1)*BK);
    CP_COMMIT();
    CP_WAIT1();
    __syncthreads();
    int st = kt & 1;
    const uint32_t* as = (const uint32_t*)(As + st*ASZ);
    const uint32_t* bs = (const uint32_t*)(Bs + st*BSZ);
    #pragma unroll
    for (int k8 = 0; k8 < BK; k8 += 8){
      uint32_t af[4][4], bf[4][2];
      #pragma unroll
      for (int mm = 0; mm < 4; mm++){
        int mb = wm + mm*16;
        if (ATRANS){
          af[mm][0] = as[(k8+tq  )*136 + mb + g];
          af[mm][1] = as[(k8+tq  )*136 + mb + g + 8];
          af[mm][2] = as[(k8+tq+4)*136 + mb + g];
          af[mm][3] = as[(k8+tq+4)*136 + mb + g + 8];
        } else {
          af[mm][0] = as[(mb + g    )*36 + k8 + tq];
          af[mm][1] = as[(mb + g + 8)*36 + k8 + tq];
          af[mm][2] = as[(mb + g    )*36 + k8 + tq + 4];
          af[mm][3] = as[(mb + g + 8)*36 + k8 + tq + 4];
        }
      }
      #pragma unroll
      for (int nn = 0; nn < 4; nn++){
        int nb = wn + nn*8;
        bf[nn][0] = bs[(nb + g)*36 + k8 + tq];
        bf[nn][1] = bs[(nb + g)*36 + k8 + tq + 4];
      }
      #pragma unroll
      for (int mm = 0; mm < 4; mm++)
        #pragma unroll
        for (int nn = 0; nn < 4; nn++){
          asm volatile(
            "mma.sync.aligned.m16n8k8.row.col.f32.tf32.tf32.f32 "
            "{%0,%1,%2,%3}, {%4,%5,%6,%7}, {%8,%9}, {%0,%1,%2,%3};\n"
            : "+f"(acc[mm][nn][0]), "+f"(acc[mm][nn][1]),
              "+f"(acc[mm][nn][2]), "+f"(acc[mm][nn][3])
            : "r"(af[mm][0]), "r"(af[mm][1]), "r"(af[mm][2]), "r"(af[mm][3]),
              "r"(bf[nn][0]), "r"(bf[nn][1]));
        }
    }
    __syncthreads();
  }

  #pragma unroll
  for (int mm = 0; mm < 4; mm++)
    #pragma unroll
    for (int nn = 0; nn < 4; nn++){
      int row0 = wm + mm*16 + g;
      int col  = wn + nn*8 + 2*tq;
      float2 v0 = make_float2(acc[mm][nn][0], acc[mm][nn][1]);
      float2 v1 = make_float2(acc[mm][nn][2], acc[mm][nn][3]);
      if (R){
        float2 r0 = *(const float2*)(R + (size_t)row0*rld + col);
        float2 r1 = *(const float2*)(R + (size_t)(row0+8)*rld + col);
        v0.x += r0.x; v0.y += r0.y; v1.x += r1.x; v1.y += r1.y;
      }
      *(float2*)(C + (size_t)row0*ldc + col)     = v0;
      *(float2*)(C + (size_t)(row0+8)*ldc + col) = v1;
    }
}

// ---------------- depthwise conv + silu (coalesced) ----------------
__global__ __launch_bounds__(256) void k_conv(
  const float* __restrict__ cw_f, const float* __restrict__ cb_f,
  const float* __restrict__ cw_b, const float* __restrict__ cb_b)
{
  __shared__ float s[LL + 4];
  int tid = threadIdx.x;
  int b   = blockIdx.x;
  int d   = blockIdx.y;
  int dir = blockIdx.z;

  const float* cw = dir ? cw_b : cw_f;
  const float* cb = dir ? cb_b : cb_f;
  float c0, c1, c2, c3;
  if (dir == 0){ c0 = cw[d*4+0]; c1 = cw[d*4+1]; c2 = cw[d*4+2]; c3 = cw[d*4+3]; }
  else         { c0 = cw[d*4+3]; c1 = cw[d*4+2]; c2 = cw[d*4+1]; c3 = cw[d*4+0]; }
  float bias = cb[d];

  const float* xrow = g_xzT + ((size_t)(dir*1024 + d))*MROWS + b*LL;
  if (dir == 0){
    for (int i = tid; i < LL + 3; i += 256)
      s[i] = (i >= 3) ? xrow[i-3] : 0.f;
  } else {
    for (int i = tid; i < LL + 3; i += 256)
      s[i] = (i < LL) ? xrow[i] : 0.f;
  }
  __syncthreads();

  float* urow = g_ut + ((size_t)((dir*BB + b)*DINN + d))*LL;
  int t0 = tid*8;
  float o[8];
  #pragma unroll
  for (int j = 0; j < 8; j++){
    int t = t0 + j;
    float acc = bias + c0*s[t] + c1*s[t+1] + c2*s[t+2] + c3*s[t+3];
    o[j] = acc/(1.f + __expf(-acc));
  }
  *(float4*)(urow + t0)     = make_float4(o[0], o[1], o[2], o[3]);
  *(float4*)(urow + t0 + 4) = make_float4(o[4], o[5], o[6], o[7]);
}

// ---------------- x_dbl = xw(48x512) @ u_t(512xL) ----------------
__global__ __launch_bounds__(256) void k_xproj(
  const float* __restrict__ xw_f, const float* __restrict__ xw_b)
{
  extern __shared__ float dyn[];
  float* sw = dyn;
  float* su = dyn + 48*64;
  float* sx = su + 64*132;

  int tid = threadIdx.x;
  int t0  = blockIdx.x*128;
  int b   = blockIdx.y;
  int dir = blockIdx.z;
  const float* xw = dir ? xw_b : xw_f;

  int col = 2*(tid & 63);
  int rq  = tid >> 6;
  float acc[12][2];
  #pragma unroll
  for (int r = 0; r < 12; r++){ acc[r][0] = 0.f; acc[r][1] = 0.f; }

  size_t ubase = (size_t)(dir*BB + b)*DINN*LL;
  for (int k0 = 0; k0 < DINN; k0 += 64){
    for (int i = tid; i < 48*64; i += 256){
      int r = i >> 6, k = i & 63;
      sw[i] = xw[r*DINN + k0 + k];
    }
    for (int j = tid; j < 64*32; j += 256){
      int row = j >> 5, ts = (j & 31)*4;
      *(float4*)&su[row*132 + ts] =
        *(const float4*)(g_ut + ubase + (size_t)(k0+row)*LL + t0 + ts);
    }
    __syncthreads();
    #pragma unroll 8
    for (int k = 0; k < 64; k++){
      float u0 = su[k*132 + col];
      float u1 = su[k*132 + col + 1];
      #pragma unroll
      for (int r = 0; r < 12; r++){
        float w = sw[(rq*12 + r)*64 + k];
        acc[r][0] = fmaf(w, u0, acc[r][0]);
        acc[r][1] = fmaf(w, u1, acc[r][1]);
      }
    }
    __syncthreads();
  }

  #pragma unroll
  for (int r = 0; r < 12; r++){
    sx[(rq*12 + r)*132 + col]     = acc[r][0];
    sx[(rq*12 + r)*132 + col + 1] = acc[r][1];
  }
  __syncthreads();
  size_t obase = (size_t)(dir*BB + b)*48*LL;
  for (int i = tid; i < 48*32; i += 256){
    int row = i >> 5, seg = (i & 31)*4;
    *(float4*)&g_dbl[obase + (size_t)row*LL + t0 + seg] = *(float4*)&sx[row*132 + seg];
  }
}

// ---------------- dt projection + softplus ----------------
__global__ __launch_bounds__(512) void k_dt(
  const float* __restrict__ dw_f, const float* __restrict__ db_f,
  const float* __restrict__ dw_b, const float* __restrict__ db_b)
{
  int d   = threadIdx.x;
  int t0  = blockIdx.x*128;
  int b   = blockIdx.y;
  int dir = blockIdx.z;
  const float* dw = dir ? dw_b : dw_f;
  const float* db = dir ? db_b : db_f;

  float dwr[16];
  #pragma unroll
  for (int i = 0; i < 16; i += 4)
    *(float4*)&dwr[i] = *(const float4*)(dw + d*16 + i);
  float bd = db[d];

  const float* px = g_dbl + (size_t)(dir*BB + b)*48*LL;
  float* po = g_dtt + ((size_t)((dir*BB + b)*DINN + d))*LL;

  for (int tt = 0; tt < 128; tt += 4){
    int t = t0 + tt;
    float s0 = bd, s1 = bd, s2 = bd, s3 = bd;
    #pragma unroll
    for (int r = 0; r < 16; r++){
      float4 xv = *(const float4*)(px + (size_t)r*LL + t);
      s0 = fmaf(dwr[r], xv.x, s0);
      s1 = fmaf(dwr[r], xv.y, s1);
      s2 = fmaf(dwr[r], xv.z, s2);
      s3 = fmaf(dwr[r], xv.w, s3);
    }
    s0 = (s0 > 20.f) ? s0 : log1pf(__expf(s0));
    s1 = (s1 > 20.f) ? s1 : log1pf(__expf(s1));
    s2 = (s2 > 20.f) ? s2 : log1pf(__expf(s2));
    s3 = (s3 > 20.f) ? s3 : log1pf(__expf(s3));
    *(float4*)(po + t) = make_float4(s0, s1, s2, s3);
  }
}

// ---------------- selective scan: 5-shfl multi-reduce per 4 steps ----------------
__device__ __forceinline__ float sstep(float dt, float uu, float Bv, float a, float &h){
  float dA = __expf(dt*a);
  h = fmaf(dA, h, dt*Bv*uu);
  return h;
}

__global__ __launch_bounds__(256) void k3_scan(
  const float* __restrict__ alog_f, const float* __restrict__ alog_b,
  const float* __restrict__ Dpf,   const float* __restrict__ Dpb)
{
  int tid = threadIdx.x;
  int ch = blockIdx.x*16 + (tid >> 4);
  int n  = tid & 15;
  int dir = ch >> 11;
  int b   = (ch >> 9) & 3;
  int d   = ch & 511;

  float a  = -__expf((dir ? alog_b : alog_f)[d*16 + n]);
  float dp = (dir ? Dpb : Dpf)[d];

  size_t cbase = ((size_t)((dir*BB + b)*DINN + d))*LL;
  const float* pdt = g_dtt + cbase;
  const float* pu  = g_ut  + cbase;
  const float* pz  = g_xzT + ((size_t)(dir*1024 + 512 + d))*MROWS + b*LL;
  const float* pB  = g_dbl + ((size_t)(dir*BB + b)*48 + 16 + n)*LL;
  const float* pC  = pB + 16*LL;
  float* pyT = g_yT + ((size_t)(dir*DINN + d))*MROWS + b*LL;

  float h = 0.f;
  bool b3 = (n & 8) != 0, b2 = (n & 4) != 0;
  bool wr = (n & 3) == 0;
  int tmap = (b3 ? 2 : 0) + (b2 ? 1 : 0);

  int t4    = dir ? (LL - 4) : 0;
  int tstep = dir ? -4 : 4;

  for (int it = 0; it < LL/4; it++, t4 += tstep){
    float4 dt4 = *(const float4*)(pdt + t4);
    float4 u4  = *(const float4*)(pu  + t4);
    float4 B4  = *(const float4*)(pB  + t4);
    float4 C4  = *(const float4*)(pC  + t4);
    float4 z4  = *(const float4*)(pz  + t4);

    float y0, y1, y2, y3;
    if (dir == 0){
      y0 = sstep(dt4.x, u4.x, B4.x, a, h) * C4.x;
      y1 = sstep(dt4.y, u4.y, B4.y, a, h) * C4.y;
      y2 = sstep(dt4.z, u4.z, B4.z, a, h) * C4.z;
      y3 = sstep(dt4.w, u4.w, B4.w, a, h) * C4.w;
    } else {
      y3 = sstep(dt4.w, u4.w, B4.w, a, h) * C4.w;
      y2 = sstep(dt4.z, u4.z, B4.z, a, h) * C4.z;
      y1 = sstep(dt4.y, u4.y, B4.y, a, h) * C4.y;
      y0 = sstep(dt4.x, u4.x, B4.x, a, h) * C4.x;
    }

    // multi-value butterfly: 5 shfls reduce 4 values over 16 lanes
    float slo = b3 ? y0 : y2;
    float shi = b3 ? y1 : y3;
    float rlo = __shfl_xor_sync(0xffffffffu, slo, 8);
    float rhi = __shfl_xor_sync(0xffffffffu, shi, 8);
    float p0  = (b3 ? y2 : y0) + rlo;
    float p1  = (b3 ? y3 : y1) + rhi;
    float sb  = b2 ? p0 : p1;
    float rb  = __shfl_xor_sync(0xffffffffu, sb, 4);
    float v   = (b2 ? p1 : p0) + rb;
    v += __shfl_xor_sync(0xffffffffu, v, 2);
    v += __shfl_xor_sync(0xffffffffu, v, 1);

    if (wr){
      float ut = b3 ? (b2 ? u4.w : u4.z) : (b2 ? u4.y : u4.x);
      float zv = b3 ? (b2 ? z4.w : z4.z) : (b2 ? z4.y : z4.x);
      float sz = zv/(1.f + __expf(-zv));
      pyT[t4 + tmap] = (v + ut*dp)*sz;
    }
  }
}

// ---------------- launch ----------------
extern "C" void kernel_launch(void* const* d_in, const int* in_sizes, int n_in,
                              void* d_out, int out_size)
{
  (void)in_sizes; (void)n_in; (void)out_size;
  const float* x       = (const float*)d_in[0];
  const float* fw_norm = (const float*)d_in[1];
  const float* fw_inw  = (const float*)d_in[2];
  const float* fw_cw   = (const float*)d_in[3];
  const float* fw_cb   = (const float*)d_in[4];
  const float* fw_xw   = (const float*)d_in[5];
  const float* fw_dw   = (const float*)d_in[6];
  const float* fw_db   = (const float*)d_in[7];
  const float* fw_al   = (const float*)d_in[8];
  const float* fw_Dp   = (const float*)d_in[9];
  const float* fw_ow   = (const float*)d_in[10];
  const float* bw_norm = (const float*)d_in[11];
  const float* bw_inw  = (const float*)d_in[12];
  const float* bw_cw   = (const float*)d_in[13];
  const float* bw_cb   = (const float*)d_in[14];
  const float* bw_xw   = (const float*)d_in[15];
  const float* bw_dw   = (const float*)d_in[16];
  const float* bw_db   = (const float*)d_in[17];
  const float* bw_al   = (const float*)d_in[18];
  const float* bw_Dp   = (const float*)d_in[19];
  const float* bw_ow   = (const float*)d_in[20];

  float *p_xn, *p_w1, *p_w2, *p_xzT, *p_yT;
  cudaGetSymbolAddress((void**)&p_xn, g_xn);
  cudaGetSymbolAddress((void**)&p_w1, g_w1);
  cudaGetSymbolAddress((void**)&p_w2, g_w2);
  cudaGetSymbolAddress((void**)&p_xzT, g_xzT);
  cudaGetSymbolAddress((void**)&p_yT, g_yT);

  const int smemA0 = (2*(128*36) + 2*(128*36))*(int)sizeof(float);   // 73728
  const int smemA1 = (2*(32*136) + 2*(128*36))*(int)sizeof(float);   // 71680
  cudaFuncSetAttribute(k_gemm_db<0>, cudaFuncAttributeMaxDynamicSharedMemorySize, smemA0);
  cudaFuncSetAttribute(k_gemm_db<1>, cudaFuncAttributeMaxDynamicSharedMemorySize, smemA1);

  k_prep1<<<2048, 256>>>(fw_inw, fw_norm, bw_inw, bw_norm);
  k_prep2<<<1024, 256>>>(fw_ow, bw_ow);
  k_rms<<<MROWS, 256>>>(x);
  // in_proj: g_xzT[2048 x 8192] = w1[2048x256] @ xn[8192x256]^T
  k_gemm_db<0><<<dim3(64, 16), 256, smemA0>>>(p_w1, DD, (size_t)0, 1000000,
                                              p_xn, DD, p_xzT, MROWS, nullptr, DD, DD);
  k_conv<<<dim3(BB, DINN, NDIR), 256>>>(fw_cw, fw_cb, bw_cw, bw_cb);
  int smemx = (48*64 + 64*132 + 48*132)*(int)sizeof(float);
  cudaFuncSetAttribute(k_xproj, cudaFuncAttributeMaxDynamicSharedMemorySize, smemx);
  k_xproj<<<dim3(LL/128, BB, NDIR), 256, smemx>>>(fw_xw, bw_xw);
  k_dt<<<dim3(LL/128, BB, NDIR), 512>>>(fw_dw, fw_db, bw_dw, bw_db);
  k3_scan<<<256, 256>>>(fw_al, bw_al, fw_Dp, bw_Dp);
  // out_proj: C[8192 x 512] = Y^T (A stored [e][m]) @ w2^T, + residual x
  k_gemm_db<1><<<dim3(4, 64), 256, smemA1>>>(p_yT, MROWS, (size_t)DINN*MROWS, 2,
                                             p_w2, DINN, (float*)d_out, 2*DD, x, DD, DINN);
}

// round 7
// speedup vs baseline: 2.0770x; 1.2496x over previous
#include <cuda_runtime.h>
#include <math.h>
#include <stdint.h>

#define BB 4
#define LL 2048
#define DD 256
#define DINN 512
#define NST 16
#define NDIR 2
#define MROWS (BB*LL)      // 8192
#define N1 2048
#define EPSF 1e-5f
#define CHT 256            // scan smem chunk (timesteps)

// ---------------- scratch ----------------
__device__ float g_xn[MROWS*DD];
__device__ float g_w1[N1*DD];
__device__ float g_w2[NDIR*DD*DINN];
__device__ float g_xzT[(size_t)N1*MROWS];          // in_proj out [e][b*L+t]
__device__ float g_ut [(size_t)NDIR*BB*DINN*LL];   // u [dir][b][d][t]
__device__ float g_dtt[(size_t)NDIR*BB*DINN*LL];   // dt [dir][b][d][t]
__device__ float g_dbl[(size_t)NDIR*BB*48*LL];     // x_dbl dt-rank rows [dir][b][r][t]
__device__ float g_bcT[(size_t)NDIR*BB*LL*32];     // B/C t-major [dir][b][t][32]
__device__ float g_yT [(size_t)NDIR*DINN*MROWS];   // scan out [dir][d][b*L+t]

// ---------------- prep ----------------
__global__ __launch_bounds__(256) void k_prep1(
    const float* __restrict__ inw_f, const float* __restrict__ nw_f,
    const float* __restrict__ inw_b, const float* __restrict__ nw_b)
{
  int i = blockIdx.x*256 + threadIdx.x;
  if (i < N1*DD){
    int dir = i / (1024*DD);
    int rem = i - dir*1024*DD;
    int d = rem % DD;
    g_w1[i] = dir ? inw_b[rem]*nw_b[d] : inw_f[rem]*nw_f[d];
  }
}
__global__ __launch_bounds__(256) void k_prep2(
    const float* __restrict__ ow_f, const float* __restrict__ ow_b)
{
  int i = blockIdx.x*256 + threadIdx.x;
  if (i < NDIR*DD*DINN){
    int dir = i / (DD*DINN);
    int rem = i - dir*DD*DINN;
    g_w2[i] = dir ? ow_b[rem] : ow_f[rem];
  }
}

// ---------------- rmsnorm ----------------
__global__ __launch_bounds__(256) void k_rms(const float* __restrict__ x)
{
  int row = blockIdx.x;
  int tid = threadIdx.x;
  float v = x[row*DD + tid];
  float s = v*v;
  #pragma unroll
  for (int o = 16; o; o >>= 1) s += __shfl_xor_sync(0xffffffffu, s, o);
  __shared__ float ws[8];
  __shared__ float scale;
  if ((tid & 31) == 0) ws[tid >> 5] = s;
  __syncthreads();
  if (tid == 0){
    float t = 0.f;
    #pragma unroll
    for (int i = 0; i < 8; i++) t += ws[i];
    scale = rsqrtf(t*(1.0f/DD) + EPSF);
  }
  __syncthreads();
  g_xn[row*DD + tid] = v*scale;
}

// ---------------- cp.async helpers ----------------
__device__ __forceinline__ void cp16(uint32_t dst, const float* src){
  asm volatile("cp.async.ca.shared.global [%0], [%1], 16;\n" :: "r"(dst), "l"(src));
}
#define CP_COMMIT() asm volatile("cp.async.commit_group;\n" ::: "memory")
#define CP_WAIT1()  asm volatile("cp.async.wait_group 1;\n" ::: "memory")

// ---------------- 3-stage TF32 GEMM, BK=16: C = A * B^T (+resid) ----------------
// ATRANS=0: A row-major [M][K]. ATRANS=1: A stored [K][M], lda = m-row stride.
template<int ATRANS>
__global__ __launch_bounds__(256) void k_gemm_db(
    const float* __restrict__ A, int lda, size_t aDirStride, int bpdX,
    const float* __restrict__ Bw, int ldb,
    float* __restrict__ C, int ldc,
    const float* __restrict__ resid, int rld, int K)
{
  const int BM = 128, BN = 128, BK = 16;
  const int ASZ = ATRANS ? 16*136 : 128*20;
  const int BSZ = 128*20;
  extern __shared__ float dyn[];
  float* As = dyn;               // 3 stages
  float* Bs = dyn + 3*ASZ;

  int tid = threadIdx.x;
  int bx = blockIdx.x, by = blockIdx.y;
  int dir = bx / bpdX;
  A  += (size_t)dir*aDirStride + (ATRANS ? (size_t)(by*BM) : (size_t)(by*BM)*lda);
  Bw += (size_t)(bx*BN)*ldb;
  C  += (size_t)(by*BM)*ldc + (size_t)(bx*BN);
  const float* R = resid ? (resid + (size_t)(by*BM)*rld + (size_t)(bx % bpdX)*BN) : nullptr;

  uint32_t asb = (uint32_t)__cvta_generic_to_shared(As);
  uint32_t bsb = (uint32_t)__cvta_generic_to_shared(Bs);

  int warp = tid >> 5, lane = tid & 31;
  int wm = (warp >> 2)*64, wn = (warp & 3)*32;
  int g  = lane >> 2, tq = lane & 3;

  float acc[4][4][4];
  #pragma unroll
  for (int i = 0; i < 4; i++)
    #pragma unroll
    for (int j = 0; j < 4; j++)
      #pragma unroll
      for (int q = 0; q < 4; q++) acc[i][j][q] = 0.f;

  // 128x16 tile = 256 work items (half-rows): row = tid>>1, kc = (tid&1)*8, 2x cp16.
  auto prefetch = [&](int st, int k0){
    {
      int row = tid >> 1, kc = (tid & 1)*8;
      cp16(bsb + (uint32_t)((st*BSZ + row*20 + kc)*4),     Bw + (size_t)row*ldb + k0 + kc);
      cp16(bsb + (uint32_t)((st*BSZ + row*20 + kc + 4)*4), Bw + (size_t)row*ldb + k0 + kc + 4);
    }
    if (ATRANS){
      // 16x128 tile = 512 cp16 items
      #pragma unroll
      for (int i = 0; i < 2; i++){
        int c = tid + i*256;
        int kr = c >> 5, mc = (c & 31)*4;
        cp16(asb + (uint32_t)((st*ASZ + kr*136 + mc)*4), A + (size_t)(k0+kr)*lda + mc);
      }
    } else {
      int row = tid >> 1, kc = (tid & 1)*8;
      cp16(asb + (uint32_t)((st*ASZ + row*20 + kc)*4),     A + (size_t)row*lda + k0 + kc);
      cp16(asb + (uint32_t)((st*ASZ + row*20 + kc + 4)*4), A + (size_t)row*lda + k0 + kc + 4);
    }
  };

  prefetch(0, 0);      CP_COMMIT();
  prefetch(1, BK);     CP_COMMIT();
  int NK = K/BK;
  for (int kt = 0; kt < NK; kt++){
    CP_WAIT1();
    __syncthreads();
    if (kt + 2 < NK) prefetch((kt+2) % 3, (kt+2)*BK);
    CP_COMMIT();
    int st = kt % 3;
    const uint32_t* as = (const uint32_t*)(As + st*ASZ);
    const uint32_t* bs = (const uint32_t*)(Bs + st*BSZ);
    #pragma unroll
    for (int k8 = 0; k8 < BK; k8 += 8){
      uint32_t af[4][4], bf[4][2];
      #pragma unroll
      for (int mm = 0; mm < 4; mm++){
        int mb = wm + mm*16;
        if (ATRANS){
          af[mm][0] = as[(k8+tq  )*136 + mb + g];
          af[mm][1] = as[(k8+tq  )*136 + mb + g + 8];
          af[mm][2] = as[(k8+tq+4)*136 + mb + g];
          af[mm][3] = as[(k8+tq+4)*136 + mb + g + 8];
        } else {
          af[mm][0] = as[(mb + g    )*20 + k8 + tq];
          af[mm][1] = as[(mb + g + 8)*20 + k8 + tq];
          af[mm][2] = as[(mb + g    )*20 + k8 + tq + 4];
          af[mm][3] = as[(mb + g + 8)*20 + k8 + tq + 4];
        }
      }
      #pragma unroll
      for (int nn = 0; nn < 4; nn++){
        int nb = wn + nn*8;
        bf[nn][0] = bs[(nb + g)*20 + k8 + tq];
        bf[nn][1] = bs[(nb + g)*20 + k8 + tq + 4];
      }
      #pragma unroll
      for (int mm = 0; mm < 4; mm++)
        #pragma unroll
        for (int nn = 0; nn < 4; nn++){
          asm volatile(
            "mma.sync.aligned.m16n8k8.row.col.f32.tf32.tf32.f32 "
            "{%0,%1,%2,%3}, {%4,%5,%6,%7}, {%8,%9}, {%0,%1,%2,%3};\n"
            : "+f"(acc[mm][nn][0]), "+f"(acc[mm][nn][1]),
              "+f"(acc[mm][nn][2]), "+f"(acc[mm][nn][3])
            : "r"(af[mm][0]), "r"(af[mm][1]), "r"(af[mm][2]), "r"(af[mm][3]),
              "r"(bf[nn][0]), "r"(bf[nn][1]));
        }
    }
  }

  __syncthreads();
  #pragma unroll
  for (int mm = 0; mm < 4; mm++)
    #pragma unroll
    for (int nn = 0; nn < 4; nn++){
      int row0 = wm + mm*16 + g;
      int col  = wn + nn*8 + 2*tq;
      float2 v0 = make_float2(acc[mm][nn][0], acc[mm][nn][1]);
      float2 v1 = make_float2(acc[mm][nn][2], acc[mm][nn][3]);
      if (R){
        float2 r0 = *(const float2*)(R + (size_t)row0*rld + col);
        float2 r1 = *(const float2*)(R + (size_t)(row0+8)*rld + col);
        v0.x += r0.x; v0.y += r0.y; v1.x += r1.x; v1.y += r1.y;
      }
      *(float2*)(C + (size_t)row0*ldc + col)     = v0;
      *(float2*)(C + (size_t)(row0+8)*ldc + col) = v1;
    }
}

// ---------------- depthwise conv + silu (float4 smem reads) ----------------
__global__ __launch_bounds__(256) void k_conv(
  const float* __restrict__ cw_f, const float* __restrict__ cb_f,
  const float* __restrict__ cw_b, const float* __restrict__ cb_b)
{
  __shared__ float s[LL + 4];
  int tid = threadIdx.x;
  int b   = blockIdx.x;
  int d   = blockIdx.y;
  int dir = blockIdx.z;

  const float* cw = dir ? cw_b : cw_f;
  const float* cb = dir ? cb_b : cb_f;
  float c0, c1, c2, c3;
  if (dir == 0){ c0 = cw[d*4+0]; c1 = cw[d*4+1]; c2 = cw[d*4+2]; c3 = cw[d*4+3]; }
  else         { c0 = cw[d*4+3]; c1 = cw[d*4+2]; c2 = cw[d*4+1]; c3 = cw[d*4+0]; }
  float bias = cb[d];

  const float* xrow = g_xzT + ((size_t)(dir*1024 + d))*MROWS + b*LL;
  if (dir == 0){
    for (int i = tid; i < LL + 4; i += 256)
      s[i] = (i >= 3 && i < LL + 3) ? xrow[i-3] : 0.f;
  } else {
    for (int i = tid; i < LL + 4; i += 256)
      s[i] = (i < LL) ? xrow[i] : 0.f;
  }
  __syncthreads();

  float* urow = g_ut + ((size_t)((dir*BB + b)*DINN + d))*LL;
  int t0 = tid*8;
  float v[12];
  *(float4*)&v[0] = *(const float4*)&s[t0];
  *(float4*)&v[4] = *(const float4*)&s[t0+4];
  *(float4*)&v[8] = *(const float4*)&s[t0+8];
  float o[8];
  #pragma unroll
  for (int j = 0; j < 8; j++){
    float acc = bias + c0*v[j] + c1*v[j+1] + c2*v[j+2] + c3*v[j+3];
    o[j] = acc/(1.f + __expf(-acc));
  }
  *(float4*)(urow + t0)     = make_float4(o[0], o[1], o[2], o[3]);
  *(float4*)(urow + t0 + 4) = make_float4(o[4], o[5], o[6], o[7]);
}

// ---------------- x_dbl = xw(48x512) @ u_t(512xL); dt rows -> g_dbl, B/C -> g_bcT ----
__global__ __launch_bounds__(256) void k_xproj(
  const float* __restrict__ xw_f, const float* __restrict__ xw_b)
{
  extern __shared__ float dyn[];
  float* sw = dyn;
  float* su = dyn + 48*64;
  float* sx = su + 64*132;

  int tid = threadIdx.x;
  int t0  = blockIdx.x*128;
  int b   = blockIdx.y;
  int dir = blockIdx.z;
  const float* xw = dir ? xw_b : xw_f;

  int col = 2*(tid & 63);
  int rq  = tid >> 6;
  float acc[12][2];
  #pragma unroll
  for (int r = 0; r < 12; r++){ acc[r][0] = 0.f; acc[r][1] = 0.f; }

  size_t ubase = (size_t)(dir*BB + b)*DINN*LL;
  for (int k0 = 0; k0 < DINN; k0 += 64){
    for (int i = tid; i < 48*64; i += 256){
      int r = i >> 6, k = i & 63;
      sw[i] = xw[r*DINN + k0 + k];
    }
    for (int j = tid; j < 64*32; j += 256){
      int row = j >> 5, ts = (j & 31)*4;
      *(float4*)&su[row*132 + ts] =
        *(const float4*)(g_ut + ubase + (size_t)(k0+row)*LL + t0 + ts);
    }
    __syncthreads();
    #pragma unroll 8
    for (int k = 0; k < 64; k++){
      float u0 = su[k*132 + col];
      float u1 = su[k*132 + col + 1];
      #pragma unroll
      for (int r = 0; r < 12; r++){
        float w = sw[(rq*12 + r)*64 + k];
        acc[r][0] = fmaf(w, u0, acc[r][0]);
        acc[r][1] = fmaf(w, u1, acc[r][1]);
      }
    }
    __syncthreads();
  }

  #pragma unroll
  for (int r = 0; r < 12; r++){
    sx[(rq*12 + r)*132 + col]     = acc[r][0];
    sx[(rq*12 + r)*132 + col + 1] = acc[r][1];
  }
  __syncthreads();
  // dt-rank rows (0..15) -> g_dbl [r][t]
  size_t obase = (size_t)(dir*BB + b)*48*LL;
  for (int i = tid; i < 16*32; i += 256){
    int row = i >> 5, seg = (i & 31)*4;
    *(float4*)&g_dbl[obase + (size_t)row*LL + t0 + seg] = *(float4*)&sx[row*132 + seg];
  }
  // B/C rows (16..47) -> g_bcT t-major [t][32]
  size_t cbase = ((size_t)(dir*BB + b)*LL + t0)*32;
  for (int i = tid; i < 128*32; i += 256){
    int t = i >> 5, n = i & 31;
    g_bcT[cbase + (size_t)t*32 + n] = sx[(16 + n)*132 + t];
  }
}

// ---------------- dt projection + softplus ----------------
__global__ __launch_bounds__(512) void k_dt(
  const float* __restrict__ dw_f, const float* __restrict__ db_f,
  const float* __restrict__ dw_b, const float* __restrict__ db_b)
{
  int d   = threadIdx.x;
  int t0  = blockIdx.x*128;
  int b   = blockIdx.y;
  int dir = blockIdx.z;
  const float* dw = dir ? dw_b : dw_f;
  const float* db = dir ? db_b : db_f;

  float dwr[16];
  #pragma unroll
  for (int i = 0; i < 16; i += 4)
    *(float4*)&dwr[i] = *(const float4*)(dw + d*16 + i);
  float bd = db[d];

  const float* px = g_dbl + (size_t)(dir*BB + b)*48*LL;
  float* po = g_dtt + ((size_t)((dir*BB + b)*DINN + d))*LL;

  for (int tt = 0; tt < 128; tt += 4){
    int t = t0 + tt;
    float s0 = bd, s1 = bd, s2 = bd, s3 = bd;
    #pragma unroll
    for (int r = 0; r < 16; r++){
      float4 xv = *(const float4*)(px + (size_t)r*LL + t);
      s0 = fmaf(dwr[r], xv.x, s0);
      s1 = fmaf(dwr[r], xv.y, s1);
      s2 = fmaf(dwr[r], xv.z, s2);
      s3 = fmaf(dwr[r], xv.w, s3);
    }
    s0 = (s0 > 20.f) ? s0 : log1pf(__expf(s0));
    s1 = (s1 > 20.f) ? s1 : log1pf(__expf(s1));
    s2 = (s2 > 20.f) ? s2 : log1pf(__expf(s2));
    s3 = (s3 > 20.f) ? s3 : log1pf(__expf(s3));
    *(float4*)(po + t) = make_float4(s0, s1, s2, s3);
  }
}

// ---------------- selective scan: smem-staged B/C, 5-shfl reduce per 4 steps ----
__device__ __forceinline__ float sstep(float dt, float uu, float Bv, float a, float &h){
  float dA = __expf(dt*a);
  h = fmaf(dA, h, dt*Bv*uu);
  return h;
}

__global__ __launch_bounds__(256) void k3_scan(
  const float* __restrict__ alog_f, const float* __restrict__ alog_b,
  const float* __restrict__ Dpf,   const float* __restrict__ Dpb)
{
  __shared__ float sbc[CHT*32];    // 32KB: [t][32] (B 0-15, C 16-31)
  int tid = threadIdx.x;
  int ch = blockIdx.x*16 + (tid >> 4);
  int n  = tid & 15;
  int dir = ch >> 11;
  int b   = (ch >> 9) & 3;
  int d   = ch & 511;

  float a  = -__expf((dir ? alog_b : alog_f)[d*16 + n]);
  float dp = (dir ? Dpb : Dpf)[d];

  size_t cbase = ((size_t)((dir*BB + b)*DINN + d))*LL;
  const float* pdt = g_dtt + cbase;
  const float* pu  = g_ut  + cbase;
  const float* pz  = g_xzT + ((size_t)(dir*1024 + 512 + d))*MROWS + b*LL;
  const float* pbc = g_bcT + ((size_t)(dir*BB + b))*LL*32;
  float* pyT = g_yT + ((size_t)(dir*DINN + d))*MROWS + b*LL;

  float h = 0.f;
  bool b3 = (n & 8) != 0, b2 = (n & 4) != 0;
  bool wr = (n & 3) == 0;
  int tmap = (b3 ? 2 : 0) + (b2 ? 1 : 0);

  for (int c = 0; c < LL/CHT; c++){
    int tc0 = dir ? (LL - (c+1)*CHT) : c*CHT;
    __syncthreads();
    {
      const float4* src = (const float4*)(pbc + (size_t)tc0*32);
      float4* dst = (float4*)sbc;
      #pragma unroll
      for (int i = 0; i < CHT*32/4/256; i++)
        dst[tid + i*256] = src[tid + i*256];
    }
    __syncthreads();

    int t4    = dir ? (tc0 + CHT - 4) : tc0;
    int tstep = dir ? -4 : 4;
    for (int it = 0; it < CHT/4; it++, t4 += tstep){
      float4 dt4 = *(const float4*)(pdt + t4);
      float4 u4  = *(const float4*)(pu  + t4);
      float4 z4  = *(const float4*)(pz  + t4);
      int tl = (t4 - tc0)*32;
      float B0 = sbc[tl +      n], C0 = sbc[tl +      16 + n];
      float B1 = sbc[tl + 32 + n], C1 = sbc[tl + 32 + 16 + n];
      float B2 = sbc[tl + 64 + n], C2 = sbc[tl + 64 + 16 + n];
      float B3 = sbc[tl + 96 + n], C3 = sbc[tl + 96 + 16 + n];

      float y0, y1, y2, y3;
      if (dir == 0){
        y0 = sstep(dt4.x, u4.x, B0, a, h) * C0;
        y1 = sstep(dt4.y, u4.y, B1, a, h) * C1;
        y2 = sstep(dt4.z, u4.z, B2, a, h) * C2;
        y3 = sstep(dt4.w, u4.w, B3, a, h) * C3;
      } else {
        y3 = sstep(dt4.w, u4.w, B3, a, h) * C3;
        y2 = sstep(dt4.z, u4.z, B2, a, h) * C2;
        y1 = sstep(dt4.y, u4.y, B1, a, h) * C1;
        y0 = sstep(dt4.x, u4.x, B0, a, h) * C0;
      }

      // multi-value butterfly: 5 shfls reduce 4 values over 16 lanes
      float slo = b3 ? y0 : y2;
      float shi = b3 ? y1 : y3;
      float rlo = __shfl_xor_sync(0xffffffffu, slo, 8);
      float rhi = __shfl_xor_sync(0xffffffffu, shi, 8);
      float p0  = (b3 ? y2 : y0) + rlo;
      float p1  = (b3 ? y3 : y1) + rhi;
      float sb  = b2 ? p0 : p1;
      float rb  = __shfl_xor_sync(0xffffffffu, sb, 4);
      float v   = (b2 ? p1 : p0) + rb;
      v += __shfl_xor_sync(0xffffffffu, v, 2);
      v += __shfl_xor_sync(0xffffffffu, v, 1);

      if (wr){
        float ut = b3 ? (b2 ? u4.w : u4.z) : (b2 ? u4.y : u4.x);
        float zv = b3 ? (b2 ? z4.w : z4.z) : (b2 ? z4.y : z4.x);
        float sz = zv/(1.f + __expf(-zv));
        pyT[t4 + tmap] = (v + ut*dp)*sz;
      }
    }
  }
}

// ---------------- launch ----------------
extern "C" void kernel_launch(void* const* d_in, const int* in_sizes, int n_in,
                              void* d_out, int out_size)
{
  (void)in_sizes; (void)n_in; (void)out_size;
  const float* x       = (const float*)d_in[0];
  const float* fw_norm = (const float*)d_in[1];
  const float* fw_inw  = (const float*)d_in[2];
  const float* fw_cw   = (const float*)d_in[3];
  const float* fw_cb   = (const float*)d_in[4];
  const float* fw_xw   = (const float*)d_in[5];
  const float* fw_dw   = (const float*)d_in[6];
  const float* fw_db   = (const float*)d_in[7];
  const float* fw_al   = (const float*)d_in[8];
  const float* fw_Dp   = (const float*)d_in[9];
  const float* fw_ow   = (const float*)d_in[10];
  const float* bw_norm = (const float*)d_in[11];
  const float* bw_inw  = (const float*)d_in[12];
  const float* bw_cw   = (const float*)d_in[13];
  const float* bw_cb   = (const float*)d_in[14];
  const float* bw_xw   = (const float*)d_in[15];
  const float* bw_dw   = (const float*)d_in[16];
  const float* bw_db   = (const float*)d_in[17];
  const float* bw_al   = (const float*)d_in[18];
  const float* bw_Dp   = (const float*)d_in[19];
  const float* bw_ow   = (const float*)d_in[20];

  float *p_xn, *p_w1, *p_w2, *p_xzT, *p_yT;
  cudaGetSymbolAddress((void**)&p_xn, g_xn);
  cudaGetSymbolAddress((void**)&p_w1, g_w1);
  cudaGetSymbolAddress((void**)&p_w2, g_w2);
  cudaGetSymbolAddress((void**)&p_xzT, g_xzT);
  cudaGetSymbolAddress((void**)&p_yT, g_yT);

  const int smemA0 = 3*(128*20 + 128*20)*(int)sizeof(float);   // 61440
  const int smemA1 = 3*(16*136 + 128*20)*(int)sizeof(float);   // 56832
  cudaFuncSetAttribute(k_gemm_db<0>, cudaFuncAttributeMaxDynamicSharedMemorySize, smemA0);
  cudaFuncSetAttribute(k_gemm_db<1>, cudaFuncAttributeMaxDynamicSharedMemorySize, smemA1);

  k_prep1<<<2048, 256>>>(fw_inw, fw_norm, bw_inw, bw_norm);
  k_prep2<<<1024, 256>>>(fw_ow, bw_ow);
  k_rms<<<MROWS, 256>>>(x);
  // in_proj: g_xzT[2048 x 8192] = w1[2048x256] @ xn[8192x256]^T
  k_gemm_db<0><<<dim3(64, 16), 256, smemA0>>>(p_w1, DD, (size_t)0, 1000000,
                                              p_xn, DD, p_xzT, MROWS, nullptr, DD, DD);
  k_conv<<<dim3(BB, DINN, NDIR), 256>>>(fw_cw, fw_cb, bw_cw, bw_cb);
  int smemx = (48*64 + 64*132 + 48*132)*(int)sizeof(float);
  cudaFuncSetAttribute(k_xproj, cudaFuncAttributeMaxDynamicSharedMemorySize, smemx);
  k_xproj<<<dim3(LL/128, BB, NDIR), 256, smemx>>>(fw_xw, bw_xw);
  k_dt<<<dim3(LL/128, BB, NDIR), 512>>>(fw_dw, fw_db, bw_dw, bw_db);
  k3_scan<<<256, 256>>>(fw_al, bw_al, fw_Dp, bw_Dp);
  // out_proj: C[8192 x 512] = Y^T (A stored [e][m]) @ w2^T, + residual x
  k_gemm_db<1><<<dim3(4, 64), 256, smemA1>>>(p_yT, MROWS, (size_t)DINN*MROWS, 2,
                                             p_w2, DINN, (float*)d_out, 2*DD, x, DD, DINN);
}

// round 8
// speedup vs baseline: 2.3081x; 1.1113x over previous
#include <cuda_runtime.h>
#include <math.h>
#include <stdint.h>

#define BB 4
#define LL 2048
#define DD 256
#define DINN 512
#define NST 16
#define NDIR 2
#define MROWS (BB*LL)      // 8192
#define N1 2048
#define EPSF 1e-5f
#define CHT 256            // scan smem chunk (timesteps)

// ---------------- scratch ----------------
__device__ float g_xn[MROWS*DD];
__device__ float g_w1[N1*DD];
__device__ float g_w2[NDIR*DD*DINN];
__device__ float g_xzT[(size_t)N1*MROWS];          // in_proj out [e][b*L+t]
__device__ float g_ut [(size_t)NDIR*BB*DINN*LL];   // u [dir][b][d][t]
__device__ float g_dtt[(size_t)NDIR*BB*DINN*LL];   // dt [dir][b][d][t]
__device__ float g_dbl[(size_t)NDIR*BB*48*LL];     // x_dbl dt-rank rows [dir][b][r][t]
__device__ float g_bcT[(size_t)NDIR*BB*LL*32];     // B/C t-major [dir][b][t][32]
__device__ float g_yT [(size_t)NDIR*DINN*MROWS];   // scan out [dir][d][b*L+t]

// ---------------- fused prep (w1 fold, w2 stack) + rmsnorm ----------------
// blocks 0..8191: rmsnorm rows; 8192..10239: w1; 10240..11263: w2
__global__ __launch_bounds__(256) void k_prep_rms(
    const float* __restrict__ x,
    const float* __restrict__ inw_f, const float* __restrict__ nw_f,
    const float* __restrict__ inw_b, const float* __restrict__ nw_b,
    const float* __restrict__ ow_f,  const float* __restrict__ ow_b)
{
  int blk = blockIdx.x;
  int tid = threadIdx.x;
  if (blk < MROWS){
    int row = blk;
    float v = x[row*DD + tid];
    float s = v*v;
    #pragma unroll
    for (int o = 16; o; o >>= 1) s += __shfl_xor_sync(0xffffffffu, s, o);
    __shared__ float ws[8];
    __shared__ float scale;
    if ((tid & 31) == 0) ws[tid >> 5] = s;
    __syncthreads();
    if (tid == 0){
      float t = 0.f;
      #pragma unroll
      for (int i = 0; i < 8; i++) t += ws[i];
      scale = rsqrtf(t*(1.0f/DD) + EPSF);
    }
    __syncthreads();
    g_xn[row*DD + tid] = v*scale;
  } else if (blk < MROWS + 2048){
    int i = (blk - MROWS)*256 + tid;
    int dir = i / (1024*DD);
    int rem = i - dir*1024*DD;
    int d = rem % DD;
    g_w1[i] = dir ? inw_b[rem]*nw_b[d] : inw_f[rem]*nw_f[d];
  } else {
    int i = (blk - MROWS - 2048)*256 + tid;
    int dir = i / (DD*DINN);
    int rem = i - dir*DD*DINN;
    g_w2[i] = dir ? ow_b[rem] : ow_f[rem];
  }
}

// ---------------- cp.async helpers ----------------
__device__ __forceinline__ void cp16(uint32_t dst, const float* src){
  asm volatile("cp.async.ca.shared.global [%0], [%1], 16;\n" :: "r"(dst), "l"(src));
}
#define CP_COMMIT() asm volatile("cp.async.commit_group;\n" ::: "memory")
#define CP_WAIT1()  asm volatile("cp.async.wait_group 1;\n" ::: "memory")

// ---------------- double-buffered TF32 GEMM, BK=32 (round-5 measured-best) ----
// ATRANS=0: A row-major [M][K]. ATRANS=1: A stored [K][M], lda = m-row stride.
template<int ATRANS>
__global__ __launch_bounds__(256) void k_gemm_db(
    const float* __restrict__ A, int lda, size_t aDirStride, int bpdX,
    const float* __restrict__ Bw, int ldb,
    float* __restrict__ C, int ldc,
    const float* __restrict__ resid, int rld, int K)
{
  const int BM = 128, BN = 128, BK = 32;
  const int ASZ = ATRANS ? 32*136 : 128*36;
  const int BSZ = 128*36;
  extern __shared__ float dyn[];
  float* As = dyn;             // 2 stages
  float* Bs = dyn + 2*ASZ;

  int tid = threadIdx.x;
  int bx = blockIdx.x, by = blockIdx.y;
  int dir = bx / bpdX;
  A  += (size_t)dir*aDirStride + (ATRANS ? (size_t)(by*BM) : (size_t)(by*BM)*lda);
  Bw += (size_t)(bx*BN)*ldb;
  C  += (size_t)(by*BM)*ldc + (size_t)(bx*BN);
  const float* R = resid ? (resid + (size_t)(by*BM)*rld + (size_t)(bx % bpdX)*BN) : nullptr;

  uint32_t asb = (uint32_t)__cvta_generic_to_shared(As);
  uint32_t bsb = (uint32_t)__cvta_generic_to_shared(Bs);

  int warp = tid >> 5, lane = tid & 31;
  int wm = (warp >> 2)*64, wn = (warp & 3)*32;
  int g  = lane >> 2, tq = lane & 3;

  float acc[4][4][4];
  #pragma unroll
  for (int i = 0; i < 4; i++)
    #pragma unroll
    for (int j = 0; j < 4; j++)
      #pragma unroll
      for (int q = 0; q < 4; q++) acc[i][j][q] = 0.f;

  auto prefetch = [&](int st, int k0){
    #pragma unroll
    for (int i = 0; i < 4; i++){
      int c = tid + i*256;
      int row = c >> 3, kc = (c & 7)*4;
      cp16(bsb + (uint32_t)((st*BSZ + row*36 + kc)*4), Bw + (size_t)row*ldb + k0 + kc);
    }
    if (ATRANS){
      #pragma unroll
      for (int i = 0; i < 4; i++){
        int c = tid + i*256;
        int kr = c >> 5, mc = (c & 31)*4;
        cp16(asb + (uint32_t)((st*ASZ + kr*136 + mc)*4), A + (size_t)(k0+kr)*lda + mc);
      }
    } else {
      #pragma unroll
      for (int i = 0; i < 4; i++){
        int c = tid + i*256;
        int row = c >> 3, kc = (c & 7)*4;
        cp16(asb + (uint32_t)((st*ASZ + row*36 + kc)*4), A + (size_t)row*lda + k0 + kc);
      }
    }
  };

  prefetch(0, 0);
  CP_COMMIT();
  int NK = K/BK;
  for (int kt = 0; kt < NK; kt++){
    if (kt + 1 < NK) prefetch((kt+1) & 1, (kt+1)*BK);
    CP_COMMIT();
    CP_WAIT1();
    __syncthreads();
    int st = kt & 1;
    const uint32_t* as = (const uint32_t*)(As + st*ASZ);
    const uint32_t* bs = (const uint32_t*)(Bs + st*BSZ);
    #pragma unroll
    for (int k8 = 0; k8 < BK; k8 += 8){
      uint32_t af[4][4], bf[4][2];
      #pragma unroll
      for (int mm = 0; mm < 4; mm++){
        int mb = wm + mm*16;
        if (ATRANS){
          af[mm][0] = as[(k8+tq  )*136 + mb + g];
          af[mm][1] = as[(k8+tq  )*136 + mb + g + 8];
          af[mm][2] = as[(k8+tq+4)*136 + mb + g];
          af[mm][3] = as[(k8+tq+4)*136 + mb + g + 8];
        } else {
          af[mm][0] = as[(mb + g    )*36 + k8 + tq];
          af[mm][1] = as[(mb + g + 8)*36 + k8 + tq];
          af[mm][2] = as[(mb + g    )*36 + k8 + tq + 4];
          af[mm][3] = as[(mb + g + 8)*36 + k8 + tq + 4];
        }
      }
      #pragma unroll
      for (int nn = 0; nn < 4; nn++){
        int nb = wn + nn*8;
        bf[nn][0] = bs[(nb + g)*36 + k8 + tq];
        bf[nn][1] = bs[(nb + g)*36 + k8 + tq + 4];
      }
      #pragma unroll
      for (int mm = 0; mm < 4; mm++)
        #pragma unroll
        for (int nn = 0; nn < 4; nn++){
          asm volatile(
            "mma.sync.aligned.m16n8k8.row.col.f32.tf32.tf32.f32 "
            "{%0,%1,%2,%3}, {%4,%5,%6,%7}, {%8,%9}, {%0,%1,%2,%3};\n"
            : "+f"(acc[mm][nn][0]), "+f"(acc[mm][nn][1]),
              "+f"(acc[mm][nn][2]), "+f"(acc[mm][nn][3])
            : "r"(af[mm][0]), "r"(af[mm][1]), "r"(af[mm][2]), "r"(af[mm][3]),
              "r"(bf[nn][0]), "r"(bf[nn][1]));
        }
    }
    __syncthreads();
  }

  #pragma unroll
  for (int mm = 0; mm < 4; mm++)
    #pragma unroll
    for (int nn = 0; nn < 4; nn++){
      int row0 = wm + mm*16 + g;
      int col  = wn + nn*8 + 2*tq;
      float2 v0 = make_float2(acc[mm][nn][0], acc[mm][nn][1]);
      float2 v1 = make_float2(acc[mm][nn][2], acc[mm][nn][3]);
      if (R){
        float2 r0 = *(const float2*)(R + (size_t)row0*rld + col);
        float2 r1 = *(const float2*)(R + (size_t)(row0+8)*rld + col);
        v0.x += r0.x; v0.y += r0.y; v1.x += r1.x; v1.y += r1.y;
      }
      *(float2*)(C + (size_t)row0*ldc + col)     = v0;
      *(float2*)(C + (size_t)(row0+8)*ldc + col) = v1;
    }
}

// ---------------- depthwise conv + silu (float4 smem reads) ----------------
__global__ __launch_bounds__(256) void k_conv(
  const float* __restrict__ cw_f, const float* __restrict__ cb_f,
  const float* __restrict__ cw_b, const float* __restrict__ cb_b)
{
  __shared__ float s[LL + 4];
  int tid = threadIdx.x;
  int b   = blockIdx.x;
  int d   = blockIdx.y;
  int dir = blockIdx.z;

  const float* cw = dir ? cw_b : cw_f;
  const float* cb = dir ? cb_b : cb_f;
  float c0, c1, c2, c3;
  if (dir == 0){ c0 = cw[d*4+0]; c1 = cw[d*4+1]; c2 = cw[d*4+2]; c3 = cw[d*4+3]; }
  else         { c0 = cw[d*4+3]; c1 = cw[d*4+2]; c2 = cw[d*4+1]; c3 = cw[d*4+0]; }
  float bias = cb[d];

  const float* xrow = g_xzT + ((size_t)(dir*1024 + d))*MROWS + b*LL;
  if (dir == 0){
    for (int i = tid; i < LL + 4; i += 256)
      s[i] = (i >= 3 && i < LL + 3) ? xrow[i-3] : 0.f;
  } else {
    for (int i = tid; i < LL + 4; i += 256)
      s[i] = (i < LL) ? xrow[i] : 0.f;
  }
  __syncthreads();

  float* urow = g_ut + ((size_t)((dir*BB + b)*DINN + d))*LL;
  int t0 = tid*8;
  float v[12];
  *(float4*)&v[0] = *(const float4*)&s[t0];
  *(float4*)&v[4] = *(const float4*)&s[t0+4];
  *(float4*)&v[8] = *(const float4*)&s[t0+8];
  float o[8];
  #pragma unroll
  for (int j = 0; j < 8; j++){
    float acc = bias + c0*v[j] + c1*v[j+1] + c2*v[j+2] + c3*v[j+3];
    o[j] = acc/(1.f + __expf(-acc));
  }
  *(float4*)(urow + t0)     = make_float4(o[0], o[1], o[2], o[3]);
  *(float4*)(urow + t0 + 4) = make_float4(o[4], o[5], o[6], o[7]);
}

// ---------------- x_dbl = xw(48x512) @ u_t(512xL); dt rows -> g_dbl, B/C -> g_bcT ----
__global__ __launch_bounds__(256) void k_xproj(
  const float* __restrict__ xw_f, const float* __restrict__ xw_b)
{
  extern __shared__ float dyn[];
  float* sw = dyn;
  float* su = dyn + 48*64;
  float* sx = su + 64*132;

  int tid = threadIdx.x;
  int t0  = blockIdx.x*128;
  int b   = blockIdx.y;
  int dir = blockIdx.z;
  const float* xw = dir ? xw_b : xw_f;

  int col = 2*(tid & 63);
  int rq  = tid >> 6;
  float acc[12][2];
  #pragma unroll
  for (int r = 0; r < 12; r++){ acc[r][0] = 0.f; acc[r][1] = 0.f; }

  size_t ubase = (size_t)(dir*BB + b)*DINN*LL;
  for (int k0 = 0; k0 < DINN; k0 += 64){
    for (int i = tid; i < 48*64; i += 256){
      int r = i >> 6, k = i & 63;
      sw[i] = xw[r*DINN + k0 + k];
    }
    for (int j = tid; j < 64*32; j += 256){
      int row = j >> 5, ts = (j & 31)*4;
      *(float4*)&su[row*132 + ts] =
        *(const float4*)(g_ut + ubase + (size_t)(k0+row)*LL + t0 + ts);
    }
    __syncthreads();
    #pragma unroll 8
    for (int k = 0; k < 64; k++){
      float u0 = su[k*132 + col];
      float u1 = su[k*132 + col + 1];
      #pragma unroll
      for (int r = 0; r < 12; r++){
        float w = sw[(rq*12 + r)*64 + k];
        acc[r][0] = fmaf(w, u0, acc[r][0]);
        acc[r][1] = fmaf(w, u1, acc[r][1]);
      }
    }
    __syncthreads();
  }

  #pragma unroll
  for (int r = 0; r < 12; r++){
    sx[(rq*12 + r)*132 + col]     = acc[r][0];
    sx[(rq*12 + r)*132 + col + 1] = acc[r][1];
  }
  __syncthreads();
  // dt-rank rows (0..15) -> g_dbl [r][t]
  size_t obase = (size_t)(dir*BB + b)*48*LL;
  for (int i = tid; i < 16*32; i += 256){
    int row = i >> 5, seg = (i & 31)*4;
    *(float4*)&g_dbl[obase + (size_t)row*LL + t0 + seg] = *(float4*)&sx[row*132 + seg];
  }
  // B/C rows (16..47) -> g_bcT t-major [t][32]
  size_t cbase = ((size_t)(dir*BB + b)*LL + t0)*32;
  for (int i = tid; i < 128*32; i += 256){
    int t = i >> 5, n = i & 31;
    g_bcT[cbase + (size_t)t*32 + n] = sx[(16 + n)*132 + t];
  }
}

// ---------------- dt projection + softplus (coalesced: threads sweep t) ----------
__global__ __launch_bounds__(128) void k_dt(
  const float* __restrict__ dw_f, const float* __restrict__ db_f,
  const float* __restrict__ dw_b, const float* __restrict__ db_b)
{
  int t   = blockIdx.x*512 + threadIdx.x*4;
  int d   = blockIdx.y;
  int bb  = blockIdx.z;            // dir*4 + b
  int dir = bb >> 2;
  const float* dw = dir ? dw_b : dw_f;
  const float* db = dir ? db_b : db_f;

  float dwr[16];
  #pragma unroll
  for (int i = 0; i < 16; i += 4)
    *(float4*)&dwr[i] = *(const float4*)(dw + d*16 + i);
  float bd = db[d];

  const float* px = g_dbl + (size_t)bb*48*LL;
  float s0 = bd, s1 = bd, s2 = bd, s3 = bd;
  #pragma unroll
  for (int r = 0; r < 16; r++){
    float4 xv = *(const float4*)(px + (size_t)r*LL + t);
    s0 = fmaf(dwr[r], xv.x, s0);
    s1 = fmaf(dwr[r], xv.y, s1);
    s2 = fmaf(dwr[r], xv.z, s2);
    s3 = fmaf(dwr[r], xv.w, s3);
  }
  s0 = (s0 > 20.f) ? s0 : log1pf(__expf(s0));
  s1 = (s1 > 20.f) ? s1 : log1pf(__expf(s1));
  s2 = (s2 > 20.f) ? s2 : log1pf(__expf(s2));
  s3 = (s3 > 20.f) ? s3 : log1pf(__expf(s3));
  *(float4*)(g_dtt + ((size_t)(bb*DINN + d))*LL + t) = make_float4(s0, s1, s2, s3);
}

// ---------------- selective scan: smem-staged B/C, 5-shfl reduce per 4 steps ----
__device__ __forceinline__ float sstep(float dt, float uu, float Bv, float a, float &h){
  float dA = __expf(dt*a);
  h = fmaf(dA, h, dt*Bv*uu);
  return h;
}

__global__ __launch_bounds__(256) void k3_scan(
  const float* __restrict__ alog_f, const float* __restrict__ alog_b,
  const float* __restrict__ Dpf,   const float* __restrict__ Dpb)
{
  __shared__ float sbc[CHT*32];    // 32KB: [t][32] (B 0-15, C 16-31)
  int tid = threadIdx.x;
  int ch = blockIdx.x*16 + (tid >> 4);
  int n  = tid & 15;
  int dir = ch >> 11;
  int b   = (ch >> 9) & 3;
  int d   = ch & 511;

  float a  = -__expf((dir ? alog_b : alog_f)[d*16 + n]);
  float dp = (dir ? Dpb : Dpf)[d];

  size_t cbase = ((size_t)((dir*BB + b)*DINN + d))*LL;
  const float* pdt = g_dtt + cbase;
  const float* pu  = g_ut  + cbase;
  const float* pz  = g_xzT + ((size_t)(dir*1024 + 512 + d))*MROWS + b*LL;
  const float* pbc = g_bcT + ((size_t)(dir*BB + b))*LL*32;
  float* pyT = g_yT + ((size_t)(dir*DINN + d))*MROWS + b*LL;

  float h = 0.f;
  bool b3 = (n & 8) != 0, b2 = (n & 4) != 0;
  bool wr = (n & 3) == 0;
  int tmap = (b3 ? 2 : 0) + (b2 ? 1 : 0);

  for (int c = 0; c < LL/CHT; c++){
    int tc0 = dir ? (LL - (c+1)*CHT) : c*CHT;
    __syncthreads();
    {
      const float4* src = (const float4*)(pbc + (size_t)tc0*32);
      float4* dst = (float4*)sbc;
      #pragma unroll
      for (int i = 0; i < CHT*32/4/256; i++)
        dst[tid + i*256] = src[tid + i*256];
    }
    __syncthreads();

    int t4    = dir ? (tc0 + CHT - 4) : tc0;
    int tstep = dir ? -4 : 4;
    for (int it = 0; it < CHT/4; it++, t4 += tstep){
      float4 dt4 = *(const float4*)(pdt + t4);
      float4 u4  = *(const float4*)(pu  + t4);
      float4 z4  = *(const float4*)(pz  + t4);
      int tl = (t4 - tc0)*32;
      float B0 = sbc[tl +      n], C0 = sbc[tl +      16 + n];
      float B1 = sbc[tl + 32 + n], C1 = sbc[tl + 32 + 16 + n];
      float B2 = sbc[tl + 64 + n], C2 = sbc[tl + 64 + 16 + n];
      float B3 = sbc[tl + 96 + n], C3 = sbc[tl + 96 + 16 + n];

      float y0, y1, y2, y3;
      if (dir == 0){
        y0 = sstep(dt4.x, u4.x, B0, a, h) * C0;
        y1 = sstep(dt4.y, u4.y, B1, a, h) * C1;
        y2 = sstep(dt4.z, u4.z, B2, a, h) * C2;
        y3 = sstep(dt4.w, u4.w, B3, a, h) * C3;
      } else {
        y3 = sstep(dt4.w, u4.w, B3, a, h) * C3;
        y2 = sstep(dt4.z, u4.z, B2, a, h) * C2;
        y1 = sstep(dt4.y, u4.y, B1, a, h) * C1;
        y0 = sstep(dt4.x, u4.x, B0, a, h) * C0;
      }

      float slo = b3 ? y0 : y2;
      float shi = b3 ? y1 : y3;
      float rlo = __shfl_xor_sync(0xffffffffu, slo, 8);
      float rhi = __shfl_xor_sync(0xffffffffu, shi, 8);
      float p0  = (b3 ? y2 : y0) + rlo;
      float p1  = (b3 ? y3 : y1) + rhi;
      float sb  = b2 ? p0 : p1;
      float rb  = __shfl_xor_sync(0xffffffffu, sb, 4);
      float v   = (b2 ? p1 : p0) + rb;
      v += __shfl_xor_sync(0xffffffffu, v, 2);
      v += __shfl_xor_sync(0xffffffffu, v, 1);

      if (wr){
        float ut = b3 ? (b2 ? u4.w : u4.z) : (b2 ? u4.y : u4.x);
        float zv = b3 ? (b2 ? z4.w : z4.z) : (b2 ? z4.y : z4.x);
        float sz = zv/(1.f + __expf(-zv));
        pyT[t4 + tmap] = (v + ut*dp)*sz;
      }
    }
  }
}

// ---------------- launch ----------------
extern "C" void kernel_launch(void* const* d_in, const int* in_sizes, int n_in,
                              void* d_out, int out_size)
{
  (void)in_sizes; (void)n_in; (void)out_size;
  const float* x       = (const float*)d_in[0];
  const float* fw_norm = (const float*)d_in[1];
  const float* fw_inw  = (const float*)d_in[2];
  const float* fw_cw   = (const float*)d_in[3];
  const float* fw_cb   = (const float*)d_in[4];
  const float* fw_xw   = (const float*)d_in[5];
  const float* fw_dw   = (const float*)d_in[6];
  const float* fw_db   = (const float*)d_in[7];
  const float* fw_al   = (const float*)d_in[8];
  const float* fw_Dp   = (const float*)d_in[9];
  const float* fw_ow   = (const float*)d_in[10];
  const float* bw_norm = (const float*)d_in[11];
  const float* bw_inw  = (const float*)d_in[12];
  const float* bw_cw   = (const float*)d_in[13];
  const float* bw_cb   = (const float*)d_in[14];
  const float* bw_xw   = (const float*)d_in[15];
  const float* bw_dw   = (const float*)d_in[16];
  const float* bw_db   = (const float*)d_in[17];
  const float* bw_al   = (const float*)d_in[18];
  const float* bw_Dp   = (const float*)d_in[19];
  const float* bw_ow   = (const float*)d_in[20];

  float *p_xn, *p_w1, *p_w2, *p_xzT, *p_yT;
  cudaGetSymbolAddress((void**)&p_xn, g_xn);
  cudaGetSymbolAddress((void**)&p_w1, g_w1);
  cudaGetSymbolAddress((void**)&p_w2, g_w2);
  cudaGetSymbolAddress((void**)&p_xzT, g_xzT);
  cudaGetSymbolAddress((void**)&p_yT, g_yT);

  const int smemA0 = (2*(128*36) + 2*(128*36))*(int)sizeof(float);   // 73728
  const int smemA1 = (2*(32*136) + 2*(128*36))*(int)sizeof(float);   // 71680
  cudaFuncSetAttribute(k_gemm_db<0>, cudaFuncAttributeMaxDynamicSharedMemorySize, smemA0);
  cudaFuncSetAttribute(k_gemm_db<1>, cudaFuncAttributeMaxDynamicSharedMemorySize, smemA1);

  // 1) fused prep + rmsnorm
  k_prep_rms<<<MROWS + 2048 + 1024, 256>>>(x, fw_inw, fw_norm, bw_inw, bw_norm,
                                           fw_ow, bw_ow);
  // 2) in_proj: g_xzT[2048 x 8192] = w1[2048x256] @ xn[8192x256]^T
  k_gemm_db<0><<<dim3(64, 16), 256, smemA0>>>(p_w1, DD, (size_t)0, 1000000,
                                              p_xn, DD, p_xzT, MROWS, nullptr, DD, DD);
  // 3) depthwise conv + silu
  k_conv<<<dim3(BB, DINN, NDIR), 256>>>(fw_cw, fw_cb, bw_cw, bw_cb);
  // 4) x_dbl projection  (this is launch #4 -> ncu capture slot)
  int smemx = (48*64 + 64*132 + 48*132)*(int)sizeof(float);
  cudaFuncSetAttribute(k_xproj, cudaFuncAttributeMaxDynamicSharedMemorySize, smemx);
  k_xproj<<<dim3(LL/128, BB, NDIR), 256, smemx>>>(fw_xw, bw_xw);
  // 5) dt projection + softplus (coalesced)
  k_dt<<<dim3(LL/512, DINN, BB*NDIR), 128>>>(fw_dw, fw_db, bw_dw, bw_db);
  // 6) selective scan
  k3_scan<<<256, 256>>>(fw_al, bw_al, fw_Dp, bw_Dp);
  // 7) out_proj + residual
  k_gemm_db<1><<<dim3(4, 64), 256, smemA1>>>(p_yT, MROWS, (size_t)DINN*MROWS, 2,
                                             p_w2, DINN, (float*)d_out, 2*DD, x, DD, DINN);
}

// round 9
// speedup vs baseline: 2.3383x; 1.0131x over previous
#include <cuda_runtime.h>
#include <math.h>
#include <stdint.h>

#define BB 4
#define LL 2048
#define DD 256
#define DINN 512
#define NST 16
#define NDIR 2
#define MROWS (BB*LL)      // 8192
#define N1 2048
#define EPSF 1e-5f
#define CHT 256            // scan smem chunk (timesteps)

// ---------------- scratch ----------------
__device__ float g_xn[MROWS*DD];
__device__ float g_w1[N1*DD];
__device__ float g_w2[NDIR*DD*DINN];
__device__ float g_xzT[(size_t)N1*MROWS];          // in_proj out [e][b*L+t]
__device__ float g_ut [(size_t)NDIR*BB*DINN*LL];   // u [dir][b][d][t]
__device__ float g_dtt[(size_t)NDIR*BB*DINN*LL];   // dt [dir][b][d][t]
__device__ float g_dbl[(size_t)NDIR*BB*48*LL];     // x_dbl dt-rank rows [dir][b][r][t] (rows 0..15 used)
__device__ float g_bcT[(size_t)NDIR*BB*LL*32];     // B/C t-major [dir][b][t][32]
__device__ float g_yT [(size_t)NDIR*DINN*MROWS];   // scan out [dir][d][b*L+t]

// ---------------- fused prep (w1 fold, w2 stack) + rmsnorm ----------------
__global__ __launch_bounds__(256) void k_prep_rms(
    const float* __restrict__ x,
    const float* __restrict__ inw_f, const float* __restrict__ nw_f,
    const float* __restrict__ inw_b, const float* __restrict__ nw_b,
    const float* __restrict__ ow_f,  const float* __restrict__ ow_b)
{
  int blk = blockIdx.x;
  int tid = threadIdx.x;
  if (blk < MROWS){
    int row = blk;
    float v = x[row*DD + tid];
    float s = v*v;
    #pragma unroll
    for (int o = 16; o; o >>= 1) s += __shfl_xor_sync(0xffffffffu, s, o);
    __shared__ float ws[8];
    __shared__ float scale;
    if ((tid & 31) == 0) ws[tid >> 5] = s;
    __syncthreads();
    if (tid == 0){
      float t = 0.f;
      #pragma unroll
      for (int i = 0; i < 8; i++) t += ws[i];
      scale = rsqrtf(t*(1.0f/DD) + EPSF);
    }
    __syncthreads();
    g_xn[row*DD + tid] = v*scale;
  } else if (blk < MROWS + 2048){
    int i = (blk - MROWS)*256 + tid;
    int dir = i / (1024*DD);
    int rem = i - dir*1024*DD;
    int d = rem % DD;
    g_w1[i] = dir ? inw_b[rem]*nw_b[d] : inw_f[rem]*nw_f[d];
  } else {
    int i = (blk - MROWS - 2048)*256 + tid;
    int dir = i / (DD*DINN);
    int rem = i - dir*DD*DINN;
    g_w2[i] = dir ? ow_b[rem] : ow_f[rem];
  }
}

// ---------------- cp.async helpers ----------------
__device__ __forceinline__ void cp16(uint32_t dst, const float* src){
  asm volatile("cp.async.ca.shared.global [%0], [%1], 16;\n" :: "r"(dst), "l"(src));
}
#define CP_COMMIT() asm volatile("cp.async.commit_group;\n" ::: "memory")
#define CP_WAIT1()  asm volatile("cp.async.wait_group 1;\n" ::: "memory")

// ---------------- double-buffered TF32 GEMM, BK=32 ----------------
template<int ATRANS>
__global__ __launch_bounds__(256) void k_gemm_db(
    const float* __restrict__ A, int lda, size_t aDirStride, int bpdX,
    const float* __restrict__ Bw, int ldb,
    float* __restrict__ C, int ldc,
    const float* __restrict__ resid, int rld, int K)
{
  const int BM = 128, BN = 128, BK = 32;
  const int ASZ = ATRANS ? 32*136 : 128*36;
  const int BSZ = 128*36;
  extern __shared__ float dyn[];
  float* As = dyn;
  float* Bs = dyn + 2*ASZ;

  int tid = threadIdx.x;
  int bx = blockIdx.x, by = blockIdx.y;
  int dir = bx / bpdX;
  A  += (size_t)dir*aDirStride + (ATRANS ? (size_t)(by*BM) : (size_t)(by*BM)*lda);
  Bw += (size_t)(bx*BN)*ldb;
  C  += (size_t)(by*BM)*ldc + (size_t)(bx*BN);
  const float* R = resid ? (resid + (size_t)(by*BM)*rld + (size_t)(bx % bpdX)*BN) : nullptr;

  uint32_t asb = (uint32_t)__cvta_generic_to_shared(As);
  uint32_t bsb = (uint32_t)__cvta_generic_to_shared(Bs);

  int warp = tid >> 5, lane = tid & 31;
  int wm = (warp >> 2)*64, wn = (warp & 3)*32;
  int g  = lane >> 2, tq = lane & 3;

  float acc[4][4][4];
  #pragma unroll
  for (int i = 0; i < 4; i++)
    #pragma unroll
    for (int j = 0; j < 4; j++)
      #pragma unroll
      for (int q = 0; q < 4; q++) acc[i][j][q] = 0.f;

  auto prefetch = [&](int st, int k0){
    #pragma unroll
    for (int i = 0; i < 4; i++){
      int c = tid + i*256;
      int row = c >> 3, kc = (c & 7)*4;
      cp16(bsb + (uint32_t)((st*BSZ + row*36 + kc)*4), Bw + (size_t)row*ldb + k0 + kc);
    }
    if (ATRANS){
      #pragma unroll
      for (int i = 0; i < 4; i++){
        int c = tid + i*256;
        int kr = c >> 5, mc = (c & 31)*4;
        cp16(asb + (uint32_t)((st*ASZ + kr*136 + mc)*4), A + (size_t)(k0+kr)*lda + mc);
      }
    } else {
      #pragma unroll
      for (int i = 0; i < 4; i++){
        int c = tid + i*256;
        int row = c >> 3, kc = (c & 7)*4;
        cp16(asb + (uint32_t)((st*ASZ + row*36 + kc)*4), A + (size_t)row*lda + k0 + kc);
      }
    }
  };

  prefetch(0, 0);
  CP_COMMIT();
  int NK = K/BK;
  for (int kt = 0; kt < NK; kt++){
    if (kt + 1 < NK) prefetch((kt+1) & 1, (kt+1)*BK);
    CP_COMMIT();
    CP_WAIT1();
    __syncthreads();
    int st = kt & 1;
    const uint32_t* as = (const uint32_t*)(As + st*ASZ);
    const uint32_t* bs = (const uint32_t*)(Bs + st*BSZ);
    #pragma unroll
    for (int k8 = 0; k8 < BK; k8 += 8){
      uint32_t af[4][4], bf[4][2];
      #pragma unroll
      for (int mm = 0; mm < 4; mm++){
        int mb = wm + mm*16;
        if (ATRANS){
          af[mm][0] = as[(k8+tq  )*136 + mb + g];
          af[mm][1] = as[(k8+tq  )*136 + mb + g + 8];
          af[mm][2] = as[(k8+tq+4)*136 + mb + g];
          af[mm][3] = as[(k8+tq+4)*136 + mb + g + 8];
        } else {
          af[mm][0] = as[(mb + g    )*36 + k8 + tq];
          af[mm][1] = as[(mb + g + 8)*36 + k8 + tq];
          af[mm][2] = as[(mb + g    )*36 + k8 + tq + 4];
          af[mm][3] = as[(mb + g + 8)*36 + k8 + tq + 4];
        }
      }
      #pragma unroll
      for (int nn = 0; nn < 4; nn++){
        int nb = wn + nn*8;
        bf[nn][0] = bs[(nb + g)*36 + k8 + tq];
        bf[nn][1] = bs[(nb + g)*36 + k8 + tq + 4];
      }
      #pragma unroll
      for (int mm = 0; mm < 4; mm++)
        #pragma unroll
        for (int nn = 0; nn < 4; nn++){
          asm volatile(
            "mma.sync.aligned.m16n8k8.row.col.f32.tf32.tf32.f32 "
            "{%0,%1,%2,%3}, {%4,%5,%6,%7}, {%8,%9}, {%0,%1,%2,%3};\n"
            : "+f"(acc[mm][nn][0]), "+f"(acc[mm][nn][1]),
              "+f"(acc[mm][nn][2]), "+f"(acc[mm][nn][3])
            : "r"(af[mm][0]), "r"(af[mm][1]), "r"(af[mm][2]), "r"(af[mm][3]),
              "r"(bf[nn][0]), "r"(bf[nn][1]));
        }
    }
    __syncthreads();
  }

  #pragma unroll
  for (int mm = 0; mm < 4; mm++)
    #pragma unroll
    for (int nn = 0; nn < 4; nn++){
      int row0 = wm + mm*16 + g;
      int col  = wn + nn*8 + 2*tq;
      float2 v0 = make_float2(acc[mm][nn][0], acc[mm][nn][1]);
      float2 v1 = make_float2(acc[mm][nn][2], acc[mm][nn][3]);
      if (R){
        float2 r0 = *(const float2*)(R + (size_t)row0*rld + col);
        float2 r1 = *(const float2*)(R + (size_t)(row0+8)*rld + col);
        v0.x += r0.x; v0.y += r0.y; v1.x += r1.x; v1.y += r1.y;
      }
      *(float2*)(C + (size_t)row0*ldc + col)     = v0;
      *(float2*)(C + (size_t)(row0+8)*ldc + col) = v1;
    }
}

// ---------------- fused conv+silu+xproj: t-tile 64 ----------------
// Computes u = silu(conv(xh)) in smem, stores u to g_ut, accumulates
// x_dbl = xw @ u; dt rows -> g_dbl, B/C -> g_bcT.
__global__ __launch_bounds__(256) void k_xproj(
  const float* __restrict__ cw_f, const float* __restrict__ cb_f, const float* __restrict__ xw_f,
  const float* __restrict__ cw_b, const float* __restrict__ cb_b, const float* __restrict__ xw_b)
{
  extern __shared__ float dyn[];
  float* sxh = dyn;                 // [64][71]  (70 cols + pad) -> 4544
  float* su  = dyn + 64*71;         // [64][65]                  -> 4160
  float* sw  = dyn + 64*71 + 64*65; // [48][64]                  -> 3072
  float* sx  = sxh;                 // epilogue alias: [48][68] = 3264 <= 4544

  int tid = threadIdx.x;
  int t0  = blockIdx.x*64;
  int b   = blockIdx.y;
  int dir = blockIdx.z;
  const float* cw = dir ? cw_b : cw_f;
  const float* cb = dir ? cb_b : cb_f;
  const float* xw = dir ? xw_b : xw_f;

  int col = tid & 63;               // t within tile
  int rq  = tid >> 6;               // 0..3 -> rows rq*12..rq*12+11
  float acc[12];
  #pragma unroll
  for (int r = 0; r < 12; r++) acc[r] = 0.f;

  int dl = tid >> 2;                // conv: local channel 0..63
  int sq = (tid & 3)*16;            // conv: 16 timesteps per thread
  int off = dir ? 3 : 0;

  for (int k0 = 0; k0 < DINN; k0 += 64){
    __syncthreads();
    // load xh window rows k0..k0+63, cols [t0-3, t0+66]
    for (int i = tid; i < 64*70; i += 256){
      int r = i / 70, c = i - r*70;
      int t = t0 - 3 + c;
      sxh[r*71 + c] = (t >= 0 && t < LL)
        ? g_xzT[((size_t)(dir*1024 + k0 + r))*MROWS + b*LL + t] : 0.f;
    }
    // load weights [48][64]
    for (int i = tid; i < 48*64; i += 256){
      int r = i >> 6, k = i & 63;
      sw[i] = xw[r*DINN + k0 + k];
    }
    __syncthreads();

    // conv + silu -> su, and store u to g_ut
    {
      int d = k0 + dl;
      float w0, w1, w2, w3;
      if (dir == 0){ w0 = cw[d*4+0]; w1 = cw[d*4+1]; w2 = cw[d*4+2]; w3 = cw[d*4+3]; }
      else         { w0 = cw[d*4+3]; w1 = cw[d*4+2]; w2 = cw[d*4+1]; w3 = cw[d*4+0]; }
      float bias = cb[d];
      const float* xr = sxh + dl*71 + off;
      float uu[16];
      #pragma unroll
      for (int j = 0; j < 16; j++){
        int s = sq + j;
        float a = bias + w0*xr[s] + w1*xr[s+1] + w2*xr[s+2] + w3*xr[s+3];
        uu[j] = a/(1.f + __expf(-a));
        su[dl*65 + s] = uu[j];
      }
      float* up = g_ut + ((size_t)((dir*BB + b)*DINN + d))*LL + t0 + sq;
      #pragma unroll
      for (int j = 0; j < 16; j += 4)
        *(float4*)(up + j) = make_float4(uu[j], uu[j+1], uu[j+2], uu[j+3]);
    }
    __syncthreads();

    // GEMM accumulate: acc[r] += sum_k sw[row][k] * su[k][col]
    #pragma unroll 8
    for (int k = 0; k < 64; k++){
      float u0 = su[k*65 + col];
      #pragma unroll
      for (int r = 0; r < 12; r++)
        acc[r] = fmaf(sw[(rq*12 + r)*64 + k], u0, acc[r]);
    }
  }

  __syncthreads();
  #pragma unroll
  for (int r = 0; r < 12; r++)
    sx[(rq*12 + r)*68 + col] = acc[r];
  __syncthreads();

  // dt-rank rows (0..15) -> g_dbl [r][t]
  size_t obase = (size_t)(dir*BB + b)*48*LL;
  for (int i = tid; i < 16*16; i += 256){
    int row = i >> 4, seg = (i & 15)*4;
    *(float4*)&g_dbl[obase + (size_t)row*LL + t0 + seg] = *(float4*)&sx[row*68 + seg];
  }
  // B/C rows (16..47) -> g_bcT t-major [t][32] (coalesced global writes)
  size_t cbase = ((size_t)(dir*BB + b)*LL + t0)*32;
  for (int i = tid; i < 64*32; i += 256){
    int t = i >> 5, n = i & 31;
    g_bcT[cbase + (size_t)t*32 + n] = sx[(16 + n)*68 + t];
  }
}

// ---------------- dt projection + softplus (coalesced) ----------------
__global__ __launch_bounds__(128) void k_dt(
  const float* __restrict__ dw_f, const float* __restrict__ db_f,
  const float* __restrict__ dw_b, const float* __restrict__ db_b)
{
  int t   = blockIdx.x*512 + threadIdx.x*4;
  int d   = blockIdx.y;
  int bb  = blockIdx.z;            // dir*4 + b
  int dir = bb >> 2;
  const float* dw = dir ? dw_b : dw_f;
  const float* db = dir ? db_b : db_f;

  float dwr[16];
  #pragma unroll
  for (int i = 0; i < 16; i += 4)
    *(float4*)&dwr[i] = *(const float4*)(dw + d*16 + i);
  float bd = db[d];

  const float* px = g_dbl + (size_t)bb*48*LL;
  float s0 = bd, s1 = bd, s2 = bd, s3 = bd;
  #pragma unroll
  for (int r = 0; r < 16; r++){
    float4 xv = *(const float4*)(px + (size_t)r*LL + t);
    s0 = fmaf(dwr[r], xv.x, s0);
    s1 = fmaf(dwr[r], xv.y, s1);
    s2 = fmaf(dwr[r], xv.z, s2);
    s3 = fmaf(dwr[r], xv.w, s3);
  }
  s0 = (s0 > 20.f) ? s0 : log1pf(__expf(s0));
  s1 = (s1 > 20.f) ? s1 : log1pf(__expf(s1));
  s2 = (s2 > 20.f) ? s2 : log1pf(__expf(s2));
  s3 = (s3 > 20.f) ? s3 : log1pf(__expf(s3));
  *(float4*)(g_dtt + ((size_t)(bb*DINN + d))*LL + t) = make_float4(s0, s1, s2, s3);
}

// ---------------- selective scan: smem-staged B/C, prefetched loads ----------
__device__ __forceinline__ float sstep(float dt, float uu, float Bv, float a, float &h){
  float dA = __expf(dt*a);
  h = fmaf(dA, h, dt*Bv*uu);
  return h;
}

__global__ __launch_bounds__(256) void k3_scan(
  const float* __restrict__ alog_f, const float* __restrict__ alog_b,
  const float* __restrict__ Dpf,   const float* __restrict__ Dpb)
{
  __shared__ float sbc[CHT*32];    // 32KB: [t][32] (B 0-15, C 16-31)
  int tid = threadIdx.x;
  int ch = blockIdx.x*16 + (tid >> 4);
  int n  = tid & 15;
  int dir = ch >> 11;
  int b   = (ch >> 9) & 3;
  int d   = ch & 511;

  float a  = -__expf((dir ? alog_b : alog_f)[d*16 + n]);
  float dp = (dir ? Dpb : Dpf)[d];

  size_t cbase = ((size_t)((dir*BB + b)*DINN + d))*LL;
  const float* pdt = g_dtt + cbase;
  const float* pu  = g_ut  + cbase;
  const float* pz  = g_xzT + ((size_t)(dir*1024 + 512 + d))*MROWS + b*LL;
  const float* pbc = g_bcT + ((size_t)(dir*BB + b))*LL*32;
  float* pyT = g_yT + ((size_t)(dir*DINN + d))*MROWS + b*LL;

  float h = 0.f;
  bool b3 = (n & 8) != 0, b2 = (n & 4) != 0;
  bool wr = (n & 3) == 0;
  int tmap = (b3 ? 2 : 0) + (b2 ? 1 : 0);

  for (int c = 0; c < LL/CHT; c++){
    int tc0 = dir ? (LL - (c+1)*CHT) : c*CHT;
    __syncthreads();
    {
      const float4* src = (const float4*)(pbc + (size_t)tc0*32);
      float4* dst = (float4*)sbc;
      #pragma unroll
      for (int i = 0; i < CHT*32/4/256; i++)
        dst[tid + i*256] = src[tid + i*256];
    }
    __syncthreads();

    int t4    = dir ? (tc0 + CHT - 4) : tc0;
    int tstep = dir ? -4 : 4;
    float4 dt4 = *(const float4*)(pdt + t4);
    float4 u4  = *(const float4*)(pu  + t4);
    float4 z4  = *(const float4*)(pz  + t4);

    for (int it = 0; it < CHT/4; it++){
      // prefetch next iteration (clamped; value unused on last iter)
      int t4n = t4 + tstep;
      int t4c = t4n < 0 ? 0 : (t4n > LL-4 ? LL-4 : t4n);
      float4 dtn = *(const float4*)(pdt + t4c);
      float4 un  = *(const float4*)(pu  + t4c);
      float4 zn  = *(const float4*)(pz  + t4c);

      int tl = (t4 - tc0)*32;
      float B0 = sbc[tl +      n], C0 = sbc[tl +      16 + n];
      float B1 = sbc[tl + 32 + n], C1 = sbc[tl + 32 + 16 + n];
      float B2 = sbc[tl + 64 + n], C2 = sbc[tl + 64 + 16 + n];
      float B3 = sbc[tl + 96 + n], C3 = sbc[tl + 96 + 16 + n];

      float y0, y1, y2, y3;
      if (dir == 0){
        y0 = sstep(dt4.x, u4.x, B0, a, h) * C0;
        y1 = sstep(dt4.y, u4.y, B1, a, h) * C1;
        y2 = sstep(dt4.z, u4.z, B2, a, h) * C2;
        y3 = sstep(dt4.w, u4.w, B3, a, h) * C3;
      } else {
        y3 = sstep(dt4.w, u4.w, B3, a, h) * C3;
        y2 = sstep(dt4.z, u4.z, B2, a, h) * C2;
        y1 = sstep(dt4.y, u4.y, B1, a, h) * C1;
        y0 = sstep(dt4.x, u4.x, B0, a, h) * C0;
      }

      // multi-value butterfly: 5 shfls reduce 4 values over 16 lanes
      float slo = b3 ? y0 : y2;
      float shi = b3 ? y1 : y3;
      float rlo = __shfl_xor_sync(0xffffffffu, slo, 8);
      float rhi = __shfl_xor_sync(0xffffffffu, shi, 8);
      float p0  = (b3 ? y2 : y0) + rlo;
      float p1  = (b3 ? y3 : y1) + rhi;
      float sb  = b2 ? p0 : p1;
      float rb  = __shfl_xor_sync(0xffffffffu, sb, 4);
      float v   = (b2 ? p1 : p0) + rb;
      v += __shfl_xor_sync(0xffffffffu, v, 2);
      v += __shfl_xor_sync(0xffffffffu, v, 1);

      if (wr){
        float ut = b3 ? (b2 ? u4.w : u4.z) : (b2 ? u4.y : u4.x);
        float zv = b3 ? (b2 ? z4.w : z4.z) : (b2 ? z4.y : z4.x);
        float sz = zv/(1.f + __expf(-zv));
        pyT[t4 + tmap] = (v + ut*dp)*sz;
      }
      dt4 = dtn; u4 = un; z4 = zn; t4 = t4n;
    }
  }
}

// ---------------- launch ----------------
extern "C" void kernel_launch(void* const* d_in, const int* in_sizes, int n_in,
                              void* d_out, int out_size)
{
  (void)in_sizes; (void)n_in; (void)out_size;
  const float* x       = (const float*)d_in[0];
  const float* fw_norm = (const float*)d_in[1];
  const float* fw_inw  = (const float*)d_in[2];
  const float* fw_cw   = (const float*)d_in[3];
  const float* fw_cb   = (const float*)d_in[4];
  const float* fw_xw   = (const float*)d_in[5];
  const float* fw_dw   = (const float*)d_in[6];
  const float* fw_db   = (const float*)d_in[7];
  const float* fw_al   = (const float*)d_in[8];
  const float* fw_Dp   = (const float*)d_in[9];
  const float* fw_ow   = (const float*)d_in[10];
  const float* bw_norm = (const float*)d_in[11];
  const float* bw_inw  = (const float*)d_in[12];
  const float* bw_cw   = (const float*)d_in[13];
  const float* bw_cb   = (const float*)d_in[14];
  const float* bw_xw   = (const float*)d_in[15];
  const float* bw_dw   = (const float*)d_in[16];
  const float* bw_db   = (const float*)d_in[17];
  const float* bw_al   = (const float*)d_in[18];
  const float* bw_Dp   = (const float*)d_in[19];
  const float* bw_ow   = (const float*)d_in[20];

  float *p_xn, *p_w1, *p_w2, *p_xzT, *p_yT;
  cudaGetSymbolAddress((void**)&p_xn, g_xn);
  cudaGetSymbolAddress((void**)&p_w1, g_w1);
  cudaGetSymbolAddress((void**)&p_w2, g_w2);
  cudaGetSymbolAddress((void**)&p_xzT, g_xzT);
  cudaGetSymbolAddress((void**)&p_yT, g_yT);

  const int smemA0 = (2*(128*36) + 2*(128*36))*(int)sizeof(float);   // 73728
  const int smemA1 = (2*(32*136) + 2*(128*36))*(int)sizeof(float);   // 71680
  cudaFuncSetAttribute(k_gemm_db<0>, cudaFuncAttributeMaxDynamicSharedMemorySize, smemA0);
  cudaFuncSetAttribute(k_gemm_db<1>, cudaFuncAttributeMaxDynamicSharedMemorySize, smemA1);

  // 1) fused prep + rmsnorm
  k_prep_rms<<<MROWS + 2048 + 1024, 256>>>(x, fw_inw, fw_norm, bw_inw, bw_norm,
                                           fw_ow, bw_ow);
  // 2) in_proj: g_xzT[2048 x 8192] = w1[2048x256] @ xn[8192x256]^T
  k_gemm_db<0><<<dim3(64, 16), 256, smemA0>>>(p_w1, DD, (size_t)0, 1000000,
                                              p_xn, DD, p_xzT, MROWS, nullptr, DD, DD);
  // 3) fused conv + silu + x_dbl projection
  int smemx = (64*71 + 64*65 + 48*64)*(int)sizeof(float);   // 47104
  cudaFuncSetAttribute(k_xproj, cudaFuncAttributeMaxDynamicSharedMemorySize, smemx);
  k_xproj<<<dim3(LL/64, BB, NDIR), 256, smemx>>>(fw_cw, fw_cb, fw_xw,
                                                 bw_cw, bw_cb, bw_xw);
  // 4) dt projection + softplus
  k_dt<<<dim3(LL/512, DINN, BB*NDIR), 128>>>(fw_dw, fw_db, bw_dw, bw_db);
  // 5) selective scan
  k3_scan<<<256, 256>>>(fw_al, bw_al, fw_Dp, bw_Dp);
  // 6) out_proj + residual
  k_gemm_db<1><<<dim3(4, 64), 256, smemA1>>>(p_yT, MROWS, (size_t)DINN*MROWS, 2,
                                             p_w2, DINN, (float*)d_out, 2*DD, x, DD, DINN);
}

// round 10
// speedup vs baseline: 2.3528x; 1.0062x over previous
#include <cuda_runtime.h>
#include <math.h>
#include <stdint.h>

#define BB 4
#define LL 2048
#define DD 256
#define DINN 512
#define NST 16
#define NDIR 2
#define MROWS (BB*LL)      // 8192
#define N1 2048
#define EPSF 1e-5f
#define CHT 256            // scan smem chunk (timesteps)

// ---------------- scratch ----------------
__device__ float g_xn[MROWS*DD];
__device__ float g_w1[N1*DD];
__device__ float g_w2[NDIR*DD*DINN];
__device__ float g_xzT[(size_t)N1*MROWS];          // in_proj out [e][b*L+t]
__device__ float g_ut [(size_t)NDIR*BB*DINN*LL];   // u [dir][b][d][t]
__device__ float g_dtt[(size_t)NDIR*BB*DINN*LL];   // dt [dir][b][d][t]
__device__ float g_bcT[(size_t)NDIR*BB*LL*32];     // B/C t-major [dir][b][t][32]
__device__ float g_yT [(size_t)NDIR*DINN*MROWS];   // scan out [dir][d][b*L+t]

// ---------------- fused prep (w1 fold, w2 stack) + rmsnorm ----------------
__global__ __launch_bounds__(256) void k_prep_rms(
    const float* __restrict__ x,
    const float* __restrict__ inw_f, const float* __restrict__ nw_f,
    const float* __restrict__ inw_b, const float* __restrict__ nw_b,
    const float* __restrict__ ow_f,  const float* __restrict__ ow_b)
{
  int blk = blockIdx.x;
  int tid = threadIdx.x;
  if (blk < MROWS){
    int row = blk;
    float v = x[row*DD + tid];
    float s = v*v;
    #pragma unroll
    for (int o = 16; o; o >>= 1) s += __shfl_xor_sync(0xffffffffu, s, o);
    __shared__ float ws[8];
    __shared__ float scale;
    if ((tid & 31) == 0) ws[tid >> 5] = s;
    __syncthreads();
    if (tid == 0){
      float t = 0.f;
      #pragma unroll
      for (int i = 0; i < 8; i++) t += ws[i];
      scale = rsqrtf(t*(1.0f/DD) + EPSF);
    }
    __syncthreads();
    g_xn[row*DD + tid] = v*scale;
  } else if (blk < MROWS + 2048){
    int i = (blk - MROWS)*256 + tid;
    int dir = i / (1024*DD);
    int rem = i - dir*1024*DD;
    int d = rem % DD;
    g_w1[i] = dir ? inw_b[rem]*nw_b[d] : inw_f[rem]*nw_f[d];
  } else {
    int i = (blk - MROWS - 2048)*256 + tid;
    int dir = i / (DD*DINN);
    int rem = i - dir*DD*DINN;
    g_w2[i] = dir ? ow_b[rem] : ow_f[rem];
  }
}

// ---------------- cp.async helpers ----------------
__device__ __forceinline__ void cp16(uint32_t dst, const float* src){
  asm volatile("cp.async.ca.shared.global [%0], [%1], 16;\n" :: "r"(dst), "l"(src));
}
#define CP_COMMIT() asm volatile("cp.async.commit_group;\n" ::: "memory")
#define CP_WAIT1()  asm volatile("cp.async.wait_group 1;\n" ::: "memory")

// ---------------- double-buffered TF32 GEMM, BK=32 ----------------
template<int ATRANS>
__global__ __launch_bounds__(256) void k_gemm_db(
    const float* __restrict__ A, int lda, size_t aDirStride, int bpdX,
    const float* __restrict__ Bw, int ldb,
    float* __restrict__ C, int ldc,
    const float* __restrict__ resid, int rld, int K)
{
  const int BM = 128, BN = 128, BK = 32;
  const int ASZ = ATRANS ? 32*136 : 128*36;
  const int BSZ = 128*36;
  extern __shared__ float dyn[];
  float* As = dyn;
  float* Bs = dyn + 2*ASZ;

  int tid = threadIdx.x;
  int bx = blockIdx.x, by = blockIdx.y;
  int dir = bx / bpdX;
  A  += (size_t)dir*aDirStride + (ATRANS ? (size_t)(by*BM) : (size_t)(by*BM)*lda);
  Bw += (size_t)(bx*BN)*ldb;
  C  += (size_t)(by*BM)*ldc + (size_t)(bx*BN);
  const float* R = resid ? (resid + (size_t)(by*BM)*rld + (size_t)(bx % bpdX)*BN) : nullptr;

  uint32_t asb = (uint32_t)__cvta_generic_to_shared(As);
  uint32_t bsb = (uint32_t)__cvta_generic_to_shared(Bs);

  int warp = tid >> 5, lane = tid & 31;
  int wm = (warp >> 2)*64, wn = (warp & 3)*32;
  int g  = lane >> 2, tq = lane & 3;

  float acc[4][4][4];
  #pragma unroll
  for (int i = 0; i < 4; i++)
    #pragma unroll
    for (int j = 0; j < 4; j++)
      #pragma unroll
      for (int q = 0; q < 4; q++) acc[i][j][q] = 0.f;

  auto prefetch = [&](int st, int k0){
    #pragma unroll
    for (int i = 0; i < 4; i++){
      int c = tid + i*256;
      int row = c >> 3, kc = (c & 7)*4;
      cp16(bsb + (uint32_t)((st*BSZ + row*36 + kc)*4), Bw + (size_t)row*ldb + k0 + kc);
    }
    if (ATRANS){
      #pragma unroll
      for (int i = 0; i < 4; i++){
        int c = tid + i*256;
        int kr = c >> 5, mc = (c & 31)*4;
        cp16(asb + (uint32_t)((st*ASZ + kr*136 + mc)*4), A + (size_t)(k0+kr)*lda + mc);
      }
    } else {
      #pragma unroll
      for (int i = 0; i < 4; i++){
        int c = tid + i*256;
        int row = c >> 3, kc = (c & 7)*4;
        cp16(asb + (uint32_t)((st*ASZ + row*36 + kc)*4), A + (size_t)row*lda + k0 + kc);
      }
    }
  };

  prefetch(0, 0);
  CP_COMMIT();
  int NK = K/BK;
  for (int kt = 0; kt < NK; kt++){
    if (kt + 1 < NK) prefetch((kt+1) & 1, (kt+1)*BK);
    CP_COMMIT();
    CP_WAIT1();
    __syncthreads();
    int st = kt & 1;
    const uint32_t* as = (const uint32_t*)(As + st*ASZ);
    const uint32_t* bs = (const uint32_t*)(Bs + st*BSZ);
    #pragma unroll
    for (int k8 = 0; k8 < BK; k8 += 8){
      uint32_t af[4][4], bf[4][2];
      #pragma unroll
      for (int mm = 0; mm < 4; mm++){
        int mb = wm + mm*16;
        if (ATRANS){
          af[mm][0] = as[(k8+tq  )*136 + mb + g];
          af[mm][1] = as[(k8+tq  )*136 + mb + g + 8];
          af[mm][2] = as[(k8+tq+4)*136 + mb + g];
          af[mm][3] = as[(k8+tq+4)*136 + mb + g + 8];
        } else {
          af[mm][0] = as[(mb + g    )*36 + k8 + tq];
          af[mm][1] = as[(mb + g + 8)*36 + k8 + tq];
          af[mm][2] = as[(mb + g    )*36 + k8 + tq + 4];
          af[mm][3] = as[(mb + g + 8)*36 + k8 + tq + 4];
        }
      }
      #pragma unroll
      for (int nn = 0; nn < 4; nn++){
        int nb = wn + nn*8;
        bf[nn][0] = bs[(nb + g)*36 + k8 + tq];
        bf[nn][1] = bs[(nb + g)*36 + k8 + tq + 4];
      }
      #pragma unroll
      for (int mm = 0; mm < 4; mm++)
        #pragma unroll
        for (int nn = 0; nn < 4; nn++){
          asm volatile(
            "mma.sync.aligned.m16n8k8.row.col.f32.tf32.tf32.f32 "
            "{%0,%1,%2,%3}, {%4,%5,%6,%7}, {%8,%9}, {%0,%1,%2,%3};\n"
            : "+f"(acc[mm][nn][0]), "+f"(acc[mm][nn][1]),
              "+f"(acc[mm][nn][2]), "+f"(acc[mm][nn][3])
            : "r"(af[mm][0]), "r"(af[mm][1]), "r"(af[mm][2]), "r"(af[mm][3]),
              "r"(bf[nn][0]), "r"(bf[nn][1]));
        }
    }
    __syncthreads();
  }

  #pragma unroll
  for (int mm = 0; mm < 4; mm++)
    #pragma unroll
    for (int nn = 0; nn < 4; nn++){
      int row0 = wm + mm*16 + g;
      int col  = wn + nn*8 + 2*tq;
      float2 v0 = make_float2(acc[mm][nn][0], acc[mm][nn][1]);
      float2 v1 = make_float2(acc[mm][nn][2], acc[mm][nn][3]);
      if (R){
        float2 r0 = *(const float2*)(R + (size_t)row0*rld + col);
        float2 r1 = *(const float2*)(R + (size_t)(row0+8)*rld + col);
        v0.x += r0.x; v0.y += r0.y; v1.x += r1.x; v1.y += r1.y;
      }
      *(float2*)(C + (size_t)row0*ldc + col)     = v0;
      *(float2*)(C + (size_t)(row0+8)*ldc + col) = v1;
    }
}

// ---------------- fused conv+silu+xproj+dtproj: t-tile 64 ----------------
__global__ __launch_bounds__(256) void k_xproj(
  const float* __restrict__ cw_f, const float* __restrict__ cb_f, const float* __restrict__ xw_f,
  const float* __restrict__ dw_f, const float* __restrict__ db_f,
  const float* __restrict__ cw_b, const float* __restrict__ cb_b, const float* __restrict__ xw_b,
  const float* __restrict__ dw_b, const float* __restrict__ db_b)
{
  extern __shared__ float dyn[];
  float* sxh = dyn;                 // [64][71]  -> 4544 floats
  float* su  = dyn + 64*71;         // [64][65]  -> 4160 floats (reused for dw chunks)
  float* sw  = dyn + 64*71 + 64*65; // [48][64]  -> 3072 floats (reused for db)
  float* sx  = sxh;                 // epilogue alias: [48][68] = 3264 <= 4544

  int tid = threadIdx.x;
  int t0  = blockIdx.x*64;
  int b   = blockIdx.y;
  int dir = blockIdx.z;
  const float* cw = dir ? cw_b : cw_f;
  const float* cb = dir ? cb_b : cb_f;
  const float* xw = dir ? xw_b : xw_f;
  const float* dw = dir ? dw_b : dw_f;
  const float* dbp = dir ? db_b : db_f;

  int col = tid & 63;               // t within tile
  int rq  = tid >> 6;               // 0..3
  float acc[12];
  #pragma unroll
  for (int r = 0; r < 12; r++) acc[r] = 0.f;

  int dl = tid >> 2;                // conv: local channel 0..63
  int sq = (tid & 3)*16;            // conv: 16 timesteps per thread
  int off = dir ? 3 : 0;

  for (int k0 = 0; k0 < DINN; k0 += 64){
    __syncthreads();
    for (int i = tid; i < 64*70; i += 256){
      int r = i / 70, c = i - r*70;
      int t = t0 - 3 + c;
      sxh[r*71 + c] = (t >= 0 && t < LL)
        ? g_xzT[((size_t)(dir*1024 + k0 + r))*MROWS + b*LL + t] : 0.f;
    }
    for (int i = tid; i < 48*64; i += 256){
      int r = i >> 6, k = i & 63;
      sw[i] = xw[r*DINN + k0 + k];
    }
    __syncthreads();

    {
      int d = k0 + dl;
      float w0, w1, w2, w3;
      if (dir == 0){ w0 = cw[d*4+0]; w1 = cw[d*4+1]; w2 = cw[d*4+2]; w3 = cw[d*4+3]; }
      else         { w0 = cw[d*4+3]; w1 = cw[d*4+2]; w2 = cw[d*4+1]; w3 = cw[d*4+0]; }
      float bias = cb[d];
      const float* xr = sxh + dl*71 + off;
      float uu[16];
      #pragma unroll
      for (int j = 0; j < 16; j++){
        int s = sq + j;
        float a = bias + w0*xr[s] + w1*xr[s+1] + w2*xr[s+2] + w3*xr[s+3];
        uu[j] = a/(1.f + __expf(-a));
        su[dl*65 + s] = uu[j];
      }
      float* up = g_ut + ((size_t)((dir*BB + b)*DINN + d))*LL + t0 + sq;
      #pragma unroll
      for (int j = 0; j < 16; j += 4)
        *(float4*)(up + j) = make_float4(uu[j], uu[j+1], uu[j+2], uu[j+3]);
    }
    __syncthreads();

    #pragma unroll 8
    for (int k = 0; k < 64; k++){
      float u0 = su[k*65 + col];
      #pragma unroll
      for (int r = 0; r < 12; r++)
        acc[r] = fmaf(sw[(rq*12 + r)*64 + k], u0, acc[r]);
    }
  }

  __syncthreads();
  #pragma unroll
  for (int r = 0; r < 12; r++)
    sx[(rq*12 + r)*68 + col] = acc[r];
  // stage dt bias into sw (free after main loop)
  for (int i = tid; i < DINN; i += 256) sw[i] = dbp[i];
  __syncthreads();

  // B/C rows (16..47) -> g_bcT t-major [t][32]
  size_t cbase = ((size_t)(dir*BB + b)*LL + t0)*32;
  for (int i = tid; i < 64*32; i += 256){
    int t = i >> 5, n = i & 31;
    g_bcT[cbase + (size_t)t*32 + n] = sx[(16 + n)*68 + t];
  }

  // dt projection + softplus, fused: xr[16] in regs, dw staged in 2 chunks
  float xr[16];
  #pragma unroll
  for (int r = 0; r < 16; r++) xr[r] = sx[r*68 + col];
  float* dtbase = g_dtt + (size_t)(dir*BB + b)*DINN*LL + t0 + col;

  #pragma unroll
  for (int chunk = 0; chunk < 2; chunk++){
    int dbase = chunk*256;
    __syncthreads();
    // stage dw[dbase..dbase+255][16] (4096 floats) into su
    #pragma unroll
    for (int i = 0; i < 4; i++)
      ((float4*)su)[tid + i*256] = *(const float4*)(dw + (size_t)dbase*16 + (tid + i*256)*4);
    __syncthreads();
    #pragma unroll 4
    for (int dd = 0; dd < 64; dd++){
      int dl2 = rq*64 + dd;
      int d = dbase + dl2;
      float s = sw[d];
      const float* wrow = su + dl2*16;
      #pragma unroll
      for (int r = 0; r < 16; r++) s = fmaf(wrow[r], xr[r], s);
      s = (s > 20.f) ? s : log1pf(__expf(s));
      dtbase[(size_t)d*LL] = s;
    }
  }
}

// ---------------- selective scan: smem-staged B/C, prefetched loads ----------
__device__ __forceinline__ float sstep(float dt, float uu, float Bv, float a, float &h){
  float dA = __expf(dt*a);
  h = fmaf(dA, h, dt*Bv*uu);
  return h;
}

__global__ __launch_bounds__(256) void k3_scan(
  const float* __restrict__ alog_f, const float* __restrict__ alog_b,
  const float* __restrict__ Dpf,   const float* __restrict__ Dpb)
{
  __shared__ float sbc[CHT*32];    // 32KB: [t][32] (B 0-15, C 16-31)
  int tid = threadIdx.x;
  int ch = blockIdx.x*16 + (tid >> 4);
  int n  = tid & 15;
  int dir = ch >> 11;
  int b   = (ch >> 9) & 3;
  int d   = ch & 511;

  float a  = -__expf((dir ? alog_b : alog_f)[d*16 + n]);
  float dp = (dir ? Dpb : Dpf)[d];

  size_t cbase = ((size_t)((dir*BB + b)*DINN + d))*LL;
  const float* pdt = g_dtt + cbase;
  const float* pu  = g_ut  + cbase;
  const float* pz  = g_xzT + ((size_t)(dir*1024 + 512 + d))*MROWS + b*LL;
  const float* pbc = g_bcT + ((size_t)(dir*BB + b))*LL*32;
  float* pyT = g_yT + ((size_t)(dir*DINN + d))*MROWS + b*LL;

  float h = 0.f;
  bool b3 = (n & 8) != 0, b2 = (n & 4) != 0;
  bool wr = (n & 3) == 0;
  int tmap = (b3 ? 2 : 0) + (b2 ? 1 : 0);

  for (int c = 0; c < LL/CHT; c++){
    int tc0 = dir ? (LL - (c+1)*CHT) : c*CHT;
    __syncthreads();
    {
      const float4* src = (const float4*)(pbc + (size_t)tc0*32);
      float4* dst = (float4*)sbc;
      #pragma unroll
      for (int i = 0; i < CHT*32/4/256; i++)
        dst[tid + i*256] = src[tid + i*256];
    }
    __syncthreads();

    int t4    = dir ? (tc0 + CHT - 4) : tc0;
    int tstep = dir ? -4 : 4;
    float4 dt4 = *(const float4*)(pdt + t4);
    float4 u4  = *(const float4*)(pu  + t4);
    float4 z4  = *(const float4*)(pz  + t4);

    for (int it = 0; it < CHT/4; it++){
      int t4n = t4 + tstep;
      int t4c = t4n < 0 ? 0 : (t4n > LL-4 ? LL-4 : t4n);
      float4 dtn = *(const float4*)(pdt + t4c);
      float4 un  = *(const float4*)(pu  + t4c);
      float4 zn  = *(const float4*)(pz  + t4c);

      int tl = (t4 - tc0)*32;
      float B0 = sbc[tl +      n], C0 = sbc[tl +      16 + n];
      float B1 = sbc[tl + 32 + n], C1 = sbc[tl + 32 + 16 + n];
      float B2 = sbc[tl + 64 + n], C2 = sbc[tl + 64 + 16 + n];
      float B3 = sbc[tl + 96 + n], C3 = sbc[tl + 96 + 16 + n];

      float y0, y1, y2, y3;
      if (dir == 0){
        y0 = sstep(dt4.x, u4.x, B0, a, h) * C0;
        y1 = sstep(dt4.y, u4.y, B1, a, h) * C1;
        y2 = sstep(dt4.z, u4.z, B2, a, h) * C2;
        y3 = sstep(dt4.w, u4.w, B3, a, h) * C3;
      } else {
        y3 = sstep(dt4.w, u4.w, B3, a, h) * C3;
        y2 = sstep(dt4.z, u4.z, B2, a, h) * C2;
        y1 = sstep(dt4.y, u4.y, B1, a, h) * C1;
        y0 = sstep(dt4.x, u4.x, B0, a, h) * C0;
      }

      float slo = b3 ? y0 : y2;
      float shi = b3 ? y1 : y3;
      float rlo = __shfl_xor_sync(0xffffffffu, slo, 8);
      float rhi = __shfl_xor_sync(0xffffffffu, shi, 8);
      float p0  = (b3 ? y2 : y0) + rlo;
      float p1  = (b3 ? y3 : y1) + rhi;
      float sb  = b2 ? p0 : p1;
      float rb  = __shfl_xor_sync(0xffffffffu, sb, 4);
      float v   = (b2 ? p1 : p0) + rb;
      v += __shfl_xor_sync(0xffffffffu, v, 2);
      v += __shfl_xor_sync(0xffffffffu, v, 1);

      if (wr){
        float ut = b3 ? (b2 ? u4.w : u4.z) : (b2 ? u4.y : u4.x);
        float zv = b3 ? (b2 ? z4.w : z4.z) : (b2 ? z4.y : z4.x);
        float sz = zv/(1.f + __expf(-zv));
        pyT[t4 + tmap] = (v + ut*dp)*sz;
      }
      dt4 = dtn; u4 = un; z4 = zn; t4 = t4n;
    }
  }
}

// ---------------- launch ----------------
extern "C" void kernel_launch(void* const* d_in, const int* in_sizes, int n_in,
                              void* d_out, int out_size)
{
  (void)in_sizes; (void)n_in; (void)out_size;
  const float* x       = (const float*)d_in[0];
  const float* fw_norm = (const float*)d_in[1];
  const float* fw_inw  = (const float*)d_in[2];
  const float* fw_cw   = (const float*)d_in[3];
  const float* fw_cb   = (const float*)d_in[4];
  const float* fw_xw   = (const float*)d_in[5];
  const float* fw_dw   = (const float*)d_in[6];
  const float* fw_db   = (const float*)d_in[7];
  const float* fw_al   = (const float*)d_in[8];
  const float* fw_Dp   = (const float*)d_in[9];
  const float* fw_ow   = (const float*)d_in[10];
  const float* bw_norm = (const float*)d_in[11];
  const float* bw_inw  = (const float*)d_in[12];
  const float* bw_cw   = (const float*)d_in[13];
  const float* bw_cb   = (const float*)d_in[14];
  const float* bw_xw   = (const float*)d_in[15];
  const float* bw_dw   = (const float*)d_in[16];
  const float* bw_db   = (const float*)d_in[17];
  const float* bw_al   = (const float*)d_in[18];
  const float* bw_Dp   = (const float*)d_in[19];
  const float* bw_ow   = (const float*)d_in[20];

  float *p_xn, *p_w1, *p_w2, *p_xzT, *p_yT;
  cudaGetSymbolAddress((void**)&p_xn, g_xn);
  cudaGetSymbolAddress((void**)&p_w1, g_w1);
  cudaGetSymbolAddress((void**)&p_w2, g_w2);
  cudaGetSymbolAddress((void**)&p_xzT, g_xzT);
  cudaGetSymbolAddress((void**)&p_yT, g_yT);

  const int smemA0 = (2*(128*36) + 2*(128*36))*(int)sizeof(float);   // 73728
  const int smemA1 = (2*(32*136) + 2*(128*36))*(int)sizeof(float);   // 71680
  cudaFuncSetAttribute(k_gemm_db<0>, cudaFuncAttributeMaxDynamicSharedMemorySize, smemA0);
  cudaFuncSetAttribute(k_gemm_db<1>, cudaFuncAttributeMaxDynamicSharedMemorySize, smemA1);

  // 1) fused prep + rmsnorm
  k_prep_rms<<<MROWS + 2048 + 1024, 256>>>(x, fw_inw, fw_norm, bw_inw, bw_norm,
                                           fw_ow, bw_ow);
  // 2) in_proj: g_xzT[2048 x 8192] = w1[2048x256] @ xn[8192x256]^T
  k_gemm_db<0><<<dim3(64, 16), 256, smemA0>>>(p_w1, DD, (size_t)0, 1000000,
                                              p_xn, DD, p_xzT, MROWS, nullptr, DD, DD);
  // 3) fused conv + silu + x_dbl + dt projection
  int smemx = (64*71 + 64*65 + 48*64)*(int)sizeof(float);   // 47104
  cudaFuncSetAttribute(k_xproj, cudaFuncAttributeMaxDynamicSharedMemorySize, smemx);
  k_xproj<<<dim3(LL/64, BB, NDIR), 256, smemx>>>(fw_cw, fw_cb, fw_xw, fw_dw, fw_db,
                                                 bw_cw, bw_cb, bw_xw, bw_dw, bw_db);
  // 4) selective scan  (launch #4 -> ncu capture slot)
  k3_scan<<<256, 256>>>(fw_al, bw_al, fw_Dp, bw_Dp);
  // 5) out_proj + residual
  k_gemm_db<1><<<dim3(4, 64), 256, smemA1>>>(p_yT, MROWS, (size_t)DINN*MROWS, 2,
                                             p_w2, DINN, (float*)d_out, 2*DD, x, DD, DINN);
}

// round 11
// speedup vs baseline: 2.5024x; 1.0636x over previous
#include <cuda_runtime.h>
#include <math.h>
#include <stdint.h>

#define BB 4
#define LL 2048
#define DD 256
#define DINN 512
#define NST 16
#define NDIR 2
#define MROWS (BB*LL)      // 8192
#define N1 2048
#define EPSF 1e-5f
#define CHT 256            // scan smem chunk (timesteps)

// ---------------- scratch ----------------
__device__ float g_xn[MROWS*DD];
__device__ float g_w1[N1*DD];
__device__ float g_w2[NDIR*DD*DINN];
__device__ float g_xzT[(size_t)N1*MROWS];          // in_proj out [e][b*L+t]
__device__ float g_ut [(size_t)NDIR*BB*DINN*LL];   // u [dir][b][d][t]
__device__ float g_dtt[(size_t)NDIR*BB*DINN*LL];   // dt [dir][b][d][t]
__device__ float g_bcT[(size_t)NDIR*BB*LL*32];     // B/C interleaved [dir][b][t][n][{B,C}]
__device__ float g_yT [(size_t)NDIR*DINN*MROWS];   // scan out [dir][d][b*L+t]

// ---------------- fused prep (w1 fold, w2 stack) + rmsnorm ----------------
__global__ __launch_bounds__(256) void k_prep_rms(
    const float* __restrict__ x,
    const float* __restrict__ inw_f, const float* __restrict__ nw_f,
    const float* __restrict__ inw_b, const float* __restrict__ nw_b,
    const float* __restrict__ ow_f,  const float* __restrict__ ow_b)
{
  int blk = blockIdx.x;
  int tid = threadIdx.x;
  if (blk < MROWS){
    int row = blk;
    float v = x[row*DD + tid];
    float s = v*v;
    #pragma unroll
    for (int o = 16; o; o >>= 1) s += __shfl_xor_sync(0xffffffffu, s, o);
    __shared__ float ws[8];
    __shared__ float scale;
    if ((tid & 31) == 0) ws[tid >> 5] = s;
    __syncthreads();
    if (tid == 0){
      float t = 0.f;
      #pragma unroll
      for (int i = 0; i < 8; i++) t += ws[i];
      scale = rsqrtf(t*(1.0f/DD) + EPSF);
    }
    __syncthreads();
    g_xn[row*DD + tid] = v*scale;
  } else if (blk < MROWS + 2048){
    int i = (blk - MROWS)*256 + tid;
    int dir = i / (1024*DD);
    int rem = i - dir*1024*DD;
    int d = rem % DD;
    g_w1[i] = dir ? inw_b[rem]*nw_b[d] : inw_f[rem]*nw_f[d];
  } else {
    int i = (blk - MROWS - 2048)*256 + tid;
    int dir = i / (DD*DINN);
    int rem = i - dir*DD*DINN;
    g_w2[i] = dir ? ow_b[rem] : ow_f[rem];
  }
}

// ---------------- cp.async helpers ----------------
__device__ __forceinline__ void cp16(uint32_t dst, const float* src){
  asm volatile("cp.async.ca.shared.global [%0], [%1], 16;\n" :: "r"(dst), "l"(src));
}
#define CP_COMMIT() asm volatile("cp.async.commit_group;\n" ::: "memory")
#define CP_WAIT1()  asm volatile("cp.async.wait_group 1;\n" ::: "memory")

// ---------------- double-buffered TF32 GEMM, BK=32 ----------------
template<int ATRANS>
__global__ __launch_bounds__(256) void k_gemm_db(
    const float* __restrict__ A, int lda, size_t aDirStride, int bpdX,
    const float* __restrict__ Bw, int ldb,
    float* __restrict__ C, int ldc,
    const float* __restrict__ resid, int rld, int K)
{
  const int BM = 128, BN = 128, BK = 32;
  const int ASZ = ATRANS ? 32*136 : 128*36;
  const int BSZ = 128*36;
  extern __shared__ float dyn[];
  float* As = dyn;
  float* Bs = dyn + 2*ASZ;

  int tid = threadIdx.x;
  int bx = blockIdx.x, by = blockIdx.y;
  int dir = bx / bpdX;
  A  += (size_t)dir*aDirStride + (ATRANS ? (size_t)(by*BM) : (size_t)(by*BM)*lda);
  Bw += (size_t)(bx*BN)*ldb;
  C  += (size_t)(by*BM)*ldc + (size_t)(bx*BN);
  const float* R = resid ? (resid + (size_t)(by*BM)*rld + (size_t)(bx % bpdX)*BN) : nullptr;

  uint32_t asb = (uint32_t)__cvta_generic_to_shared(As);
  uint32_t bsb = (uint32_t)__cvta_generic_to_shared(Bs);

  int warp = tid >> 5, lane = tid & 31;
  int wm = (warp >> 2)*64, wn = (warp & 3)*32;
  int g  = lane >> 2, tq = lane & 3;

  float acc[4][4][4];
  #pragma unroll
  for (int i = 0; i < 4; i++)
    #pragma unroll
    for (int j = 0; j < 4; j++)
      #pragma unroll
      for (int q = 0; q < 4; q++) acc[i][j][q] = 0.f;

  auto prefetch = [&](int st, int k0){
    #pragma unroll
    for (int i = 0; i < 4; i++){
      int c = tid + i*256;
      int row = c >> 3, kc = (c & 7)*4;
      cp16(bsb + (uint32_t)((st*BSZ + row*36 + kc)*4), Bw + (size_t)row*ldb + k0 + kc);
    }
    if (ATRANS){
      #pragma unroll
      for (int i = 0; i < 4; i++){
        int c = tid + i*256;
        int kr = c >> 5, mc = (c & 31)*4;
        cp16(asb + (uint32_t)((st*ASZ + kr*136 + mc)*4), A + (size_t)(k0+kr)*lda + mc);
      }
    } else {
      #pragma unroll
      for (int i = 0; i < 4; i++){
        int c = tid + i*256;
        int row = c >> 3, kc = (c & 7)*4;
        cp16(asb + (uint32_t)((st*ASZ + row*36 + kc)*4), A + (size_t)row*lda + k0 + kc);
      }
    }
  };

  prefetch(0, 0);
  CP_COMMIT();
  int NK = K/BK;
  for (int kt = 0; kt < NK; kt++){
    if (kt + 1 < NK) prefetch((kt+1) & 1, (kt+1)*BK);
    CP_COMMIT();
    CP_WAIT1();
    __syncthreads();
    int st = kt & 1;
    const uint32_t* as = (const uint32_t*)(As + st*ASZ);
    const uint32_t* bs = (const uint32_t*)(Bs + st*BSZ);
    #pragma unroll
    for (int k8 = 0; k8 < BK; k8 += 8){
      uint32_t af[4][4], bf[4][2];
      #pragma unroll
      for (int mm = 0; mm < 4; mm++){
        int mb = wm + mm*16;
        if (ATRANS){
          af[mm][0] = as[(k8+tq  )*136 + mb + g];
          af[mm][1] = as[(k8+tq  )*136 + mb + g + 8];
          af[mm][2] = as[(k8+tq+4)*136 + mb + g];
          af[mm][3] = as[(k8+tq+4)*136 + mb + g + 8];
        } else {
          af[mm][0] = as[(mb + g    )*36 + k8 + tq];
          af[mm][1] = as[(mb + g + 8)*36 + k8 + tq];
          af[mm][2] = as[(mb + g    )*36 + k8 + tq + 4];
          af[mm][3] = as[(mb + g + 8)*36 + k8 + tq + 4];
        }
      }
      #pragma unroll
      for (int nn = 0; nn < 4; nn++){
        int nb = wn + nn*8;
        bf[nn][0] = bs[(nb + g)*36 + k8 + tq];
        bf[nn][1] = bs[(nb + g)*36 + k8 + tq + 4];
      }
      #pragma unroll
      for (int mm = 0; mm < 4; mm++)
        #pragma unroll
        for (int nn = 0; nn < 4; nn++){
          asm volatile(
            "mma.sync.aligned.m16n8k8.row.col.f32.tf32.tf32.f32 "
            "{%0,%1,%2,%3}, {%4,%5,%6,%7}, {%8,%9}, {%0,%1,%2,%3};\n"
            : "+f"(acc[mm][nn][0]), "+f"(acc[mm][nn][1]),
              "+f"(acc[mm][nn][2]), "+f"(acc[mm][nn][3])
            : "r"(af[mm][0]), "r"(af[mm][1]), "r"(af[mm][2]), "r"(af[mm][3]),
              "r"(bf[nn][0]), "r"(bf[nn][1]));
        }
    }
    __syncthreads();
  }

  #pragma unroll
  for (int mm = 0; mm < 4; mm++)
    #pragma unroll
    for (int nn = 0; nn < 4; nn++){
      int row0 = wm + mm*16 + g;
      int col  = wn + nn*8 + 2*tq;
      float2 v0 = make_float2(acc[mm][nn][0], acc[mm][nn][1]);
      float2 v1 = make_float2(acc[mm][nn][2], acc[mm][nn][3]);
      if (R){
        float2 r0 = *(const float2*)(R + (size_t)row0*rld + col);
        float2 r1 = *(const float2*)(R + (size_t)(row0+8)*rld + col);
        v0.x += r0.x; v0.y += r0.y; v1.x += r1.x; v1.y += r1.y;
      }
      *(float2*)(C + (size_t)row0*ldc + col)     = v0;
      *(float2*)(C + (size_t)(row0+8)*ldc + col) = v1;
    }
}

// ---------------- fused conv+silu+xproj+dtproj: t-tile 64 ----------------
__global__ __launch_bounds__(256) void k_xproj(
  const float* __restrict__ cw_f, const float* __restrict__ cb_f, const float* __restrict__ xw_f,
  const float* __restrict__ dw_f, const float* __restrict__ db_f,
  const float* __restrict__ cw_b, const float* __restrict__ cb_b, const float* __restrict__ xw_b,
  const float* __restrict__ dw_b, const float* __restrict__ db_b)
{
  extern __shared__ float dyn[];
  float* sxh = dyn;                 // [64][71]  -> 4544 floats
  float* su  = dyn + 64*71;         // [64][65]  -> 4160 floats (reused for dw chunks)
  float* sw  = dyn + 64*71 + 64*65; // [48][64]  -> 3072 floats (reused for db)
  float* sx  = sxh;                 // epilogue alias: [48][68] = 3264 <= 4544

  int tid = threadIdx.x;
  int t0  = blockIdx.x*64;
  int b   = blockIdx.y;
  int dir = blockIdx.z;
  const float* cw = dir ? cw_b : cw_f;
  const float* cb = dir ? cb_b : cb_f;
  const float* xw = dir ? xw_b : xw_f;
  const float* dw = dir ? dw_b : dw_f;
  const float* dbp = dir ? db_b : db_f;

  int col = tid & 63;               // t within tile
  int rq  = tid >> 6;               // 0..3
  float acc[12];
  #pragma unroll
  for (int r = 0; r < 12; r++) acc[r] = 0.f;

  int dl = tid >> 2;                // conv: local channel 0..63
  int sq = (tid & 3)*16;            // conv: 16 timesteps per thread
  int off = dir ? 3 : 0;

  for (int k0 = 0; k0 < DINN; k0 += 64){
    __syncthreads();
    for (int i = tid; i < 64*70; i += 256){
      int r = i / 70, c = i - r*70;
      int t = t0 - 3 + c;
      sxh[r*71 + c] = (t >= 0 && t < LL)
        ? g_xzT[((size_t)(dir*1024 + k0 + r))*MROWS + b*LL + t] : 0.f;
    }
    for (int i = tid; i < 48*64; i += 256){
      int r = i >> 6, k = i & 63;
      sw[i] = xw[r*DINN + k0 + k];
    }
    __syncthreads();

    {
      int d = k0 + dl;
      float w0, w1, w2, w3;
      if (dir == 0){ w0 = cw[d*4+0]; w1 = cw[d*4+1]; w2 = cw[d*4+2]; w3 = cw[d*4+3]; }
      else         { w0 = cw[d*4+3]; w1 = cw[d*4+2]; w2 = cw[d*4+1]; w3 = cw[d*4+0]; }
      float bias = cb[d];
      const float* xr = sxh + dl*71 + off;
      float uu[16];
      #pragma unroll
      for (int j = 0; j < 16; j++){
        int s = sq + j;
        float a = bias + w0*xr[s] + w1*xr[s+1] + w2*xr[s+2] + w3*xr[s+3];
        uu[j] = a/(1.f + __expf(-a));
        su[dl*65 + s] = uu[j];
      }
      float* up = g_ut + ((size_t)((dir*BB + b)*DINN + d))*LL + t0 + sq;
      #pragma unroll
      for (int j = 0; j < 16; j += 4)
        *(float4*)(up + j) = make_float4(uu[j], uu[j+1], uu[j+2], uu[j+3]);
    }
    __syncthreads();

    #pragma unroll 8
    for (int k = 0; k < 64; k++){
      float u0 = su[k*65 + col];
      #pragma unroll
      for (int r = 0; r < 12; r++)
        acc[r] = fmaf(sw[(rq*12 + r)*64 + k], u0, acc[r]);
    }
  }

  __syncthreads();
  #pragma unroll
  for (int r = 0; r < 12; r++)
    sx[(rq*12 + r)*68 + col] = acc[r];
  // stage dt bias into sw (free after main loop)
  for (int i = tid; i < DINN; i += 256) sw[i] = dbp[i];
  __syncthreads();

  // B/C rows -> g_bcT interleaved [t][n][{B,C}]
  size_t cbase = ((size_t)(dir*BB + b)*LL + t0)*32;
  for (int i = tid; i < 64*16; i += 256){
    int t = i >> 4, nn = i & 15;
    float2 v = make_float2(sx[(16 + nn)*68 + t], sx[(32 + nn)*68 + t]);
    *(float2*)&g_bcT[cbase + (size_t)t*32 + nn*2] = v;
  }

  // dt projection + softplus, fused: xr[16] in regs, dw staged in 2 chunks
  float xr[16];
  #pragma unroll
  for (int r = 0; r < 16; r++) xr[r] = sx[r*68 + col];
  float* dtbase = g_dtt + (size_t)(dir*BB + b)*DINN*LL + t0 + col;

  #pragma unroll
  for (int chunk = 0; chunk < 2; chunk++){
    int dbase = chunk*256;
    __syncthreads();
    #pragma unroll
    for (int i = 0; i < 4; i++)
      ((float4*)su)[tid + i*256] = *(const float4*)(dw + (size_t)dbase*16 + (tid + i*256)*4);
    __syncthreads();
    #pragma unroll 4
    for (int dd = 0; dd < 64; dd++){
      int dl2 = rq*64 + dd;
      int d = dbase + dl2;
      float s = sw[d];
      const float* wrow = su + dl2*16;
      #pragma unroll
      for (int r = 0; r < 16; r++) s = fmaf(wrow[r], xr[r], s);
      s = (s > 20.f) ? s : log1pf(__expf(s));
      dtbase[(size_t)d*LL] = s;
    }
  }
}

// ---------------- selective scan: 2-deep pipeline, LDS.64 B/C ----------
__device__ __forceinline__ float sstep(float dt, float uu, float Bv, float a, float &h){
  float dA = __expf(dt*a);
  h = fmaf(dA, h, dt*Bv*uu);
  return h;
}

__global__ __launch_bounds__(256) void k3_scan(
  const float* __restrict__ alog_f, const float* __restrict__ alog_b,
  const float* __restrict__ Dpf,   const float* __restrict__ Dpb)
{
  __shared__ float sbc[CHT*32];    // 32KB: [t][16][{B,C}]
  int tid = threadIdx.x;
  int ch = blockIdx.x*16 + (tid >> 4);
  int n  = tid & 15;
  int dir = ch >> 11;
  int b   = (ch >> 9) & 3;
  int d   = ch & 511;

  float a  = -__expf((dir ? alog_b : alog_f)[d*16 + n]);
  float dp = (dir ? Dpb : Dpf)[d];

  size_t cbase = ((size_t)((dir*BB + b)*DINN + d))*LL;
  const float* pdt = g_dtt + cbase;
  const float* pu  = g_ut  + cbase;
  const float* pz  = g_xzT + ((size_t)(dir*1024 + 512 + d))*MROWS + b*LL;
  const float* pbc = g_bcT + ((size_t)(dir*BB + b))*LL*32;
  float* pyT = g_yT + ((size_t)(dir*DINN + d))*MROWS + b*LL;

  float h = 0.f;
  bool b3 = (n & 8) != 0, b2 = (n & 4) != 0;
  bool wr = (n & 3) == 0;
  int tmap = (b3 ? 2 : 0) + (b2 ? 1 : 0);

  int t4    = dir ? (LL - 4) : 0;
  int tstep = dir ? -4 : 4;
  // 2-deep pipeline: A = current, B = +1 ahead
  float4 dtA = *(const float4*)(pdt + t4);
  float4 uA  = *(const float4*)(pu  + t4);
  float4 zA  = *(const float4*)(pz  + t4);
  int t4b = t4 + tstep;
  float4 dtB = *(const float4*)(pdt + t4b);
  float4 uB  = *(const float4*)(pu  + t4b);
  float4 zB  = *(const float4*)(pz  + t4b);

  for (int c = 0; c < LL/CHT; c++){
    int tc0 = dir ? (LL - (c+1)*CHT) : c*CHT;
    __syncthreads();
    {
      const float4* src = (const float4*)(pbc + (size_t)tc0*32);
      float4* dst = (float4*)sbc;
      #pragma unroll
      for (int i = 0; i < CHT*32/4/256; i++)
        dst[tid + i*256] = src[tid + i*256];
    }
    __syncthreads();

    #pragma unroll 2
    for (int it = 0; it < CHT/4; it++){
      // prefetch 2 iterations ahead (clamped; unused values harmless)
      int t4c = t4 + 2*tstep;
      t4c = t4c < 0 ? 0 : (t4c > LL-4 ? LL-4 : t4c);
      float4 dtC = *(const float4*)(pdt + t4c);
      float4 uC  = *(const float4*)(pu  + t4c);
      float4 zC  = *(const float4*)(pz  + t4c);

      int tl = (t4 - tc0)*32;
      float2 bc0 = *(const float2*)&sbc[tl +      n*2];
      float2 bc1 = *(const float2*)&sbc[tl + 32 + n*2];
      float2 bc2 = *(const float2*)&sbc[tl + 64 + n*2];
      float2 bc3 = *(const float2*)&sbc[tl + 96 + n*2];

      float y0, y1, y2, y3;
      if (dir == 0){
        y0 = sstep(dtA.x, uA.x, bc0.x, a, h) * bc0.y;
        y1 = sstep(dtA.y, uA.y, bc1.x, a, h) * bc1.y;
        y2 = sstep(dtA.z, uA.z, bc2.x, a, h) * bc2.y;
        y3 = sstep(dtA.w, uA.w, bc3.x, a, h) * bc3.y;
      } else {
        y3 = sstep(dtA.w, uA.w, bc3.x, a, h) * bc3.y;
        y2 = sstep(dtA.z, uA.z, bc2.x, a, h) * bc2.y;
        y1 = sstep(dtA.y, uA.y, bc1.x, a, h) * bc1.y;
        y0 = sstep(dtA.x, uA.x, bc0.x, a, h) * bc0.y;
      }

      // multi-value butterfly: 5 shfls reduce 4 values over 16 lanes
      float slo = b3 ? y0 : y2;
      float shi = b3 ? y1 : y3;
      float rlo = __shfl_xor_sync(0xffffffffu, slo, 8);
      float rhi = __shfl_xor_sync(0xffffffffu, shi, 8);
      float p0  = (b3 ? y2 : y0) + rlo;
      float p1  = (b3 ? y3 : y1) + rhi;
      float sb  = b2 ? p0 : p1;
      float rb  = __shfl_xor_sync(0xffffffffu, sb, 4);
      float v   = (b2 ? p1 : p0) + rb;
      v += __shfl_xor_sync(0xffffffffu, v, 2);
      v += __shfl_xor_sync(0xffffffffu, v, 1);

      if (wr){
        float ut = b3 ? (b2 ? uA.w : uA.z) : (b2 ? uA.y : uA.x);
        float zv = b3 ? (b2 ? zA.w : zA.z) : (b2 ? zA.y : zA.x);
        float sz = zv/(1.f + __expf(-zv));
        pyT[t4 + tmap] = (v + ut*dp)*sz;
      }
      dtA = dtB; uA = uB; zA = zB;
      dtB = dtC; uB = uC; zB = zC;
      t4 += tstep;
    }
  }
}

// ---------------- launch ----------------
extern "C" void kernel_launch(void* const* d_in, const int* in_sizes, int n_in,
                              void* d_out, int out_size)
{
  (void)in_sizes; (void)n_in; (void)out_size;
  const float* x       = (const float*)d_in[0];
  const float* fw_norm = (const float*)d_in[1];
  const float* fw_inw  = (const float*)d_in[2];
  const float* fw_cw   = (const float*)d_in[3];
  const float* fw_cb   = (const float*)d_in[4];
  const float* fw_xw   = (const float*)d_in[5];
  const float* fw_dw   = (const float*)d_in[6];
  const float* fw_db   = (const float*)d_in[7];
  const float* fw_al   = (const float*)d_in[8];
  const float* fw_Dp   = (const float*)d_in[9];
  const float* fw_ow   = (const float*)d_in[10];
  const float* bw_norm = (const float*)d_in[11];
  const float* bw_inw  = (const float*)d_in[12];
  const float* bw_cw   = (const float*)d_in[13];
  const float* bw_cb   = (const float*)d_in[14];
  const float* bw_xw   = (const float*)d_in[15];
  const float* bw_dw   = (const float*)d_in[16];
  const float* bw_db   = (const float*)d_in[17];
  const float* bw_al   = (const float*)d_in[18];
  const float* bw_Dp   = (const float*)d_in[19];
  const float* bw_ow   = (const float*)d_in[20];

  float *p_xn, *p_w1, *p_w2, *p_xzT, *p_yT;
  cudaGetSymbolAddress((void**)&p_xn, g_xn);
  cudaGetSymbolAddress((void**)&p_w1, g_w1);
  cudaGetSymbolAddress((void**)&p_w2, g_w2);
  cudaGetSymbolAddress((void**)&p_xzT, g_xzT);
  cudaGetSymbolAddress((void**)&p_yT, g_yT);

  const int smemA0 = (2*(128*36) + 2*(128*36))*(int)sizeof(float);   // 73728
  const int smemA1 = (2*(32*136) + 2*(128*36))*(int)sizeof(float);   // 71680
  cudaFuncSetAttribute(k_gemm_db<0>, cudaFuncAttributeMaxDynamicSharedMemorySize, smemA0);
  cudaFuncSetAttribute(k_gemm_db<1>, cudaFuncAttributeMaxDynamicSharedMemorySize, smemA1);

  // 1) fused prep + rmsnorm
  k_prep_rms<<<MROWS + 2048 + 1024, 256>>>(x, fw_inw, fw_norm, bw_inw, bw_norm,
                                           fw_ow, bw_ow);
  // 2) in_proj: g_xzT[2048 x 8192] = w1[2048x256] @ xn[8192x256]^T
  k_gemm_db<0><<<dim3(64, 16), 256, smemA0>>>(p_w1, DD, (size_t)0, 1000000,
                                              p_xn, DD, p_xzT, MROWS, nullptr, DD, DD);
  // 3) fused conv + silu + x_dbl + dt projection
  int smemx = (64*71 + 64*65 + 48*64)*(int)sizeof(float);   // 47104
  cudaFuncSetAttribute(k_xproj, cudaFuncAttributeMaxDynamicSharedMemorySize, smemx);
  k_xproj<<<dim3(LL/64, BB, NDIR), 256, smemx>>>(fw_cw, fw_cb, fw_xw, fw_dw, fw_db,
                                                 bw_cw, bw_cb, bw_xw, bw_dw, bw_db);
  // 4) selective scan  (ncu capture slot)
  k3_scan<<<256, 256>>>(fw_al, bw_al, fw_Dp, bw_Dp);
  // 5) out_proj + residual
  k_gemm_db<1><<<dim3(4, 64), 256, smemA1>>>(p_yT, MROWS, (size_t)DINN*MROWS, 2,
                                             p_w2, DINN, (float*)d_out, 2*DD, x, DD, DINN);
}

// round 12
// speedup vs baseline: 2.5471x; 1.0179x over previous
#include <cuda_runtime.h>
#include <math.h>
#include <stdint.h>

#define BB 4
#define LL 2048
#define DD 256
#define DINN 512
#define NST 16
#define NDIR 2
#define MROWS (BB*LL)      // 8192
#define N1 2048
#define EPSF 1e-5f
#define CHT 256            // scan smem chunk (timesteps)

// ---------------- scratch ----------------
__device__ float g_xn[MROWS*DD];
__device__ float g_w1[N1*DD];
__device__ float g_w2[NDIR*DD*DINN];
__device__ float g_xzT[(size_t)N1*MROWS];          // in_proj out [e][b*L+t]
__device__ float g_ut [(size_t)NDIR*BB*DINN*LL];   // u [dir][b][d][t]
__device__ float g_dtt[(size_t)NDIR*BB*DINN*LL];   // dt [dir][b][d][t]
__device__ float g_bcT[(size_t)NDIR*BB*LL*32];     // B/C interleaved [dir][b][t][n][{B,C}]
__device__ float g_yT [(size_t)NDIR*DINN*MROWS];   // scan out [dir][d][b*L+t]

// ---------------- fused prep (w1 fold, w2 stack) + rmsnorm ----------------
__global__ __launch_bounds__(256) void k_prep_rms(
    const float* __restrict__ x,
    const float* __restrict__ inw_f, const float* __restrict__ nw_f,
    const float* __restrict__ inw_b, const float* __restrict__ nw_b,
    const float* __restrict__ ow_f,  const float* __restrict__ ow_b)
{
  int blk = blockIdx.x;
  int tid = threadIdx.x;
  if (blk < MROWS){
    int row = blk;
    float v = x[row*DD + tid];
    float s = v*v;
    #pragma unroll
    for (int o = 16; o; o >>= 1) s += __shfl_xor_sync(0xffffffffu, s, o);
    __shared__ float ws[8];
    __shared__ float scale;
    if ((tid & 31) == 0) ws[tid >> 5] = s;
    __syncthreads();
    if (tid == 0){
      float t = 0.f;
      #pragma unroll
      for (int i = 0; i < 8; i++) t += ws[i];
      scale = rsqrtf(t*(1.0f/DD) + EPSF);
    }
    __syncthreads();
    g_xn[row*DD + tid] = v*scale;
  } else if (blk < MROWS + 2048){
    int i = (blk - MROWS)*256 + tid;
    int dir = i / (1024*DD);
    int rem = i - dir*1024*DD;
    int d = rem % DD;
    g_w1[i] = dir ? inw_b[rem]*nw_b[d] : inw_f[rem]*nw_f[d];
  } else {
    int i = (blk - MROWS - 2048)*256 + tid;
    int dir = i / (DD*DINN);
    int rem = i - dir*DD*DINN;
    g_w2[i] = dir ? ow_b[rem] : ow_f[rem];
  }
}

// ---------------- cp.async helpers ----------------
__device__ __forceinline__ void cp16(uint32_t dst, const float* src){
  asm volatile("cp.async.ca.shared.global [%0], [%1], 16;\n" :: "r"(dst), "l"(src));
}
#define CP_COMMIT() asm volatile("cp.async.commit_group;\n" ::: "memory")
#define CP_WAIT1()  asm volatile("cp.async.wait_group 1;\n" ::: "memory")

// ---------------- double-buffered TF32 GEMM, BK=32 ----------------
template<int ATRANS>
__global__ __launch_bounds__(256) void k_gemm_db(
    const float* __restrict__ A, int lda, size_t aDirStride, int bpdX,
    const float* __restrict__ Bw, int ldb,
    float* __restrict__ C, int ldc,
    const float* __restrict__ resid, int rld, int K)
{
  const int BM = 128, BN = 128, BK = 32;
  const int ASZ = ATRANS ? 32*136 : 128*36;
  const int BSZ = 128*36;
  extern __shared__ float dyn[];
  float* As = dyn;
  float* Bs = dyn + 2*ASZ;

  int tid = threadIdx.x;
  int bx = blockIdx.x, by = blockIdx.y;
  int dir = bx / bpdX;
  A  += (size_t)dir*aDirStride + (ATRANS ? (size_t)(by*BM) : (size_t)(by*BM)*lda);
  Bw += (size_t)(bx*BN)*ldb;
  C  += (size_t)(by*BM)*ldc + (size_t)(bx*BN);
  const float* R = resid ? (resid + (size_t)(by*BM)*rld + (size_t)(bx % bpdX)*BN) : nullptr;

  uint32_t asb = (uint32_t)__cvta_generic_to_shared(As);
  uint32_t bsb = (uint32_t)__cvta_generic_to_shared(Bs);

  int warp = tid >> 5, lane = tid & 31;
  int wm = (warp >> 2)*64, wn = (warp & 3)*32;
  int g  = lane >> 2, tq = lane & 3;

  float acc[4][4][4];
  #pragma unroll
  for (int i = 0; i < 4; i++)
    #pragma unroll
    for (int j = 0; j < 4; j++)
      #pragma unroll
      for (int q = 0; q < 4; q++) acc[i][j][q] = 0.f;

  auto prefetch = [&](int st, int k0){
    #pragma unroll
    for (int i = 0; i < 4; i++){
      int c = tid + i*256;
      int row = c >> 3, kc = (c & 7)*4;
      cp16(bsb + (uint32_t)((st*BSZ + row*36 + kc)*4), Bw + (size_t)row*ldb + k0 + kc);
    }
    if (ATRANS){
      #pragma unroll
      for (int i = 0; i < 4; i++){
        int c = tid + i*256;
        int kr = c >> 5, mc = (c & 31)*4;
        cp16(asb + (uint32_t)((st*ASZ + kr*136 + mc)*4), A + (size_t)(k0+kr)*lda + mc);
      }
    } else {
      #pragma unroll
      for (int i = 0; i < 4; i++){
        int c = tid + i*256;
        int row = c >> 3, kc = (c & 7)*4;
        cp16(asb + (uint32_t)((st*ASZ + row*36 + kc)*4), A + (size_t)row*lda + k0 + kc);
      }
    }
  };

  prefetch(0, 0);
  CP_COMMIT();
  int NK = K/BK;
  for (int kt = 0; kt < NK; kt++){
    if (kt + 1 < NK) prefetch((kt+1) & 1, (kt+1)*BK);
    CP_COMMIT();
    CP_WAIT1();
    __syncthreads();
    int st = kt & 1;
    const uint32_t* as = (const uint32_t*)(As + st*ASZ);
    const uint32_t* bs = (const uint32_t*)(Bs + st*BSZ);
    #pragma unroll
    for (int k8 = 0; k8 < BK; k8 += 8){
      uint32_t af[4][4], bf[4][2];
      #pragma unroll
      for (int mm = 0; mm < 4; mm++){
        int mb = wm + mm*16;
        if (ATRANS){
          af[mm][0] = as[(k8+tq  )*136 + mb + g];
          af[mm][1] = as[(k8+tq  )*136 + mb + g + 8];
          af[mm][2] = as[(k8+tq+4)*136 + mb + g];
          af[mm][3] = as[(k8+tq+4)*136 + mb + g + 8];
        } else {
          af[mm][0] = as[(mb + g    )*36 + k8 + tq];
          af[mm][1] = as[(mb + g + 8)*36 + k8 + tq];
          af[mm][2] = as[(mb + g    )*36 + k8 + tq + 4];
          af[mm][3] = as[(mb + g + 8)*36 + k8 + tq + 4];
        }
      }
      #pragma unroll
      for (int nn = 0; nn < 4; nn++){
        int nb = wn + nn*8;
        bf[nn][0] = bs[(nb + g)*36 + k8 + tq];
        bf[nn][1] = bs[(nb + g)*36 + k8 + tq + 4];
      }
      #pragma unroll
      for (int mm = 0; mm < 4; mm++)
        #pragma unroll
        for (int nn = 0; nn < 4; nn++){
          asm volatile(
            "mma.sync.aligned.m16n8k8.row.col.f32.tf32.tf32.f32 "
            "{%0,%1,%2,%3}, {%4,%5,%6,%7}, {%8,%9}, {%0,%1,%2,%3};\n"
            : "+f"(acc[mm][nn][0]), "+f"(acc[mm][nn][1]),
              "+f"(acc[mm][nn][2]), "+f"(acc[mm][nn][3])
            : "r"(af[mm][0]), "r"(af[mm][1]), "r"(af[mm][2]), "r"(af[mm][3]),
              "r"(bf[nn][0]), "r"(bf[nn][1]));
        }
    }
    __syncthreads();
  }

  #pragma unroll
  for (int mm = 0; mm < 4; mm++)
    #pragma unroll
    for (int nn = 0; nn < 4; nn++){
      int row0 = wm + mm*16 + g;
      int col  = wn + nn*8 + 2*tq;
      float2 v0 = make_float2(acc[mm][nn][0], acc[mm][nn][1]);
      float2 v1 = make_float2(acc[mm][nn][2], acc[mm][nn][3]);
      if (R){
        float2 r0 = *(const float2*)(R + (size_t)row0*rld + col);
        float2 r1 = *(const float2*)(R + (size_t)(row0+8)*rld + col);
        v0.x += r0.x; v0.y += r0.y; v1.x += r1.x; v1.y += r1.y;
      }
      *(float2*)(C + (size_t)row0*ldc + col)     = v0;
      *(float2*)(C + (size_t)(row0+8)*ldc + col) = v1;
    }
}

// ---------------- fused conv+silu+xproj+dtproj: t-tile 64 ----------------
__global__ __launch_bounds__(256) void k_xproj(
  const float* __restrict__ cw_f, const float* __restrict__ cb_f, const float* __restrict__ xw_f,
  const float* __restrict__ dw_f, const float* __restrict__ db_f,
  const float* __restrict__ cw_b, const float* __restrict__ cb_b, const float* __restrict__ xw_b,
  const float* __restrict__ dw_b, const float* __restrict__ db_b)
{
  extern __shared__ float dyn[];
  float* sxh = dyn;                 // [64][71]  -> 4544 floats
  float* su  = dyn + 64*71;         // [64][65]  -> 4160 floats (reused for dw chunks)
  float* sw  = dyn + 64*71 + 64*65; // [48][64]  -> 3072 floats (reused for db)
  float* sx  = sxh;                 // epilogue alias: [48][68] = 3264 <= 4544

  int tid = threadIdx.x;
  int t0  = blockIdx.x*64;
  int b   = blockIdx.y;
  int dir = blockIdx.z;
  const float* cw = dir ? cw_b : cw_f;
  const float* cb = dir ? cb_b : cb_f;
  const float* xw = dir ? xw_b : xw_f;
  const float* dw = dir ? dw_b : dw_f;
  const float* dbp = dir ? db_b : db_f;

  int col = tid & 63;               // t within tile
  int rq  = tid >> 6;               // 0..3
  float acc[12];
  #pragma unroll
  for (int r = 0; r < 12; r++) acc[r] = 0.f;

  int dl = tid >> 2;                // conv: local channel 0..63
  int sq = (tid & 3)*16;            // conv: 16 timesteps per thread
  int off = dir ? 3 : 0;

  for (int k0 = 0; k0 < DINN; k0 += 64){
    __syncthreads();
    for (int i = tid; i < 64*70; i += 256){
      int r = i / 70, c = i - r*70;
      int t = t0 - 3 + c;
      sxh[r*71 + c] = (t >= 0 && t < LL)
        ? g_xzT[((size_t)(dir*1024 + k0 + r))*MROWS + b*LL + t] : 0.f;
    }
    for (int i = tid; i < 48*64; i += 256){
      int r = i >> 6, k = i & 63;
      sw[i] = xw[r*DINN + k0 + k];
    }
    __syncthreads();

    {
      int d = k0 + dl;
      float w0, w1, w2, w3;
      if (dir == 0){ w0 = cw[d*4+0]; w1 = cw[d*4+1]; w2 = cw[d*4+2]; w3 = cw[d*4+3]; }
      else         { w0 = cw[d*4+3]; w1 = cw[d*4+2]; w2 = cw[d*4+1]; w3 = cw[d*4+0]; }
      float bias = cb[d];
      const float* xr = sxh + dl*71 + off;
      float uu[16];
      #pragma unroll
      for (int j = 0; j < 16; j++){
        int s = sq + j;
        float a = bias + w0*xr[s] + w1*xr[s+1] + w2*xr[s+2] + w3*xr[s+3];
        uu[j] = a/(1.f + __expf(-a));
        su[dl*65 + s] = uu[j];
      }
      float* up = g_ut + ((size_t)((dir*BB + b)*DINN + d))*LL + t0 + sq;
      #pragma unroll
      for (int j = 0; j < 16; j += 4)
        *(float4*)(up + j) = make_float4(uu[j], uu[j+1], uu[j+2], uu[j+3]);
    }
    __syncthreads();

    #pragma unroll 8
    for (int k = 0; k < 64; k++){
      float u0 = su[k*65 + col];
      #pragma unroll
      for (int r = 0; r < 12; r++)
        acc[r] = fmaf(sw[(rq*12 + r)*64 + k], u0, acc[r]);
    }
  }

  __syncthreads();
  #pragma unroll
  for (int r = 0; r < 12; r++)
    sx[(rq*12 + r)*68 + col] = acc[r];
  // stage dt bias into sw (free after main loop)
  for (int i = tid; i < DINN; i += 256) sw[i] = dbp[i];
  __syncthreads();

  // B/C rows -> g_bcT interleaved [t][n][{B,C}]
  size_t cbase = ((size_t)(dir*BB + b)*LL + t0)*32;
  for (int i = tid; i < 64*16; i += 256){
    int t = i >> 4, nn = i & 15;
    float2 v = make_float2(sx[(16 + nn)*68 + t], sx[(32 + nn)*68 + t]);
    *(float2*)&g_bcT[cbase + (size_t)t*32 + nn*2] = v;
  }

  // dt projection + softplus, fused: xr[16] in regs, dw staged in 2 chunks
  float xr[16];
  #pragma unroll
  for (int r = 0; r < 16; r++) xr[r] = sx[r*68 + col];
  float* dtbase = g_dtt + (size_t)(dir*BB + b)*DINN*LL + t0 + col;

  #pragma unroll
  for (int chunk = 0; chunk < 2; chunk++){
    int dbase = chunk*256;
    __syncthreads();
    #pragma unroll
    for (int i = 0; i < 4; i++)
      ((float4*)su)[tid + i*256] = *(const float4*)(dw + (size_t)dbase*16 + (tid + i*256)*4);
    __syncthreads();
    #pragma unroll 4
    for (int dd = 0; dd < 64; dd++){
      int dl2 = rq*64 + dd;
      int d = dbase + dl2;
      float s = sw[d];
      const float* wrow = su + dl2*16;
      #pragma unroll
      for (int r = 0; r < 16; r++) s = fmaf(wrow[r], xr[r], s);
      s = (s > 20.f) ? s : log1pf(__expf(s));
      dtbase[(size_t)d*LL] = s;
    }
  }
}

// ---------------- selective scan: 8 steps/iter, 8-shfl multi-reduce ----------
__device__ __forceinline__ float sstep(float dt, float uu, float Bv, float a, float &h){
  float dA = __expf(dt*a);
  h = fmaf(dA, h, dt*Bv*uu);
  return h;
}

__global__ __launch_bounds__(256) void k3_scan(
  const float* __restrict__ alog_f, const float* __restrict__ alog_b,
  const float* __restrict__ Dpf,   const float* __restrict__ Dpb)
{
  __shared__ float sbc[CHT*32];    // 32KB: [t][16][{B,C}]
  int tid = threadIdx.x;
  int ch = blockIdx.x*16 + (tid >> 4);
  int n  = tid & 15;
  int dir = ch >> 11;
  int b   = (ch >> 9) & 3;
  int d   = ch & 511;

  float a  = -__expf((dir ? alog_b : alog_f)[d*16 + n]);
  // dp folded into lane-0's pre-reduction values
  float dp = (n == 0) ? (dir ? Dpb : Dpf)[d] : 0.f;

  size_t cbase = ((size_t)((dir*BB + b)*DINN + d))*LL;
  const float* pdt = g_dtt + cbase;
  const float* pu  = g_ut  + cbase;
  const float* pz  = g_xzT + ((size_t)(dir*1024 + 512 + d))*MROWS + b*LL;
  const float* pbc = g_bcT + ((size_t)(dir*BB + b))*LL*32;
  float* pyT = g_yT + ((size_t)(dir*DINN + d))*MROWS + b*LL;

  float h = 0.f;
  bool b3 = (n & 8) != 0, b2 = (n & 4) != 0, b1 = (n & 2) != 0;
  bool wlane = (n & 1) == 0;
  int tmap = n >> 1;

  int t8    = dir ? (LL - 8) : 0;
  int tstep = dir ? -8 : 8;

  float4 dtb[2][2], ub[2][2], zb[2][2];
  dtb[0][0] = *(const float4*)(pdt + t8);     dtb[0][1] = *(const float4*)(pdt + t8 + 4);
  ub [0][0] = *(const float4*)(pu  + t8);     ub [0][1] = *(const float4*)(pu  + t8 + 4);
  zb [0][0] = *(const float4*)(pz  + t8);     zb [0][1] = *(const float4*)(pz  + t8 + 4);

  for (int c = 0; c < LL/CHT; c++){
    int tc0 = dir ? (LL - (c+1)*CHT) : c*CHT;
    __syncthreads();
    {
      const float4* src = (const float4*)(pbc + (size_t)tc0*32);
      float4* dst = (float4*)sbc;
      #pragma unroll
      for (int i = 0; i < CHT*32/4/256; i++)
        dst[tid + i*256] = src[tid + i*256];
    }
    __syncthreads();

    #pragma unroll 2
    for (int it = 0; it < CHT/8; it++){
      int cur = it & 1, nxt = cur ^ 1;
      // prefetch next 8-step group (clamped; garbage-safe on final iter)
      int t8n = t8 + tstep;
      int t8c = t8n < 0 ? 0 : (t8n > LL-8 ? LL-8 : t8n);
      dtb[nxt][0] = *(const float4*)(pdt + t8c); dtb[nxt][1] = *(const float4*)(pdt + t8c + 4);
      ub [nxt][0] = *(const float4*)(pu  + t8c); ub [nxt][1] = *(const float4*)(pu  + t8c + 4);
      zb [nxt][0] = *(const float4*)(pz  + t8c); zb [nxt][1] = *(const float4*)(pz  + t8c + 4);

      float dts[8] = {dtb[cur][0].x, dtb[cur][0].y, dtb[cur][0].z, dtb[cur][0].w,
                      dtb[cur][1].x, dtb[cur][1].y, dtb[cur][1].z, dtb[cur][1].w};
      float us [8] = {ub[cur][0].x, ub[cur][0].y, ub[cur][0].z, ub[cur][0].w,
                      ub[cur][1].x, ub[cur][1].y, ub[cur][1].z, ub[cur][1].w};
      float zs [8] = {zb[cur][0].x, zb[cur][0].y, zb[cur][0].z, zb[cur][0].w,
                      zb[cur][1].x, zb[cur][1].y, zb[cur][1].z, zb[cur][1].w};

      int tl = (t8 - tc0)*32 + n*2;
      float2 bc[8];
      #pragma unroll
      for (int i = 0; i < 8; i++) bc[i] = *(const float2*)&sbc[tl + i*32];

      float v[8];
      if (dir == 0){
        #pragma unroll
        for (int i = 0; i < 8; i++) v[i] = sstep(dts[i], us[i], bc[i].x, a, h) * bc[i].y;
      } else {
        #pragma unroll
        for (int i = 7; i >= 0; i--) v[i] = sstep(dts[i], us[i], bc[i].x, a, h) * bc[i].y;
      }
      // fold u*dp (dp==0 except lane n==0)
      #pragma unroll
      for (int i = 0; i < 8; i++) v[i] = fmaf(us[i], dp, v[i]);

      // multi-value butterfly: 8 values over 16 lanes in 8 shfls
      float s0 = b3 ? v[0] : v[4];
      float s1 = b3 ? v[1] : v[5];
      float s2 = b3 ? v[2] : v[6];
      float s3 = b3 ? v[3] : v[7];
      float r0 = __shfl_xor_sync(0xffffffffu, s0, 8);
      float r1 = __shfl_xor_sync(0xffffffffu, s1, 8);
      float r2 = __shfl_xor_sync(0xffffffffu, s2, 8);
      float r3 = __shfl_xor_sync(0xffffffffu, s3, 8);
      float w0 = (b3 ? v[4] : v[0]) + r0;
      float w1 = (b3 ? v[5] : v[1]) + r1;
      float w2 = (b3 ? v[6] : v[2]) + r2;
      float w3 = (b3 ? v[7] : v[3]) + r3;

      float s4 = b2 ? w0 : w2;
      float s5 = b2 ? w1 : w3;
      float r4 = __shfl_xor_sync(0xffffffffu, s4, 4);
      float r5 = __shfl_xor_sync(0xffffffffu, s5, 4);
      float x0 = (b2 ? w2 : w0) + r4;
      float x1 = (b2 ? w3 : w1) + r5;

      float s6 = b1 ? x0 : x1;
      float r6 = __shfl_xor_sync(0xffffffffu, s6, 2);
      float tv = (b1 ? x1 : x0) + r6;
      tv += __shfl_xor_sync(0xffffffffu, tv, 1);

      if (wlane){
        float za0 = b1 ? zs[1] : zs[0];
        float za1 = b1 ? zs[3] : zs[2];
        float za2 = b1 ? zs[5] : zs[4];
        float za3 = b1 ? zs[7] : zs[6];
        float zb0 = b2 ? za1 : za0;
        float zb1 = b2 ? za3 : za2;
        float zv = b3 ? zb1 : zb0;
        float sz = zv/(1.f + __expf(-zv));
        pyT[t8 + tmap] = tv * sz;
      }
      t8 = t8n;
    }
  }
}

// ---------------- launch ----------------
extern "C" void kernel_launch(void* const* d_in, const int* in_sizes, int n_in,
                              void* d_out, int out_size)
{
  (void)in_sizes; (void)n_in; (void)out_size;
  const float* x       = (const float*)d_in[0];
  const float* fw_norm = (const float*)d_in[1];
  const float* fw_inw  = (const float*)d_in[2];
  const float* fw_cw   = (const float*)d_in[3];
  const float* fw_cb   = (const float*)d_in[4];
  const float* fw_xw   = (const float*)d_in[5];
  const float* fw_dw   = (const float*)d_in[6];
  const float* fw_db   = (const float*)d_in[7];
  const float* fw_al   = (const float*)d_in[8];
  const float* fw_Dp   = (const float*)d_in[9];
  const float* fw_ow   = (const float*)d_in[10];
  const float* bw_norm = (const float*)d_in[11];
  const float* bw_inw  = (const float*)d_in[12];
  const float* bw_cw   = (const float*)d_in[13];
  const float* bw_cb   = (const float*)d_in[14];
  const float* bw_xw   = (const float*)d_in[15];
  const float* bw_dw   = (const float*)d_in[16];
  const float* bw_db   = (const float*)d_in[17];
  const float* bw_al   = (const float*)d_in[18];
  const float* bw_Dp   = (const float*)d_in[19];
  const float* bw_ow   = (const float*)d_in[20];

  float *p_xn, *p_w1, *p_w2, *p_xzT, *p_yT;
  cudaGetSymbolAddress((void**)&p_xn, g_xn);
  cudaGetSymbolAddress((void**)&p_w1, g_w1);
  cudaGetSymbolAddress((void**)&p_w2, g_w2);
  cudaGetSymbolAddress((void**)&p_xzT, g_xzT);
  cudaGetSymbolAddress((void**)&p_yT, g_yT);

  const int smemA0 = (2*(128*36) + 2*(128*36))*(int)sizeof(float);   // 73728
  const int smemA1 = (2*(32*136) + 2*(128*36))*(int)sizeof(float);   // 71680
  cudaFuncSetAttribute(k_gemm_db<0>, cudaFuncAttributeMaxDynamicSharedMemorySize, smemA0);
  cudaFuncSetAttribute(k_gemm_db<1>, cudaFuncAttributeMaxDynamicSharedMemorySize, smemA1);

  // 1) fused prep + rmsnorm
  k_prep_rms<<<MROWS + 2048 + 1024, 256>>>(x, fw_inw, fw_norm, bw_inw, bw_norm,
                                           fw_ow, bw_ow);
  // 2) in_proj: g_xzT[2048 x 8192] = w1[2048x256] @ xn[8192x256]^T
  k_gemm_db<0><<<dim3(64, 16), 256, smemA0>>>(p_w1, DD, (size_t)0, 1000000,
                                              p_xn, DD, p_xzT, MROWS, nullptr, DD, DD);
  // 3) fused conv + silu + x_dbl + dt projection
  int smemx = (64*71 + 64*65 + 48*64)*(int)sizeof(float);   // 47104
  cudaFuncSetAttribute(k_xproj, cudaFuncAttributeMaxDynamicSharedMemorySize, smemx);
  k_xproj<<<dim3(LL/64, BB, NDIR), 256, smemx>>>(fw_cw, fw_cb, fw_xw, fw_dw, fw_db,
                                                 bw_cw, bw_cb, bw_xw, bw_dw, bw_db);
  // 4) selective scan  (ncu capture slot)
  k3_scan<<<256, 256>>>(fw_al, bw_al, fw_Dp, bw_Dp);
  // 5) out_proj + residual
  k_gemm_db<1><<<dim3(4, 64), 256, smemA1>>>(p_yT, MROWS, (size_t)DINN*MROWS, 2,
                                             p_w2, DINN, (float*)d_out, 2*DD, x, DD, DINN);
}